// round 2
// baseline (speedup 1.0000x reference)
#include <cuda_runtime.h>
#include <cstdint>

// ---------------- problem constants ----------------
constexpr int BB = 8;      // batch
constexpr int CC = 512;    // channels
constexpr int HH = 56, WW = 56;
constexpr int NT = 3136;   // H*W tokens
constexpr int MT = 588;    // 3*196 downsampled tokens
constexpr int NH = 8;      // heads
constexpr int HD = 64;     // head dim
#define ATT_SCALE 0.125f

// ---------------- scratch (device globals; no allocation allowed) ----------------
__device__ float g_q [BB * NT * CC];          // [b][n][c]
__device__ float g_l [BB * MT * CC];          // [b][m][c] tokens (pre+post LN in place)
__device__ float g_k [BB * NH * MT * HD];     // [b][h][m][d]
__device__ float g_v [BB * NH * MT * HD];     // [b][h][m][d]
__device__ float g_t1[BB * CC * HH * 14];     // branch1 intermediate [b][c][h][w4]
__device__ float g_p3[BB * CC * 14 * 14];     // branch3 pooled [b][c][h4][w4]

// ---------------- Q projection: Q[b,n,o] = sum_c x[b,c,n] * Wq[o,c] + bq[o] ----------------
__global__ __launch_bounds__(256) void k_qproj(const float* __restrict__ x,
                                               const float* __restrict__ Wq,
                                               const float* __restrict__ bq) {
    __shared__ float As[8][132];   // As[kk][nn] = x[c0+kk][n0+nn]
    __shared__ float Bs[8][132];   // Bs[kk][oo] = Wq[o0+oo][c0+kk]
    const int b  = blockIdx.z;
    const int n0 = blockIdx.x * 128;
    const int o0 = blockIdx.y * 128;
    const float* A = x + (size_t)b * CC * NT;
    const int t  = threadIdx.x;
    const int tx = t & 15, ty = t >> 4;
    const int la_k = t >> 5, la_n = (t & 31) * 4;
    const int lb_o = t >> 1, lb_k = (t & 1) * 4;

    float acc[8][8] = {};
    for (int c0 = 0; c0 < CC; c0 += 8) {
        int n = n0 + la_n;
        float4 va = make_float4(0.f, 0.f, 0.f, 0.f);
        if (n < NT) va = *(const float4*)(A + (size_t)(c0 + la_k) * NT + n);
        *(float4*)&As[la_k][la_n] = va;
        float4 vb = *(const float4*)(Wq + (size_t)(o0 + lb_o) * CC + c0 + lb_k);
        Bs[lb_k + 0][lb_o] = vb.x; Bs[lb_k + 1][lb_o] = vb.y;
        Bs[lb_k + 2][lb_o] = vb.z; Bs[lb_k + 3][lb_o] = vb.w;
        __syncthreads();
        #pragma unroll
        for (int kk = 0; kk < 8; kk++) {
            float ra[8], rb[8];
            #pragma unroll
            for (int i = 0; i < 8; i++) ra[i] = As[kk][tx + 16 * i];
            #pragma unroll
            for (int j = 0; j < 8; j++) rb[j] = Bs[kk][ty * 8 + j];
            #pragma unroll
            for (int i = 0; i < 8; i++)
                #pragma unroll
                for (int j = 0; j < 8; j++) acc[i][j] += ra[i] * rb[j];
        }
        __syncthreads();
    }
    float* Q = g_q + (size_t)b * NT * CC;
    float bias[8];
    #pragma unroll
    for (int j = 0; j < 8; j++) bias[j] = bq[o0 + ty * 8 + j];
    #pragma unroll
    for (int i = 0; i < 8; i++) {
        int n = n0 + tx + 16 * i;
        if (n < NT) {
            float* qp = Q + (size_t)n * CC + o0 + ty * 8;
            #pragma unroll
            for (int j = 0; j < 8; j++) qp[j] = acc[i][j] + bias[j];
        }
    }
}

// ---------------- branch 1 stage a: (1,4) s(1,4) dwconv + relu -> g_t1 ----------------
__global__ void k_b1a(const float* __restrict__ x, const float* __restrict__ w1a,
                      const float* __restrict__ b1a) {
    int idx = blockIdx.x * 256 + threadIdx.x;
    if (idx >= BB * CC * HH * 14) return;
    int w4 = idx % 14;
    int h  = (idx / 14) % HH;
    int c  = (idx / (14 * HH)) % CC;
    int b  = idx / (14 * HH * CC);
    const float* xp = x + (((size_t)(b * CC + c) * HH) + h) * WW + 4 * w4;
    float s = b1a[c];
    #pragma unroll
    for (int r = 0; r < 4; r++) s += xp[r] * w1a[c * 4 + r];
    g_t1[idx] = fmaxf(s, 0.f);
}

// ---------------- branch 1 stage b: (4,1) s(4,1) dwconv + relu -> g_l[:, 0:196, :] ----------------
__global__ void k_b1b(const float* __restrict__ w1b, const float* __restrict__ b1b) {
    int idx = blockIdx.x * 256 + threadIdx.x;
    if (idx >= BB * CC * 196) return;
    int w4 = idx % 14;
    int h4 = (idx / 14) % 14;
    int c  = (idx / 196) % CC;
    int b  = idx / (196 * CC);
    float s = b1b[c];
    #pragma unroll
    for (int r = 0; r < 4; r++)
        s += g_t1[(((size_t)(b * CC + c) * HH) + 4 * h4 + r) * 14 + w4] * w1b[c * 4 + r];
    int m = h4 * 14 + w4;
    g_l[((size_t)b * MT + m) * CC + c] = fmaxf(s, 0.f);
}

// ---------------- branch 2: 4x4 s4 dwconv + relu -> g_l[:, 196:392, :] ----------------
__global__ void k_b2(const float* __restrict__ x, const float* __restrict__ w2,
                     const float* __restrict__ b2) {
    int idx = blockIdx.x * 256 + threadIdx.x;
    if (idx >= BB * CC * 196) return;
    int w4 = idx % 14;
    int h4 = (idx / 14) % 14;
    int c  = (idx / 196) % CC;
    int b  = idx / (196 * CC);
    const float* xp = x + (((size_t)(b * CC + c) * HH) + 4 * h4) * WW + 4 * w4;
    float s = b2[c];
    #pragma unroll
    for (int i = 0; i < 4; i++)
        #pragma unroll
        for (int j = 0; j < 4; j++) s += xp[i * WW + j] * w2[c * 16 + i * 4 + j];
    int m = h4 * 14 + w4;
    g_l[((size_t)b * MT + 196 + m) * CC + c] = fmaxf(s, 0.f);
}

// ---------------- branch 3 stage a: 4x4 avg pool -> g_p3 ----------------
__global__ void k_pool3(const float* __restrict__ x) {
    int idx = blockIdx.x * 256 + threadIdx.x;
    if (idx >= BB * CC * 196) return;
    int w4 = idx % 14;
    int h4 = (idx / 14) % 14;
    int c  = (idx / 196) % CC;
    int b  = idx / (196 * CC);
    const float* xp = x + (((size_t)(b * CC + c) * HH) + 4 * h4) * WW + 4 * w4;
    float s = 0.f;
    #pragma unroll
    for (int i = 0; i < 4; i++)
        #pragma unroll
        for (int j = 0; j < 4; j++) s += xp[i * WW + j];
    g_p3[idx] = s * (1.f / 16.f);
}

// ---------------- branch 3 stage b: 3x3 pad1 dwconv + relu -> g_l[:, 392:588, :] ----------------
__global__ void k_b3(const float* __restrict__ w3, const float* __restrict__ b3) {
    int idx = blockIdx.x * 256 + threadIdx.x;
    if (idx >= BB * CC * 196) return;
    int w4 = idx % 14;
    int h4 = (idx / 14) % 14;
    int c  = (idx / 196) % CC;
    int b  = idx / (196 * CC);
    const float* pp = g_p3 + (size_t)(b * CC + c) * 196;
    float s = b3[c];
    #pragma unroll
    for (int i = 0; i < 3; i++) {
        int hh = h4 - 1 + i;
        if (hh < 0 || hh >= 14) continue;
        #pragma unroll
        for (int j = 0; j < 3; j++) {
            int ww = w4 - 1 + j;
            if (ww < 0 || ww >= 14) continue;
            s += pp[hh * 14 + ww] * w3[c * 9 + i * 3 + j];
        }
    }
    int m = h4 * 14 + w4;
    g_l[((size_t)b * MT + 392 + m) * CC + c] = fmaxf(s, 0.f);
}

// ---------------- LayerNorm over C, in place on g_l ----------------
__global__ __launch_bounds__(128) void k_ln(const float* __restrict__ gamma,
                                            const float* __restrict__ beta) {
    int row = blockIdx.x;                // b*MT + m
    float* p = g_l + (size_t)row * CC;
    int t = threadIdx.x;
    float4 v = *(float4*)(p + t * 4);
    float s  = v.x + v.y + v.z + v.w;
    float ss = v.x * v.x + v.y * v.y + v.z * v.z + v.w * v.w;
    #pragma unroll
    for (int o = 16; o >= 1; o >>= 1) {
        s  += __shfl_xor_sync(0xffffffffu, s, o);
        ss += __shfl_xor_sync(0xffffffffu, ss, o);
    }
    __shared__ float sh[8];
    int w = t >> 5;
    if ((t & 31) == 0) { sh[w * 2] = s; sh[w * 2 + 1] = ss; }
    __syncthreads();
    s  = sh[0] + sh[2] + sh[4] + sh[6];
    ss = sh[1] + sh[3] + sh[5] + sh[7];
    float mu  = s * (1.f / CC);
    float var = ss * (1.f / CC) - mu * mu;
    float r   = rsqrtf(var + 1e-5f);
    float4 g  = *(const float4*)(gamma + t * 4);
    float4 be = *(const float4*)(beta + t * 4);
    v.x = (v.x - mu) * r * g.x + be.x;
    v.y = (v.y - mu) * r * g.y + be.y;
    v.z = (v.z - mu) * r * g.z + be.z;
    v.w = (v.w - mu) * r * g.w + be.w;
    *(float4*)(p + t * 4) = v;
}

// ---------------- KV projection: kv[b,m,o] = g_l[b,m,:] . Wkv[o,:] + bkv[o] ----------------
__global__ __launch_bounds__(256) void k_kvproj(const float* __restrict__ Wkv,
                                                const float* __restrict__ bkv) {
    __shared__ float As[8][132];   // As[kk][mm] = l[m0+mm][c0+kk]
    __shared__ float Bs[8][132];   // Bs[kk][oo] = Wkv[o0+oo][c0+kk]
    const int b  = blockIdx.z;
    const int m0 = blockIdx.x * 128;
    const int o0 = blockIdx.y * 128;
    const float* A = g_l + (size_t)b * MT * CC;
    const int t  = threadIdx.x;
    const int tx = t & 15, ty = t >> 4;
    const int lr = t >> 1, lk = (t & 1) * 4;

    float acc[8][8] = {};
    for (int c0 = 0; c0 < CC; c0 += 8) {
        int m = m0 + lr;
        float4 va = make_float4(0.f, 0.f, 0.f, 0.f);
        if (m < MT) va = *(const float4*)(A + (size_t)m * CC + c0 + lk);
        As[lk + 0][lr] = va.x; As[lk + 1][lr] = va.y;
        As[lk + 2][lr] = va.z; As[lk + 3][lr] = va.w;
        float4 vb = *(const float4*)(Wkv + (size_t)(o0 + lr) * CC + c0 + lk);
        Bs[lk + 0][lr] = vb.x; Bs[lk + 1][lr] = vb.y;
        Bs[lk + 2][lr] = vb.z; Bs[lk + 3][lr] = vb.w;
        __syncthreads();
        #pragma unroll
        for (int kk = 0; kk < 8; kk++) {
            float ra[8], rb[8];
            #pragma unroll
            for (int i = 0; i < 8; i++) ra[i] = As[kk][tx + 16 * i];
            #pragma unroll
            for (int j = 0; j < 8; j++) rb[j] = Bs[kk][ty * 8 + j];
            #pragma unroll
            for (int i = 0; i < 8; i++)
                #pragma unroll
                for (int j = 0; j < 8; j++) acc[i][j] += ra[i] * rb[j];
        }
        __syncthreads();
    }
    #pragma unroll
    for (int i = 0; i < 8; i++) {
        int m = m0 + tx + 16 * i;
        if (m >= MT) continue;
        #pragma unroll
        for (int j = 0; j < 8; j++) {
            int o = o0 + ty * 8 + j;
            float val = acc[i][j] + bkv[o];
            if (o < 512) {
                g_k[(((size_t)b * NH + (o >> 6)) * MT + m) * HD + (o & 63)] = val;
            } else {
                int o2 = o - 512;
                g_v[(((size_t)b * NH + (o2 >> 6)) * MT + m) * HD + (o2 & 63)] = val;
            }
        }
    }
}

// ---------------- fused attention: softmax(QK^T * scale) V ----------------
// grid: (NT/64, BB*NH), block 256; dynamic smem 4 * 64*65 floats
__global__ __launch_bounds__(256) void k_attn(float* __restrict__ out) {
    extern __shared__ float sm[];
    float* q_s = sm;           // [64][65]
    float* k_s = sm + 4160;
    float* v_s = sm + 8320;
    float* p_s = sm + 12480;

    const int bh = blockIdx.y;
    const int b = bh >> 3, h = bh & 7;
    const int n0 = blockIdx.x * 64;
    const int t = threadIdx.x;
    const int tq = t >> 4, tj = t & 15;

    const float* qptr = g_q + ((size_t)b * NT + n0) * CC + h * HD;
    #pragma unroll
    for (int i = 0; i < 16; i++) {
        int f = i * 256 + t;
        int qi = f >> 6, d = f & 63;
        q_s[qi * 65 + d] = qptr[(size_t)qi * CC + d];
    }
    const float* kb = g_k + (size_t)bh * MT * HD;
    const float* vb = g_v + (size_t)bh * MT * HD;

    float m_run[4], l_run[4], acc[4][4];
    #pragma unroll
    for (int a = 0; a < 4; a++) {
        m_run[a] = -1e30f; l_run[a] = 0.f;
        #pragma unroll
        for (int dd = 0; dd < 4; dd++) acc[a][dd] = 0.f;
    }

    for (int j0 = 0; j0 < MT; j0 += 64) {
        __syncthreads();      // protect k_s/v_s/p_s from previous chunk readers
        #pragma unroll
        for (int i = 0; i < 16; i++) {
            int f = i * 256 + t;
            int jj = f >> 6, d = f & 63;
            int j = j0 + jj;
            float kk_ = 0.f, vv_ = 0.f;
            if (j < MT) { kk_ = kb[(size_t)j * HD + d]; vv_ = vb[(size_t)j * HD + d]; }
            k_s[jj * 65 + d] = kk_;
            v_s[jj * 65 + d] = vv_;
        }
        __syncthreads();

        float s[4][4];
        #pragma unroll
        for (int a = 0; a < 4; a++)
            #pragma unroll
            for (int e = 0; e < 4; e++) s[a][e] = 0.f;

        #pragma unroll 16
        for (int d = 0; d < 64; d++) {
            float qv[4], kv[4];
            #pragma unroll
            for (int a = 0; a < 4; a++) qv[a] = q_s[(tq + 16 * a) * 65 + d];
            #pragma unroll
            for (int e = 0; e < 4; e++) kv[e] = k_s[(tj + 16 * e) * 65 + d];
            #pragma unroll
            for (int a = 0; a < 4; a++)
                #pragma unroll
                for (int e = 0; e < 4; e++) s[a][e] += qv[a] * kv[e];
        }

        // scale + mask + row max
        float mx[4];
        #pragma unroll
        for (int a = 0; a < 4; a++) {
            mx[a] = -1e30f;
            #pragma unroll
            for (int e = 0; e < 4; e++) {
                int j = j0 + tj + 16 * e;
                s[a][e] = (j < MT) ? s[a][e] * ATT_SCALE : -1e30f;
                mx[a] = fmaxf(mx[a], s[a][e]);
            }
        }
        #pragma unroll
        for (int off = 8; off >= 1; off >>= 1)
            #pragma unroll
            for (int a = 0; a < 4; a++)
                mx[a] = fmaxf(mx[a], __shfl_xor_sync(0xffffffffu, mx[a], off));

        float lsum[4];
        #pragma unroll
        for (int a = 0; a < 4; a++) {
            float mn = fmaxf(m_run[a], mx[a]);
            float fac = __expf(m_run[a] - mn);
            #pragma unroll
            for (int e = 0; e < 4; e++) s[a][e] = __expf(s[a][e] - mn);
            lsum[a] = s[a][0] + s[a][1] + s[a][2] + s[a][3];
            l_run[a] *= fac;
            m_run[a] = mn;
            #pragma unroll
            for (int dd = 0; dd < 4; dd++) acc[a][dd] *= fac;
        }
        #pragma unroll
        for (int off = 8; off >= 1; off >>= 1)
            #pragma unroll
            for (int a = 0; a < 4; a++)
                lsum[a] += __shfl_xor_sync(0xffffffffu, lsum[a], off);
        #pragma unroll
        for (int a = 0; a < 4; a++) l_run[a] += lsum[a];

        #pragma unroll
        for (int a = 0; a < 4; a++)
            #pragma unroll
            for (int e = 0; e < 4; e++)
                p_s[(tq + 16 * a) * 65 + tj + 16 * e] = s[a][e];
        __syncthreads();

        #pragma unroll 16
        for (int j = 0; j < 64; j++) {
            float pv[4], vv[4];
            #pragma unroll
            for (int a = 0; a < 4; a++) pv[a] = p_s[(tq + 16 * a) * 65 + j];
            #pragma unroll
            for (int dd = 0; dd < 4; dd++) vv[dd] = v_s[j * 65 + tj + 16 * dd];
            #pragma unroll
            for (int a = 0; a < 4; a++)
                #pragma unroll
                for (int dd = 0; dd < 4; dd++) acc[a][dd] += pv[a] * vv[dd];
        }
    }

    float* ob = out + ((size_t)b * NT + n0) * CC + h * HD;
    #pragma unroll
    for (int a = 0; a < 4; a++) {
        float inv = 1.f / l_run[a];
        #pragma unroll
        for (int dd = 0; dd < 4; dd++)
            ob[(size_t)(tq + 16 * a) * CC + tj + 16 * dd] = acc[a][dd] * inv;
    }
}

// ---------------- launch ----------------
extern "C" void kernel_launch(void* const* d_in, const int* in_sizes, int n_in,
                              void* d_out, int out_size) {
    const float* x     = (const float*)d_in[0];
    const float* Wq    = (const float*)d_in[1];
    const float* bq    = (const float*)d_in[2];
    const float* Wkv   = (const float*)d_in[3];
    const float* bkv   = (const float*)d_in[4];
    const float* w1a   = (const float*)d_in[5];
    const float* b1a   = (const float*)d_in[6];
    const float* w1b   = (const float*)d_in[7];
    const float* b1b   = (const float*)d_in[8];
    const float* w2    = (const float*)d_in[9];
    const float* b2    = (const float*)d_in[10];
    const float* w3    = (const float*)d_in[11];
    const float* b3    = (const float*)d_in[12];
    const float* gamma = (const float*)d_in[13];
    const float* beta  = (const float*)d_in[14];
    float* out = (float*)d_out;

    const int attn_smem = 4 * 64 * 65 * (int)sizeof(float);   // 66560 B
    cudaFuncSetAttribute(k_attn, cudaFuncAttributeMaxDynamicSharedMemorySize, attn_smem);

    // Q projection
    dim3 gq((NT + 127) / 128, CC / 128, BB);
    k_qproj<<<gq, 256>>>(x, Wq, bq);

    // branches
    int n1a = BB * CC * HH * 14;
    k_b1a<<<(n1a + 255) / 256, 256>>>(x, w1a, b1a);
    int nb = BB * CC * 196;
    k_b1b<<<(nb + 255) / 256, 256>>>(w1b, b1b);
    k_b2<<<(nb + 255) / 256, 256>>>(x, w2, b2);
    k_pool3<<<(nb + 255) / 256, 256>>>(x);
    k_b3<<<(nb + 255) / 256, 256>>>(w3, b3);

    // LayerNorm
    k_ln<<<BB * MT, 128>>>(gamma, beta);

    // KV projection
    dim3 gkv((MT + 127) / 128, 1024 / 128, BB);
    k_kvproj<<<gkv, 256>>>(Wkv, bkv);

    // fused attention
    dim3 ga(NT / 64, BB * NH);
    k_attn<<<ga, 256, attn_smem>>>(out);
}

// round 4
// speedup vs baseline: 1.5507x; 1.5507x over previous
#include <cuda_runtime.h>
#include <cuda_bf16.h>
#include <cstdint>

// ---------------- problem constants ----------------
constexpr int BB = 8;      // batch
constexpr int CC = 512;    // channels
constexpr int HH = 56, WW = 56;
constexpr int NT = 3136;   // H*W tokens
constexpr int MT = 588;    // 3*196 downsampled tokens
constexpr int NH = 8;      // heads
constexpr int HD = 64;     // head dim
constexpr int NP = 3200;   // NT padded to 128
constexpr int MP = 640;    // MT padded to 128
#define ATT_SCALE 0.125f

// ---------------- scratch (device globals; zero-initialized) ----------------
__device__ float g_lf[BB * MT * CC];
__device__ float g_t1[BB * CC * HH * 14];
__device__ float g_p3[BB * CC * 14 * 14];

__device__ __nv_bfloat16 g_xh[(size_t)BB * NP * CC], g_xl[(size_t)BB * NP * CC];
__device__ __nv_bfloat16 g_wqh[CC * CC], g_wql[CC * CC];
__device__ __nv_bfloat16 g_wkh[2 * CC * CC], g_wkl[2 * CC * CC];
__device__ __nv_bfloat16 g_lh[(size_t)BB * MP * CC], g_ll[(size_t)BB * MP * CC];
__device__ __nv_bfloat16 g_qh[(size_t)BB * NP * CC], g_ql[(size_t)BB * NP * CC];
__device__ __nv_bfloat16 g_kh[(size_t)BB * NH * MP * HD], g_kl[(size_t)BB * NH * MP * HD];
__device__ __nv_bfloat16 g_vth[(size_t)BB * NH * HD * MP], g_vtl[(size_t)BB * NH * HD * MP];
__device__ float         g_s [(size_t)BB * NH * NP * MP];
__device__ __nv_bfloat16 g_ph[(size_t)BB * NH * NP * MP], g_pl[(size_t)BB * NH * NP * MP];

// ---------------- PTX helpers (base sm_103 feature set only) ----------------
__device__ __forceinline__ uint32_t smem_u32_of(const void* p) {
    uint32_t a;
    asm("{ .reg .u64 t; cvta.to.shared.u64 t, %1; cvt.u32.u64 %0, t; }" : "=r"(a) : "l"(p));
    return a;
}
__device__ __forceinline__ void cpa16(uint32_t dst, const void* src) {
    asm volatile("cp.async.cg.shared.global [%0], [%1], 16;" :: "r"(dst), "l"(src));
}
__device__ __forceinline__ void ldm4(uint32_t addr, uint32_t& r0, uint32_t& r1,
                                     uint32_t& r2, uint32_t& r3) {
    asm volatile("ldmatrix.sync.aligned.m8n8.x4.shared.b16 {%0,%1,%2,%3}, [%4];"
                 : "=r"(r0), "=r"(r1), "=r"(r2), "=r"(r3) : "r"(addr));
}
__device__ __forceinline__ void mma16816(float* d, const uint32_t* a, const uint32_t* b) {
    asm volatile(
        "mma.sync.aligned.m16n8k16.row.col.f32.bf16.bf16.f32 "
        "{%0,%1,%2,%3}, {%4,%5,%6,%7}, {%8,%9}, {%0,%1,%2,%3};"
        : "+f"(d[0]), "+f"(d[1]), "+f"(d[2]), "+f"(d[3])
        : "r"(a[0]), "r"(a[1]), "r"(a[2]), "r"(a[3]), "r"(b[0]), "r"(b[1]));
}

// ---------------- HMMA GEMM engine: C[128,64] = sum_seg A_seg[128,K] * B_seg[64,K]^T ----
// A row-major [rows][K] stride lda (elements), B row-major [64 n-rows][K] stride ldb.
// K processed in chunks of 32; cps chunks per segment, 3 segments (hi*hi, hi*lo, lo*hi).
constexpr int APITCH = 80;                 // bytes per smem row (64B data + 16B pad)
constexpr int ASTAGE = 128 * APITCH;       // 10240
constexpr int BSTAGE = 64 * APITCH;        // 5120
constexpr int STAGE  = ASTAGE + BSTAGE;    // 15360

struct Segs { const __nv_bfloat16* A[3]; const __nv_bfloat16* B[3]; };

__device__ __forceinline__ void gemm_load(const Segs& sg, int lda, int ldb, int cps,
                                          uint32_t su, int i, int buf, int t) {
    const int s = i / cps;
    const int kofs = (i - s * cps) * 32;
    const __nv_bfloat16* Ab = sg.A[s] + kofs;
    const __nv_bfloat16* Bb = sg.B[s] + kofs;
    const uint32_t ab = su + buf * STAGE;
    const uint32_t bb = ab + ASTAGE;
    #pragma unroll
    for (int j = 0; j < 2; j++) {               // A: 512 x 16B granules
        int g = j * 256 + t;
        int row = g >> 2, c16 = g & 3;
        cpa16(ab + row * APITCH + c16 * 16, Ab + (size_t)row * lda + c16 * 8);
    }
    {                                           // B: 256 x 16B granules
        int row = t >> 2, c16 = t & 3;
        cpa16(bb + row * APITCH + c16 * 16, Bb + (size_t)row * ldb + c16 * 8);
    }
    asm volatile("cp.async.commit_group;");
}

__device__ __forceinline__ void gemm_main(const Segs& sg, int lda, int ldb, int cps,
                                          uint32_t su, float acc[2][4][4]) {
    const int t = threadIdx.x;
    const int lane = t & 31, wid = t >> 5;
    const int wm = wid & 3, wn = wid >> 2;     // 4x2 warp grid
    const int nc = cps * 3;

    gemm_load(sg, lda, ldb, cps, su, 0, 0, t);
    for (int i = 0; i < nc; i++) {
        const int buf = i & 1;
        if (i + 1 < nc) {
            gemm_load(sg, lda, ldb, cps, su, i + 1, buf ^ 1, t);
            asm volatile("cp.async.wait_group 1;" ::: "memory");
        } else {
            asm volatile("cp.async.wait_group 0;" ::: "memory");
        }
        __syncthreads();
        const uint32_t ab = su + buf * STAGE;
        const uint32_t bb = ab + ASTAGE;
        #pragma unroll
        for (int k16 = 0; k16 < 2; k16++) {
            // A fragments: rows wm*32 + mi*16 + (lane%16), k byte = k16*32 + (lane/16)*16
            uint32_t af[2][4];
            uint32_t a_addr = ab + (wm * 32 + (lane & 15)) * APITCH + k16 * 32 + (lane >> 4) * 16;
            ldm4(a_addr,               af[0][0], af[0][1], af[0][2], af[0][3]);
            ldm4(a_addr + 16 * APITCH, af[1][0], af[1][1], af[1][2], af[1][3]);
            // B fragments: 4 n8 blocks per warp
            uint32_t bf[4][2];
            #pragma unroll
            for (int p = 0; p < 2; p++) {
                uint32_t b_addr = bb +
                    (wn * 32 + p * 16 + (lane & 7) + (((lane >> 3) & 1) ? 8 : 0)) * APITCH +
                    k16 * 32 + ((lane >> 4) & 1) * 16;
                uint32_t r0, r1, r2, r3;
                ldm4(b_addr, r0, r1, r2, r3);
                bf[2 * p][0] = r0; bf[2 * p + 1][0] = r1;
                bf[2 * p][1] = r2; bf[2 * p + 1][1] = r3;
            }
            #pragma unroll
            for (int mi = 0; mi < 2; mi++)
                #pragma unroll
                for (int ni = 0; ni < 4; ni++)
                    mma16816(acc[mi][ni], af[mi], bf[ni]);
        }
        __syncthreads();
    }
}

// acc element (mi, ni, e): row = wm*32 + mi*16 + lane/4 + (e>=2 ? 8:0)
//                          col = wn*32 + ni*8 + (lane%4)*2 + (e&1)
#define EPILOGUE_ITER(body)                                                    \
    {                                                                          \
        const int lane = threadIdx.x & 31, wid = threadIdx.x >> 5;             \
        const int wm = wid & 3, wn = wid >> 2;                                 \
        _Pragma("unroll")                                                      \
        for (int mi = 0; mi < 2; mi++)                                         \
            _Pragma("unroll")                                                  \
            for (int ni = 0; ni < 4; ni++)                                     \
                _Pragma("unroll")                                              \
                for (int e = 0; e < 4; e++) {                                  \
                    int row = wm * 32 + mi * 16 + (lane >> 2) + ((e >> 1) * 8);\
                    int col = wn * 32 + ni * 8 + (lane & 3) * 2 + (e & 1);     \
                    float v = acc[mi][ni][e];                                  \
                    body                                                       \
                }                                                              \
    }

// ================= GEMM kernels =================
__global__ __launch_bounds__(256) void k_qproj_t(const float* __restrict__ bq) {
    __shared__ __align__(128) uint8_t smem[2 * STAGE];
    uint32_t su = smem_u32_of(smem);
    const int b = blockIdx.z, m0 = blockIdx.x * 128, n0 = blockIdx.y * 64;
    Segs sg;
    const __nv_bfloat16* ah = g_xh + ((size_t)b * NP + m0) * CC;
    const __nv_bfloat16* al = g_xl + ((size_t)b * NP + m0) * CC;
    sg.A[0] = ah; sg.A[1] = ah; sg.A[2] = al;
    sg.B[0] = g_wqh + (size_t)n0 * CC; sg.B[1] = g_wql + (size_t)n0 * CC; sg.B[2] = sg.B[0];
    float acc[2][4][4] = {};
    gemm_main(sg, CC, CC, 16, su, acc);
    EPILOGUE_ITER({
        v += bq[n0 + col];
        __nv_bfloat16 h = __float2bfloat16(v);
        size_t o = ((size_t)b * NP + m0 + row) * CC + n0 + col;
        g_qh[o] = h;
        g_ql[o] = __float2bfloat16(v - __bfloat162float(h));
    })
}

__global__ __launch_bounds__(256) void k_kvproj_t(const float* __restrict__ bkv) {
    __shared__ __align__(128) uint8_t smem[2 * STAGE];
    uint32_t su = smem_u32_of(smem);
    const int b = blockIdx.z, m0 = blockIdx.x * 128, n0 = blockIdx.y * 64;
    Segs sg;
    const __nv_bfloat16* ah = g_lh + ((size_t)b * MP + m0) * CC;
    const __nv_bfloat16* al = g_ll + ((size_t)b * MP + m0) * CC;
    sg.A[0] = ah; sg.A[1] = ah; sg.A[2] = al;
    sg.B[0] = g_wkh + (size_t)n0 * CC; sg.B[1] = g_wkl + (size_t)n0 * CC; sg.B[2] = sg.B[0];
    float acc[2][4][4] = {};
    gemm_main(sg, CC, CC, 16, su, acc);
    EPILOGUE_ITER({
        int o = n0 + col;
        int m = m0 + row;
        v += bkv[o];
        __nv_bfloat16 h = __float2bfloat16(v);
        __nv_bfloat16 l = __float2bfloat16(v - __bfloat162float(h));
        if (o < 512) {
            size_t idx = (((size_t)b * NH + (o >> 6)) * MP + m) * HD + (o & 63);
            g_kh[idx] = h; g_kl[idx] = l;
        } else {
            int o2 = o - 512;
            size_t idx = (((size_t)b * NH + (o2 >> 6)) * HD + (o2 & 63)) * MP + m;
            g_vth[idx] = h; g_vtl[idx] = l;
        }
    })
}

__global__ __launch_bounds__(256) void k_qk_t() {
    __shared__ __align__(128) uint8_t smem[2 * STAGE];
    uint32_t su = smem_u32_of(smem);
    const int bh = blockIdx.z, b = bh >> 3, h = bh & 7;
    const int m0 = blockIdx.x * 128, n0 = blockIdx.y * 64;
    Segs sg;
    const __nv_bfloat16* ah = g_qh + ((size_t)b * NP + m0) * CC + h * HD;
    const __nv_bfloat16* al = g_ql + ((size_t)b * NP + m0) * CC + h * HD;
    const __nv_bfloat16* bhh = g_kh + ((size_t)bh * MP + n0) * HD;
    const __nv_bfloat16* bll = g_kl + ((size_t)bh * MP + n0) * HD;
    sg.A[0] = ah; sg.A[1] = ah; sg.A[2] = al;
    sg.B[0] = bhh; sg.B[1] = bll; sg.B[2] = bhh;
    float acc[2][4][4] = {};
    gemm_main(sg, CC, HD, 2, su, acc);
    EPILOGUE_ITER({
        g_s[((size_t)bh * NP + m0 + row) * MP + n0 + col] = v * ATT_SCALE;
    })
}

__global__ __launch_bounds__(256) void k_pv_t(float* __restrict__ out) {
    __shared__ __align__(128) uint8_t smem[2 * STAGE];
    uint32_t su = smem_u32_of(smem);
    const int bh = blockIdx.z, b = bh >> 3, h = bh & 7;
    const int m0 = blockIdx.x * 128;
    Segs sg;
    const __nv_bfloat16* ah = g_ph + (size_t)bh * NP * MP + (size_t)m0 * MP;
    const __nv_bfloat16* al = g_pl + (size_t)bh * NP * MP + (size_t)m0 * MP;
    const __nv_bfloat16* bhh = g_vth + (size_t)bh * HD * MP;
    const __nv_bfloat16* bll = g_vtl + (size_t)bh * HD * MP;
    sg.A[0] = ah; sg.A[1] = ah; sg.A[2] = al;
    sg.B[0] = bhh; sg.B[1] = bll; sg.B[2] = bhh;
    float acc[2][4][4] = {};
    gemm_main(sg, MP, MP, 20, su, acc);
    EPILOGUE_ITER({
        int n = m0 + row;
        if (n < NT) out[((size_t)b * NT + n) * CC + h * HD + col] = v;
    })
}

// ================= support kernels =================
__global__ __launch_bounds__(256) void k_tsplit(const float* __restrict__ x) {
    __shared__ float tile[32][33];
    const int b = blockIdx.z, n0 = blockIdx.x * 32, c0 = blockIdx.y * 32;
    const int tx = threadIdx.x & 31, ty = threadIdx.x >> 5;
    const float* xp = x + ((size_t)b * CC + c0) * NT + n0;
    #pragma unroll
    for (int i = 0; i < 4; i++)
        tile[ty + 8 * i][tx] = xp[(size_t)(ty + 8 * i) * NT + tx];
    __syncthreads();
    #pragma unroll
    for (int i = 0; i < 4; i++) {
        int r = ty + 8 * i;
        float v = tile[tx][r];
        size_t o = ((size_t)b * NP + n0 + r) * CC + c0 + tx;
        __nv_bfloat16 h = __float2bfloat16(v);
        g_xh[o] = h;
        g_xl[o] = __float2bfloat16(v - __bfloat162float(h));
    }
}

__global__ void k_splitw(const float* __restrict__ Wq, const float* __restrict__ Wkv) {
    int i = blockIdx.x * 256 + threadIdx.x;
    if (i < CC * CC) {
        float v = Wq[i];
        __nv_bfloat16 h = __float2bfloat16(v);
        g_wqh[i] = h; g_wql[i] = __float2bfloat16(v - __bfloat162float(h));
    }
    if (i < 2 * CC * CC) {
        float v = Wkv[i];
        __nv_bfloat16 h = __float2bfloat16(v);
        g_wkh[i] = h; g_wkl[i] = __float2bfloat16(v - __bfloat162float(h));
    }
}

__global__ void k_b1a(const float* __restrict__ x, const float* __restrict__ w1a,
                      const float* __restrict__ b1a) {
    int idx = blockIdx.x * 256 + threadIdx.x;
    if (idx >= BB * CC * HH * 14) return;
    int w4 = idx % 14, h = (idx / 14) % HH, c = (idx / (14 * HH)) % CC, b = idx / (14 * HH * CC);
    const float* xp = x + (((size_t)(b * CC + c) * HH) + h) * WW + 4 * w4;
    float s = b1a[c];
    #pragma unroll
    for (int r = 0; r < 4; r++) s += xp[r] * w1a[c * 4 + r];
    g_t1[idx] = fmaxf(s, 0.f);
}
__global__ void k_b1b(const float* __restrict__ w1b, const float* __restrict__ b1b) {
    int idx = blockIdx.x * 256 + threadIdx.x;
    if (idx >= BB * CC * 196) return;
    int w4 = idx % 14, h4 = (idx / 14) % 14, c = (idx / 196) % CC, b = idx / (196 * CC);
    float s = b1b[c];
    #pragma unroll
    for (int r = 0; r < 4; r++)
        s += g_t1[(((size_t)(b * CC + c) * HH) + 4 * h4 + r) * 14 + w4] * w1b[c * 4 + r];
    g_lf[((size_t)b * MT + h4 * 14 + w4) * CC + c] = fmaxf(s, 0.f);
}
__global__ void k_b2(const float* __restrict__ x, const float* __restrict__ w2,
                     const float* __restrict__ b2) {
    int idx = blockIdx.x * 256 + threadIdx.x;
    if (idx >= BB * CC * 196) return;
    int w4 = idx % 14, h4 = (idx / 14) % 14, c = (idx / 196) % CC, b = idx / (196 * CC);
    const float* xp = x + (((size_t)(b * CC + c) * HH) + 4 * h4) * WW + 4 * w4;
    float s = b2[c];
    #pragma unroll
    for (int i = 0; i < 4; i++)
        #pragma unroll
        for (int j = 0; j < 4; j++) s += xp[i * WW + j] * w2[c * 16 + i * 4 + j];
    g_lf[((size_t)b * MT + 196 + h4 * 14 + w4) * CC + c] = fmaxf(s, 0.f);
}
__global__ void k_pool3(const float* __restrict__ x) {
    int idx = blockIdx.x * 256 + threadIdx.x;
    if (idx >= BB * CC * 196) return;
    int w4 = idx % 14, h4 = (idx / 14) % 14, c = (idx / 196) % CC, b = idx / (196 * CC);
    const float* xp = x + (((size_t)(b * CC + c) * HH) + 4 * h4) * WW + 4 * w4;
    float s = 0.f;
    #pragma unroll
    for (int i = 0; i < 4; i++)
        #pragma unroll
        for (int j = 0; j < 4; j++) s += xp[i * WW + j];
    g_p3[idx] = s * (1.f / 16.f);
}
__global__ void k_b3(const float* __restrict__ w3, const float* __restrict__ b3) {
    int idx = blockIdx.x * 256 + threadIdx.x;
    if (idx >= BB * CC * 196) return;
    int w4 = idx % 14, h4 = (idx / 14) % 14, c = (idx / 196) % CC, b = idx / (196 * CC);
    const float* pp = g_p3 + (size_t)(b * CC + c) * 196;
    float s = b3[c];
    #pragma unroll
    for (int i = 0; i < 3; i++) {
        int hh = h4 - 1 + i;
        if (hh < 0 || hh >= 14) continue;
        #pragma unroll
        for (int j = 0; j < 3; j++) {
            int ww = w4 - 1 + j;
            if (ww < 0 || ww >= 14) continue;
            s += pp[hh * 14 + ww] * w3[c * 9 + i * 3 + j];
        }
    }
    g_lf[((size_t)b * MT + 392 + h4 * 14 + w4) * CC + c] = fmaxf(s, 0.f);
}

__global__ __launch_bounds__(128) void k_ln(const float* __restrict__ gamma,
                                            const float* __restrict__ beta) {
    const int row = blockIdx.x;
    const int b = row / MT, m = row - b * MT;
    const float* p = g_lf + (size_t)row * CC;
    const int t = threadIdx.x;
    float4 v = *(const float4*)(p + t * 4);
    float s = v.x + v.y + v.z + v.w;
    float ss = v.x * v.x + v.y * v.y + v.z * v.z + v.w * v.w;
    #pragma unroll
    for (int o = 16; o >= 1; o >>= 1) {
        s  += __shfl_xor_sync(0xffffffffu, s, o);
        ss += __shfl_xor_sync(0xffffffffu, ss, o);
    }
    __shared__ float sh[8];
    int w = t >> 5;
    if ((t & 31) == 0) { sh[w * 2] = s; sh[w * 2 + 1] = ss; }
    __syncthreads();
    s  = sh[0] + sh[2] + sh[4] + sh[6];
    ss = sh[1] + sh[3] + sh[5] + sh[7];
    float mu = s * (1.f / CC);
    float var = ss * (1.f / CC) - mu * mu;
    float r = rsqrtf(var + 1e-5f);
    float4 g = *(const float4*)(gamma + t * 4);
    float4 be = *(const float4*)(beta + t * 4);
    float o0 = (v.x - mu) * r * g.x + be.x;
    float o1 = (v.y - mu) * r * g.y + be.y;
    float o2 = (v.z - mu) * r * g.z + be.z;
    float o3 = (v.w - mu) * r * g.w + be.w;
    size_t base = ((size_t)b * MP + m) * CC + t * 4;
    __nv_bfloat16 h0 = __float2bfloat16(o0), h1 = __float2bfloat16(o1);
    __nv_bfloat16 h2 = __float2bfloat16(o2), h3 = __float2bfloat16(o3);
    g_lh[base + 0] = h0; g_ll[base + 0] = __float2bfloat16(o0 - __bfloat162float(h0));
    g_lh[base + 1] = h1; g_ll[base + 1] = __float2bfloat16(o1 - __bfloat162float(h1));
    g_lh[base + 2] = h2; g_ll[base + 2] = __float2bfloat16(o2 - __bfloat162float(h2));
    g_lh[base + 3] = h3; g_ll[base + 3] = __float2bfloat16(o3 - __bfloat162float(h3));
}

__global__ __launch_bounds__(128) void k_smax() {
    const int bh = blockIdx.y, n = blockIdx.x;
    const float* srow = g_s + ((size_t)bh * NP + n) * MP;
    const int t = threadIdx.x;
    float vals[5];
    float mx = -1e30f;
    #pragma unroll
    for (int i = 0; i < 5; i++) {
        int j = t + 128 * i;
        vals[i] = (j < MT) ? srow[j] : -1e30f;
        mx = fmaxf(mx, vals[i]);
    }
    #pragma unroll
    for (int o = 16; o >= 1; o >>= 1) mx = fmaxf(mx, __shfl_xor_sync(0xffffffffu, mx, o));
    __shared__ float red[4], red2[4];
    int w = t >> 5;
    if ((t & 31) == 0) red[w] = mx;
    __syncthreads();
    mx = fmaxf(fmaxf(red[0], red[1]), fmaxf(red[2], red[3]));
    float sum = 0.f;
    #pragma unroll
    for (int i = 0; i < 5; i++) {
        int j = t + 128 * i;
        float e = (j < MT) ? __expf(vals[i] - mx) : 0.f;
        vals[i] = e; sum += e;
    }
    #pragma unroll
    for (int o = 16; o >= 1; o >>= 1) sum += __shfl_xor_sync(0xffffffffu, sum, o);
    if ((t & 31) == 0) red2[w] = sum;
    __syncthreads();
    sum = red2[0] + red2[1] + red2[2] + red2[3];
    float inv = 1.f / sum;
    size_t base = ((size_t)bh * NP + n) * MP;
    #pragma unroll
    for (int i = 0; i < 5; i++) {
        int j = t + 128 * i;
        if (j < MT) {
            float pv = vals[i] * inv;
            __nv_bfloat16 h = __float2bfloat16(pv);
            g_ph[base + j] = h;
            g_pl[base + j] = __float2bfloat16(pv - __bfloat162float(h));
        }
    }
}

// ---------------- launch ----------------
extern "C" void kernel_launch(void* const* d_in, const int* in_sizes, int n_in,
                              void* d_out, int out_size) {
    const float* x     = (const float*)d_in[0];
    const float* Wq    = (const float*)d_in[1];
    const float* bq    = (const float*)d_in[2];
    const float* Wkv   = (const float*)d_in[3];
    const float* bkv   = (const float*)d_in[4];
    const float* w1a   = (const float*)d_in[5];
    const float* b1a   = (const float*)d_in[6];
    const float* w1b   = (const float*)d_in[7];
    const float* b1b   = (const float*)d_in[8];
    const float* w2    = (const float*)d_in[9];
    const float* b2    = (const float*)d_in[10];
    const float* w3    = (const float*)d_in[11];
    const float* b3    = (const float*)d_in[12];
    const float* gamma = (const float*)d_in[13];
    const float* beta  = (const float*)d_in[14];
    float* out = (float*)d_out;

    // input prep
    k_tsplit<<<dim3(NT / 32, CC / 32, BB), 256>>>(x);
    k_splitw<<<(2 * CC * CC + 255) / 256, 256>>>(Wq, Wkv);

    // branches
    int n1a = BB * CC * HH * 14;
    k_b1a<<<(n1a + 255) / 256, 256>>>(x, w1a, b1a);
    int nb = BB * CC * 196;
    k_b1b<<<(nb + 255) / 256, 256>>>(w1b, b1b);
    k_b2<<<(nb + 255) / 256, 256>>>(x, w2, b2);
    k_pool3<<<(nb + 255) / 256, 256>>>(x);
    k_b3<<<(nb + 255) / 256, 256>>>(w3, b3);

    // LN -> split tokens
    k_ln<<<BB * MT, 128>>>(gamma, beta);

    // projections (HMMA)
    k_qproj_t <<<dim3(NP / 128, CC / 64, BB), 256>>>(bq);
    k_kvproj_t<<<dim3(MP / 128, 2 * CC / 64, BB), 256>>>(bkv);

    // attention (HMMA)
    k_qk_t<<<dim3(NP / 128, MP / 64, BB * NH), 256>>>();
    k_smax<<<dim3(NT, BB * NH), 128>>>();
    k_pv_t<<<dim3(NP / 128, 1, BB * NH), 256>>>(out);
}

// round 6
// speedup vs baseline: 2.2634x; 1.4596x over previous
#include <cuda_runtime.h>
#include <cuda_bf16.h>
#include <cstdint>

// ---------------- problem constants ----------------
constexpr int BB = 8;      // batch
constexpr int CC = 512;    // channels
constexpr int HH = 56, WW = 56;
constexpr int NT = 3136;   // H*W tokens
constexpr int MT = 588;    // 3*196 downsampled tokens
constexpr int NH = 8;      // heads
constexpr int HD = 64;     // head dim
constexpr int NP = 3200;   // NT padded to 128
constexpr int MP = 640;    // MT padded to 128
#define ATT_SCALE 0.125f

// ---------------- scratch (device globals; zero-initialized) ----------------
__device__ float g_lf[BB * MT * CC];
__device__ float g_p3[BB * CC * 14 * 14];

__device__ __nv_bfloat16 g_xh[(size_t)BB * NP * CC], g_xl[(size_t)BB * NP * CC];
__device__ __nv_bfloat16 g_wqh[CC * CC], g_wql[CC * CC];
__device__ __nv_bfloat16 g_wkh[2 * CC * CC], g_wkl[2 * CC * CC];
__device__ __nv_bfloat16 g_lh[(size_t)BB * MP * CC], g_ll[(size_t)BB * MP * CC];
__device__ __nv_bfloat16 g_qh[(size_t)BB * NP * CC], g_ql[(size_t)BB * NP * CC];
__device__ __nv_bfloat16 g_kh[(size_t)BB * NH * MP * HD], g_kl[(size_t)BB * NH * MP * HD];
__device__ __nv_bfloat16 g_vth[(size_t)BB * NH * HD * MP], g_vtl[(size_t)BB * NH * HD * MP];

// ---------------- PTX helpers (base sm_103 feature set only) ----------------
__device__ __forceinline__ uint32_t smem_u32_of(const void* p) {
    uint32_t a;
    asm("{ .reg .u64 t; cvta.to.shared.u64 t, %1; cvt.u32.u64 %0, t; }" : "=r"(a) : "l"(p));
    return a;
}
__device__ __forceinline__ void cpa16(uint32_t dst, const void* src) {
    asm volatile("cp.async.cg.shared.global [%0], [%1], 16;" :: "r"(dst), "l"(src));
}
__device__ __forceinline__ void ldm4(uint32_t addr, uint32_t& r0, uint32_t& r1,
                                     uint32_t& r2, uint32_t& r3) {
    asm volatile("ldmatrix.sync.aligned.m8n8.x4.shared.b16 {%0,%1,%2,%3}, [%4];"
                 : "=r"(r0), "=r"(r1), "=r"(r2), "=r"(r3) : "r"(addr));
}
__device__ __forceinline__ void mma16816(float* d, const uint32_t* a, const uint32_t* b) {
    asm volatile(
        "mma.sync.aligned.m16n8k16.row.col.f32.bf16.bf16.f32 "
        "{%0,%1,%2,%3}, {%4,%5,%6,%7}, {%8,%9}, {%0,%1,%2,%3};"
        : "+f"(d[0]), "+f"(d[1]), "+f"(d[2]), "+f"(d[3])
        : "r"(a[0]), "r"(a[1]), "r"(a[2]), "r"(a[3]), "r"(b[0]), "r"(b[1]));
}
__device__ __forceinline__ uint32_t pack_bf2(float lo, float hi) {
    __nv_bfloat16 a = __float2bfloat16(lo), b = __float2bfloat16(hi);
    return ((uint32_t)__bfloat16_as_ushort(b) << 16) | (uint32_t)__bfloat16_as_ushort(a);
}

// ---------------- HMMA GEMM engine (projections): C[128,64] ----------------
constexpr int APITCH = 80;
constexpr int ASTAGE = 128 * APITCH;
constexpr int BSTAGE = 64 * APITCH;
constexpr int STAGE  = ASTAGE + BSTAGE;

struct Segs { const __nv_bfloat16* A[3]; const __nv_bfloat16* B[3]; };

__device__ __forceinline__ void gemm_load(const Segs& sg, int lda, int ldb, int cps,
                                          uint32_t su, int i, int buf, int t) {
    const int s = i / cps;
    const int kofs = (i - s * cps) * 32;
    const __nv_bfloat16* Ab = sg.A[s] + kofs;
    const __nv_bfloat16* Bb = sg.B[s] + kofs;
    const uint32_t ab = su + buf * STAGE;
    const uint32_t bb = ab + ASTAGE;
    #pragma unroll
    for (int j = 0; j < 2; j++) {
        int g = j * 256 + t;
        int row = g >> 2, c16 = g & 3;
        cpa16(ab + row * APITCH + c16 * 16, Ab + (size_t)row * lda + c16 * 8);
    }
    {
        int row = t >> 2, c16 = t & 3;
        cpa16(bb + row * APITCH + c16 * 16, Bb + (size_t)row * ldb + c16 * 8);
    }
    asm volatile("cp.async.commit_group;");
}

__device__ __forceinline__ void gemm_main(const Segs& sg, int lda, int ldb, int cps,
                                          uint32_t su, float acc[2][4][4]) {
    const int t = threadIdx.x;
    const int lane = t & 31, wid = t >> 5;
    const int wm = wid & 3, wn = wid >> 2;
    const int nc = cps * 3;

    gemm_load(sg, lda, ldb, cps, su, 0, 0, t);
    for (int i = 0; i < nc; i++) {
        const int buf = i & 1;
        if (i + 1 < nc) {
            gemm_load(sg, lda, ldb, cps, su, i + 1, buf ^ 1, t);
            asm volatile("cp.async.wait_group 1;" ::: "memory");
        } else {
            asm volatile("cp.async.wait_group 0;" ::: "memory");
        }
        __syncthreads();
        const uint32_t ab = su + buf * STAGE;
        const uint32_t bb = ab + ASTAGE;
        #pragma unroll
        for (int k16 = 0; k16 < 2; k16++) {
            uint32_t af[2][4];
            uint32_t a_addr = ab + (wm * 32 + (lane & 15)) * APITCH + k16 * 32 + (lane >> 4) * 16;
            ldm4(a_addr,               af[0][0], af[0][1], af[0][2], af[0][3]);
            ldm4(a_addr + 16 * APITCH, af[1][0], af[1][1], af[1][2], af[1][3]);
            uint32_t bf[4][2];
            #pragma unroll
            for (int p = 0; p < 2; p++) {
                uint32_t b_addr = bb +
                    (wn * 32 + p * 16 + (lane & 7) + (((lane >> 3) & 1) ? 8 : 0)) * APITCH +
                    k16 * 32 + ((lane >> 4) & 1) * 16;
                uint32_t r0, r1, r2, r3;
                ldm4(b_addr, r0, r1, r2, r3);
                bf[2 * p][0] = r0; bf[2 * p + 1][0] = r1;
                bf[2 * p][1] = r2; bf[2 * p + 1][1] = r3;
            }
            #pragma unroll
            for (int mi = 0; mi < 2; mi++)
                #pragma unroll
                for (int ni = 0; ni < 4; ni++)
                    mma16816(acc[mi][ni], af[mi], bf[ni]);
        }
        __syncthreads();
    }
}

#define EPILOGUE_ITER(body)                                                    \
    {                                                                          \
        const int lane = threadIdx.x & 31, wid = threadIdx.x >> 5;             \
        const int wm = wid & 3, wn = wid >> 2;                                 \
        _Pragma("unroll")                                                      \
        for (int mi = 0; mi < 2; mi++)                                         \
            _Pragma("unroll")                                                  \
            for (int ni = 0; ni < 4; ni++)                                     \
                _Pragma("unroll")                                              \
                for (int e = 0; e < 4; e++) {                                  \
                    int row = wm * 32 + mi * 16 + (lane >> 2) + ((e >> 1) * 8);\
                    int col = wn * 32 + ni * 8 + (lane & 3) * 2 + (e & 1);     \
                    float v = acc[mi][ni][e];                                  \
                    body                                                       \
                }                                                              \
    }

// ================= projection kernels =================
__global__ __launch_bounds__(256) void k_qproj_t(const float* __restrict__ bq) {
    __shared__ __align__(128) uint8_t smem[2 * STAGE];
    uint32_t su = smem_u32_of(smem);
    const int b = blockIdx.z, m0 = blockIdx.x * 128, n0 = blockIdx.y * 64;
    Segs sg;
    const __nv_bfloat16* ah = g_xh + ((size_t)b * NP + m0) * CC;
    const __nv_bfloat16* al = g_xl + ((size_t)b * NP + m0) * CC;
    sg.A[0] = ah; sg.A[1] = ah; sg.A[2] = al;
    sg.B[0] = g_wqh + (size_t)n0 * CC; sg.B[1] = g_wql + (size_t)n0 * CC; sg.B[2] = sg.B[0];
    float acc[2][4][4] = {};
    gemm_main(sg, CC, CC, 16, su, acc);
    EPILOGUE_ITER({
        v += bq[n0 + col];
        __nv_bfloat16 h = __float2bfloat16(v);
        size_t o = ((size_t)b * NP + m0 + row) * CC + n0 + col;
        g_qh[o] = h;
        g_ql[o] = __float2bfloat16(v - __bfloat162float(h));
    })
}

__global__ __launch_bounds__(256) void k_kvproj_t(const float* __restrict__ bkv) {
    __shared__ __align__(128) uint8_t smem[2 * STAGE];
    uint32_t su = smem_u32_of(smem);
    const int b = blockIdx.z, m0 = blockIdx.x * 128, n0 = blockIdx.y * 64;
    Segs sg;
    const __nv_bfloat16* ah = g_lh + ((size_t)b * MP + m0) * CC;
    const __nv_bfloat16* al = g_ll + ((size_t)b * MP + m0) * CC;
    sg.A[0] = ah; sg.A[1] = ah; sg.A[2] = al;
    sg.B[0] = g_wkh + (size_t)n0 * CC; sg.B[1] = g_wkl + (size_t)n0 * CC; sg.B[2] = sg.B[0];
    float acc[2][4][4] = {};
    gemm_main(sg, CC, CC, 16, su, acc);
    EPILOGUE_ITER({
        int o = n0 + col;
        int m = m0 + row;
        v += bkv[o];
        __nv_bfloat16 h = __float2bfloat16(v);
        __nv_bfloat16 l = __float2bfloat16(v - __bfloat162float(h));
        if (o < 512) {
            size_t idx = (((size_t)b * NH + (o >> 6)) * MP + m) * HD + (o & 63);
            g_kh[idx] = h; g_kl[idx] = l;
        } else {
            int o2 = o - 512;
            size_t idx = (((size_t)b * NH + (o2 >> 6)) * HD + (o2 & 63)) * MP + m;
            g_vth[idx] = h; g_vtl[idx] = l;
        }
    })
}

// ================= fused flash attention =================
// Full 64-element k-dim per row -> 128B data + 16B pad = 144B pitch.
// Layout: Qh[128][144] @0 (18432), Ql @18432;
//         chunk buf @36864 + buf*36864: Kh 64x144 (9216), Kl +9216, Vh +18432, Vl +27648.
constexpr int FPITCH  = 144;
constexpr int Q_BYTES = 128 * FPITCH;          // 18432
constexpr int T_BYTES = 64 * FPITCH;           // 9216
constexpr int CH_OFF  = 2 * Q_BYTES;           // 36864
constexpr int CH_SIZE = 4 * T_BYTES;           // 36864
constexpr int FLASH_SMEM = CH_OFF + 2 * CH_SIZE;   // 110592

__global__ __launch_bounds__(256) void k_flash(float* __restrict__ out) {
    extern __shared__ __align__(128) uint8_t fsm[];
    uint32_t su = smem_u32_of(fsm);
    const int bh = blockIdx.y, b = bh >> 3, h = bh & 7;
    const int n0 = blockIdx.x * 128;
    const int t = threadIdx.x, lane = t & 31, w = t >> 5;

    const __nv_bfloat16* qhp = g_qh + ((size_t)b * NP + n0) * CC + h * HD;
    const __nv_bfloat16* qlp = g_ql + ((size_t)b * NP + n0) * CC + h * HD;
    const __nv_bfloat16* khp = g_kh + (size_t)bh * MP * HD;
    const __nv_bfloat16* klp = g_kl + (size_t)bh * MP * HD;
    const __nv_bfloat16* vhp = g_vth + (size_t)bh * HD * MP;
    const __nv_bfloat16* vlp = g_vtl + (size_t)bh * HD * MP;

    // Q tiles (hi+lo): 128 rows x 8 granules each
    #pragma unroll
    for (int j = 0; j < 4; j++) {
        int g = j * 256 + t, row = g >> 3, c16 = g & 7;
        cpa16(su + row * FPITCH + c16 * 16,           qhp + (size_t)row * CC + c16 * 8);
        cpa16(su + Q_BYTES + row * FPITCH + c16 * 16, qlp + (size_t)row * CC + c16 * 8);
    }
    asm volatile("cp.async.commit_group;");

    auto load_chunk = [&](int ci, int buf) {
        uint32_t base = su + CH_OFF + buf * CH_SIZE;
        #pragma unroll
        for (int j = 0; j < 2; j++) {
            int g = j * 256 + t, row = g >> 3, c16 = g & 7;
            cpa16(base +               row * FPITCH + c16 * 16,
                  khp + (size_t)(ci * 64 + row) * HD + c16 * 8);
            cpa16(base + T_BYTES +     row * FPITCH + c16 * 16,
                  klp + (size_t)(ci * 64 + row) * HD + c16 * 8);
            cpa16(base + 2 * T_BYTES + row * FPITCH + c16 * 16,
                  vhp + (size_t)row * MP + ci * 64 + c16 * 8);
            cpa16(base + 3 * T_BYTES + row * FPITCH + c16 * 16,
                  vlp + (size_t)row * MP + ci * 64 + c16 * 8);
        }
        asm volatile("cp.async.commit_group;");
    };
    load_chunk(0, 0);
    load_chunk(1, 1);
    asm volatile("cp.async.wait_group 1;" ::: "memory");   // Q + chunk0 complete
    __syncthreads();

    // Q fragments in registers (A-frag layout, 4 k16 groups, hi+lo)
    uint32_t qfh[4][4], qfl[4][4];
    #pragma unroll
    for (int g = 0; g < 4; g++) {
        uint32_t addr = su + (w * 16 + (lane & 15)) * FPITCH + g * 32 + (lane >> 4) * 16;
        ldm4(addr,           qfh[g][0], qfh[g][1], qfh[g][2], qfh[g][3]);
        ldm4(addr + Q_BYTES, qfl[g][0], qfl[g][1], qfl[g][2], qfl[g][3]);
    }

    float m0 = -1e30f, m1 = -1e30f, l0 = 0.f, l1 = 0.f;
    float oa[8][4] = {};

    for (int ci = 0; ci < 10; ci++) {
        const int buf = ci & 1;
        const uint32_t kb = su + CH_OFF + buf * CH_SIZE;

        // ---- S = Qh*Kh + Qh*Kl + Ql*Kh (3-term bf16) ----
        float sa[8][4] = {};
        #pragma unroll
        for (int g = 0; g < 4; g++) {
            uint32_t bkh[8][2], bkl[8][2];
            #pragma unroll
            for (int p = 0; p < 4; p++) {
                uint32_t addr = kb + (p * 16 + (lane & 15)) * FPITCH
                              + g * 32 + ((lane >> 4) & 1) * 16;
                uint32_t r0, r1, r2, r3;
                ldm4(addr, r0, r1, r2, r3);
                bkh[2 * p][0] = r0; bkh[2 * p + 1][0] = r1;
                bkh[2 * p][1] = r2; bkh[2 * p + 1][1] = r3;
                ldm4(addr + T_BYTES, r0, r1, r2, r3);
                bkl[2 * p][0] = r0; bkl[2 * p + 1][0] = r1;
                bkl[2 * p][1] = r2; bkl[2 * p + 1][1] = r3;
            }
            #pragma unroll
            for (int nb = 0; nb < 8; nb++) {
                mma16816(sa[nb], qfh[g], bkh[nb]);
                mma16816(sa[nb], qfh[g], bkl[nb]);
                mma16816(sa[nb], qfl[g], bkh[nb]);
            }
        }

        // ---- scale + mask + online softmax ----
        if (ci == 9) {
            #pragma unroll
            for (int nb = 0; nb < 8; nb++)
                #pragma unroll
                for (int e = 0; e < 4; e++) {
                    int j = 576 + nb * 8 + (lane & 3) * 2 + (e & 1);
                    sa[nb][e] = (j < MT) ? sa[nb][e] * ATT_SCALE : -1e30f;
                }
        } else {
            #pragma unroll
            for (int nb = 0; nb < 8; nb++)
                #pragma unroll
                for (int e = 0; e < 4; e++) sa[nb][e] *= ATT_SCALE;
        }
        float mx0 = -1e30f, mx1 = -1e30f;
        #pragma unroll
        for (int nb = 0; nb < 8; nb++) {
            mx0 = fmaxf(mx0, fmaxf(sa[nb][0], sa[nb][1]));
            mx1 = fmaxf(mx1, fmaxf(sa[nb][2], sa[nb][3]));
        }
        mx0 = fmaxf(mx0, __shfl_xor_sync(0xffffffffu, mx0, 1));
        mx0 = fmaxf(mx0, __shfl_xor_sync(0xffffffffu, mx0, 2));
        mx1 = fmaxf(mx1, __shfl_xor_sync(0xffffffffu, mx1, 1));
        mx1 = fmaxf(mx1, __shfl_xor_sync(0xffffffffu, mx1, 2));
        float mn0 = fmaxf(m0, mx0), mn1 = fmaxf(m1, mx1);
        float al0 = __expf(m0 - mn0), al1 = __expf(m1 - mn1);
        m0 = mn0; m1 = mn1;
        float ps0 = 0.f, ps1 = 0.f;
        #pragma unroll
        for (int nb = 0; nb < 8; nb++) {
            sa[nb][0] = __expf(sa[nb][0] - mn0);
            sa[nb][1] = __expf(sa[nb][1] - mn0);
            sa[nb][2] = __expf(sa[nb][2] - mn1);
            sa[nb][3] = __expf(sa[nb][3] - mn1);
            ps0 += sa[nb][0] + sa[nb][1];
            ps1 += sa[nb][2] + sa[nb][3];
        }
        ps0 += __shfl_xor_sync(0xffffffffu, ps0, 1);
        ps0 += __shfl_xor_sync(0xffffffffu, ps0, 2);
        ps1 += __shfl_xor_sync(0xffffffffu, ps1, 1);
        ps1 += __shfl_xor_sync(0xffffffffu, ps1, 2);
        l0 = l0 * al0 + ps0;
        l1 = l1 * al1 + ps1;
        #pragma unroll
        for (int nb = 0; nb < 8; nb++) {
            oa[nb][0] *= al0; oa[nb][1] *= al0; oa[nb][2] *= al1; oa[nb][3] *= al1;
        }

        // ---- PV: O += Ph*Vh + Ph*Vl + Pl*Vh; P built in registers from sa ----
        #pragma unroll
        for (int g = 0; g < 4; g++) {
            uint32_t aph[4], apl[4];
            #pragma unroll
            for (int q = 0; q < 2; q++) {
                int nb = 2 * g + q;
                float p0 = sa[nb][0], p1 = sa[nb][1], p2 = sa[nb][2], p3 = sa[nb][3];
                uint32_t hi01 = pack_bf2(p0, p1);
                uint32_t hi23 = pack_bf2(p2, p3);
                aph[2 * q]     = hi01;
                aph[2 * q + 1] = hi23;
                float r0f = p0 - __bfloat162float(__ushort_as_bfloat16((unsigned short)(hi01 & 0xffff)));
                float r1f = p1 - __bfloat162float(__ushort_as_bfloat16((unsigned short)(hi01 >> 16)));
                float r2f = p2 - __bfloat162float(__ushort_as_bfloat16((unsigned short)(hi23 & 0xffff)));
                float r3f = p3 - __bfloat162float(__ushort_as_bfloat16((unsigned short)(hi23 >> 16)));
                apl[2 * q]     = pack_bf2(r0f, r1f);
                apl[2 * q + 1] = pack_bf2(r2f, r3f);
            }
            uint32_t bvh[8][2], bvl[8][2];
            #pragma unroll
            for (int p = 0; p < 4; p++) {
                uint32_t addr = kb + 2 * T_BYTES + (p * 16 + (lane & 15)) * FPITCH
                              + g * 32 + ((lane >> 4) & 1) * 16;
                uint32_t r0, r1, r2, r3;
                ldm4(addr, r0, r1, r2, r3);
                bvh[2 * p][0] = r0; bvh[2 * p + 1][0] = r1;
                bvh[2 * p][1] = r2; bvh[2 * p + 1][1] = r3;
                ldm4(addr + T_BYTES, r0, r1, r2, r3);
                bvl[2 * p][0] = r0; bvl[2 * p + 1][0] = r1;
                bvl[2 * p][1] = r2; bvl[2 * p + 1][1] = r3;
            }
            #pragma unroll
            for (int nd = 0; nd < 8; nd++) {
                mma16816(oa[nd], aph, bvh[nd]);
                mma16816(oa[nd], aph, bvl[nd]);
                mma16816(oa[nd], apl, bvh[nd]);
            }
        }

        // ---- pipeline: refill buf with chunk ci+2 ----
        __syncthreads();
        if (ci + 2 < 10) {
            load_chunk(ci + 2, buf);
            asm volatile("cp.async.wait_group 1;" ::: "memory");
        } else if (ci + 1 < 10) {
            asm volatile("cp.async.wait_group 0;" ::: "memory");
        }
        __syncthreads();
    }

    // ---- epilogue ----
    const float inv0 = 1.f / l0, inv1 = 1.f / l1;
    const int r0 = w * 16 + (lane >> 2);
    const int nq0 = n0 + r0, nq1 = nq0 + 8;
    #pragma unroll
    for (int nd = 0; nd < 8; nd++) {
        int d = h * HD + nd * 8 + (lane & 3) * 2;
        if (nq0 < NT) {
            float2 v = make_float2(oa[nd][0] * inv0, oa[nd][1] * inv0);
            *(float2*)(out + ((size_t)b * NT + nq0) * CC + d) = v;
        }
        if (nq1 < NT) {
            float2 v = make_float2(oa[nd][2] * inv1, oa[nd][3] * inv1);
            *(float2*)(out + ((size_t)b * NT + nq1) * CC + d) = v;
        }
    }
}

// ================= support kernels =================
__global__ __launch_bounds__(256) void k_tsplit(const float* __restrict__ x) {
    __shared__ float tile[32][33];
    const int b = blockIdx.z, n0 = blockIdx.x * 32, c0 = blockIdx.y * 32;
    const int tx = threadIdx.x & 31, ty = threadIdx.x >> 5;
    const float* xp = x + ((size_t)b * CC + c0) * NT + n0;
    #pragma unroll
    for (int i = 0; i < 4; i++)
        tile[ty + 8 * i][tx] = xp[(size_t)(ty + 8 * i) * NT + tx];
    __syncthreads();
    #pragma unroll
    for (int i = 0; i < 4; i++) {
        int r = ty + 8 * i;
        float v = tile[tx][r];
        size_t o = ((size_t)b * NP + n0 + r) * CC + c0 + tx;
        __nv_bfloat16 h = __float2bfloat16(v);
        g_xh[o] = h;
        g_xl[o] = __float2bfloat16(v - __bfloat162float(h));
    }
}

__global__ void k_splitw(const float* __restrict__ Wq, const float* __restrict__ Wkv) {
    int i = blockIdx.x * 256 + threadIdx.x;
    if (i < CC * CC) {
        float v = Wq[i];
        __nv_bfloat16 h = __float2bfloat16(v);
        g_wqh[i] = h; g_wql[i] = __float2bfloat16(v - __bfloat162float(h));
    }
    if (i < 2 * CC * CC) {
        float v = Wkv[i];
        __nv_bfloat16 h = __float2bfloat16(v);
        g_wkh[i] = h; g_wkl[i] = __float2bfloat16(v - __bfloat162float(h));
    }
}

// fused branches 1, 2 and pool: one read of each 4x4 x tile
__global__ void k_branch(const float* __restrict__ x,
                         const float* __restrict__ w1a, const float* __restrict__ b1a,
                         const float* __restrict__ w1b, const float* __restrict__ b1b,
                         const float* __restrict__ w2, const float* __restrict__ b2) {
    int idx = blockIdx.x * 256 + threadIdx.x;
    if (idx >= BB * CC * 196) return;
    int w4 = idx % 14, h4 = (idx / 14) % 14, c = (idx / 196) % CC, b = idx / (196 * CC);
    const float* xp = x + (((size_t)(b * CC + c) * HH) + 4 * h4) * WW + 4 * w4;
    float wa[4], wb_[4], wc[16];
    #pragma unroll
    for (int r = 0; r < 4; r++) { wa[r] = w1a[c * 4 + r]; wb_[r] = w1b[c * 4 + r]; }
    #pragma unroll
    for (int r = 0; r < 16; r++) wc[r] = w2[c * 16 + r];
    float ba = b1a[c];
    float l1 = b1b[c], l2 = b2[c], pool = 0.f;
    #pragma unroll
    for (int i = 0; i < 4; i++) {
        float4 xv = *(const float4*)(xp + (size_t)i * WW);
        float tmid = ba + xv.x * wa[0] + xv.y * wa[1] + xv.z * wa[2] + xv.w * wa[3];
        l1 += fmaxf(tmid, 0.f) * wb_[i];
        l2 += xv.x * wc[4 * i] + xv.y * wc[4 * i + 1] + xv.z * wc[4 * i + 2] + xv.w * wc[4 * i + 3];
        pool += xv.x + xv.y + xv.z + xv.w;
    }
    int m = h4 * 14 + w4;
    g_lf[((size_t)b * MT + m) * CC + c] = fmaxf(l1, 0.f);
    g_lf[((size_t)b * MT + 196 + m) * CC + c] = fmaxf(l2, 0.f);
    g_p3[idx] = pool * (1.f / 16.f);
}

__global__ void k_b3(const float* __restrict__ w3, const float* __restrict__ b3) {
    int idx = blockIdx.x * 256 + threadIdx.x;
    if (idx >= BB * CC * 196) return;
    int w4 = idx % 14, h4 = (idx / 14) % 14, c = (idx / 196) % CC, b = idx / (196 * CC);
    const float* pp = g_p3 + (size_t)(b * CC + c) * 196;
    float s = b3[c];
    #pragma unroll
    for (int i = 0; i < 3; i++) {
        int hh = h4 - 1 + i;
        if (hh < 0 || hh >= 14) continue;
        #pragma unroll
        for (int j = 0; j < 3; j++) {
            int ww = w4 - 1 + j;
            if (ww < 0 || ww >= 14) continue;
            s += pp[hh * 14 + ww] * w3[c * 9 + i * 3 + j];
        }
    }
    g_lf[((size_t)b * MT + 392 + h4 * 14 + w4) * CC + c] = fmaxf(s, 0.f);
}

__global__ __launch_bounds__(128) void k_ln(const float* __restrict__ gamma,
                                            const float* __restrict__ beta) {
    const int row = blockIdx.x;
    const int b = row / MT, m = row - b * MT;
    const float* p = g_lf + (size_t)row * CC;
    const int t = threadIdx.x;
    float4 v = *(const float4*)(p + t * 4);
    float s = v.x + v.y + v.z + v.w;
    float ss = v.x * v.x + v.y * v.y + v.z * v.z + v.w * v.w;
    #pragma unroll
    for (int o = 16; o >= 1; o >>= 1) {
        s  += __shfl_xor_sync(0xffffffffu, s, o);
        ss += __shfl_xor_sync(0xffffffffu, ss, o);
    }
    __shared__ float sh[8];
    int w = t >> 5;
    if ((t & 31) == 0) { sh[w * 2] = s; sh[w * 2 + 1] = ss; }
    __syncthreads();
    s  = sh[0] + sh[2] + sh[4] + sh[6];
    ss = sh[1] + sh[3] + sh[5] + sh[7];
    float mu = s * (1.f / CC);
    float var = ss * (1.f / CC) - mu * mu;
    float r = rsqrtf(var + 1e-5f);
    float4 g = *(const float4*)(gamma + t * 4);
    float4 be = *(const float4*)(beta + t * 4);
    float o0 = (v.x - mu) * r * g.x + be.x;
    float o1 = (v.y - mu) * r * g.y + be.y;
    float o2 = (v.z - mu) * r * g.z + be.z;
    float o3 = (v.w - mu) * r * g.w + be.w;
    size_t base = ((size_t)b * MP + m) * CC + t * 4;
    __nv_bfloat16 h0 = __float2bfloat16(o0), h1 = __float2bfloat16(o1);
    __nv_bfloat16 h2 = __float2bfloat16(o2), h3 = __float2bfloat16(o3);
    g_lh[base + 0] = h0; g_ll[base + 0] = __float2bfloat16(o0 - __bfloat162float(h0));
    g_lh[base + 1] = h1; g_ll[base + 1] = __float2bfloat16(o1 - __bfloat162float(h1));
    g_lh[base + 2] = h2; g_ll[base + 2] = __float2bfloat16(o2 - __bfloat162float(h2));
    g_lh[base + 3] = h3; g_ll[base + 3] = __float2bfloat16(o3 - __bfloat162float(h3));
}

// ---------------- launch ----------------
extern "C" void kernel_launch(void* const* d_in, const int* in_sizes, int n_in,
                              void* d_out, int out_size) {
    const float* x     = (const float*)d_in[0];
    const float* Wq    = (const float*)d_in[1];
    const float* bq    = (const float*)d_in[2];
    const float* Wkv   = (const float*)d_in[3];
    const float* bkv   = (const float*)d_in[4];
    const float* w1a   = (const float*)d_in[5];
    const float* b1a   = (const float*)d_in[6];
    const float* w1b   = (const float*)d_in[7];
    const float* b1b   = (const float*)d_in[8];
    const float* w2    = (const float*)d_in[9];
    const float* b2    = (const float*)d_in[10];
    const float* w3    = (const float*)d_in[11];
    const float* b3    = (const float*)d_in[12];
    const float* gamma = (const float*)d_in[13];
    const float* beta  = (const float*)d_in[14];
    float* out = (float*)d_out;

    cudaFuncSetAttribute(k_flash, cudaFuncAttributeMaxDynamicSharedMemorySize, FLASH_SMEM);

    // input prep
    k_tsplit<<<dim3(NT / 32, CC / 32, BB), 256>>>(x);
    k_splitw<<<(2 * CC * CC + 255) / 256, 256>>>(Wq, Wkv);

    // branches (fused) + b3
    int nb = BB * CC * 196;
    k_branch<<<(nb + 255) / 256, 256>>>(x, w1a, b1a, w1b, b1b, w2, b2);
    k_b3<<<(nb + 255) / 256, 256>>>(w3, b3);

    // LN -> split tokens
    k_ln<<<BB * MT, 128>>>(gamma, beta);

    // projections (HMMA)
    k_qproj_t <<<dim3(NP / 128, CC / 64, BB), 256>>>(bq);
    k_kvproj_t<<<dim3(MP / 128, 2 * CC / 64, BB), 256>>>(bkv);

    // fused flash attention
    k_flash<<<dim3(NP / 128, BB * NH), 256, FLASH_SMEM>>>(out);
}

// round 8
// speedup vs baseline: 2.5334x; 1.1193x over previous
#include <cuda_runtime.h>
#include <cuda_bf16.h>
#include <cstdint>

// ---------------- problem constants ----------------
constexpr int BB = 8;      // batch
constexpr int CC = 512;    // channels
constexpr int HH = 56, WW = 56;
constexpr int NT = 3136;   // H*W tokens
constexpr int MT = 588;    // 3*196 downsampled tokens
constexpr int NH = 8;      // heads
constexpr int HD = 64;     // head dim
constexpr int NP = 3200;   // NT padded to 128
constexpr int MP = 640;    // MT padded to 128
#define ATT_SCALE 0.125f

// ---------------- scratch (device globals; zero-initialized) ----------------
__device__ float g_lf[BB * MT * CC];

__device__ __nv_bfloat16 g_xh[(size_t)BB * NP * CC], g_xl[(size_t)BB * NP * CC];
__device__ __nv_bfloat16 g_wqh[CC * CC], g_wql[CC * CC];
__device__ __nv_bfloat16 g_wkh[2 * CC * CC], g_wkl[2 * CC * CC];
__device__ __nv_bfloat16 g_lh[(size_t)BB * MP * CC], g_ll[(size_t)BB * MP * CC];
__device__ __nv_bfloat16 g_qh[(size_t)BB * NP * CC], g_ql[(size_t)BB * NP * CC];
__device__ __nv_bfloat16 g_kh[(size_t)BB * NH * MP * HD], g_kl[(size_t)BB * NH * MP * HD];
__device__ __nv_bfloat16 g_vth[(size_t)BB * NH * HD * MP], g_vtl[(size_t)BB * NH * HD * MP];

// ---------------- PTX helpers (base sm_103 feature set only) ----------------
__device__ __forceinline__ uint32_t smem_u32_of(const void* p) {
    uint32_t a;
    asm("{ .reg .u64 t; cvta.to.shared.u64 t, %1; cvt.u32.u64 %0, t; }" : "=r"(a) : "l"(p));
    return a;
}
__device__ __forceinline__ void cpa16(uint32_t dst, const void* src) {
    asm volatile("cp.async.cg.shared.global [%0], [%1], 16;" :: "r"(dst), "l"(src));
}
__device__ __forceinline__ void ldm4(uint32_t addr, uint32_t& r0, uint32_t& r1,
                                     uint32_t& r2, uint32_t& r3) {
    asm volatile("ldmatrix.sync.aligned.m8n8.x4.shared.b16 {%0,%1,%2,%3}, [%4];"
                 : "=r"(r0), "=r"(r1), "=r"(r2), "=r"(r3) : "r"(addr));
}
__device__ __forceinline__ void mma16816(float* d, const uint32_t* a, const uint32_t* b) {
    asm volatile(
        "mma.sync.aligned.m16n8k16.row.col.f32.bf16.bf16.f32 "
        "{%0,%1,%2,%3}, {%4,%5,%6,%7}, {%8,%9}, {%0,%1,%2,%3};"
        : "+f"(d[0]), "+f"(d[1]), "+f"(d[2]), "+f"(d[3])
        : "r"(a[0]), "r"(a[1]), "r"(a[2]), "r"(a[3]), "r"(b[0]), "r"(b[1]));
}
__device__ __forceinline__ uint32_t pack_bf2(float lo, float hi) {
    __nv_bfloat16 a = __float2bfloat16(lo), b = __float2bfloat16(hi);
    return ((uint32_t)__bfloat16_as_ushort(b) << 16) | (uint32_t)__bfloat16_as_ushort(a);
}

// ---------------- HMMA GEMM engine v2: per-K-chunk 4-tile load, 3-term fused ----------
// Stage: Ah[128][80] @0, Al @10240, Bh[64][80] @20480, Bl @25600.  STAGE=30720.
constexpr int GSTAGE = 30720;
constexpr int GEMM_SMEM = 2 * GSTAGE;    // 61440 dynamic

__device__ __forceinline__ void g2_load(const __nv_bfloat16* Ah, const __nv_bfloat16* Al,
                                        const __nv_bfloat16* Bh, const __nv_bfloat16* Bl,
                                        int lda, int ldb, uint32_t base, int koff, int t) {
    #pragma unroll
    for (int j = 0; j < 2; j++) {
        int g = j * 256 + t;
        int row = g >> 2, c16 = g & 3;
        cpa16(base +         row * 80 + c16 * 16, Ah + (size_t)row * lda + koff + c16 * 8);
        cpa16(base + 10240 + row * 80 + c16 * 16, Al + (size_t)row * lda + koff + c16 * 8);
    }
    {
        int row = t >> 2, c16 = t & 3;
        cpa16(base + 20480 + row * 80 + c16 * 16, Bh + (size_t)row * ldb + koff + c16 * 8);
        cpa16(base + 25600 + row * 80 + c16 * 16, Bl + (size_t)row * ldb + koff + c16 * 8);
    }
    asm volatile("cp.async.commit_group;");
}

__device__ __forceinline__ void gemm_main2(const __nv_bfloat16* Ah, const __nv_bfloat16* Al,
                                           const __nv_bfloat16* Bh, const __nv_bfloat16* Bl,
                                           int lda, int ldb, int nchunks,
                                           uint32_t su, float acc[2][4][4]) {
    const int t = threadIdx.x;
    const int lane = t & 31, wid = t >> 5;
    const int wm = wid & 3, wn = wid >> 2;

    g2_load(Ah, Al, Bh, Bl, lda, ldb, su, 0, t);
    for (int i = 0; i < nchunks; i++) {
        const int buf = i & 1;
        if (i + 1 < nchunks) {
            g2_load(Ah, Al, Bh, Bl, lda, ldb, su + (buf ^ 1) * GSTAGE, (i + 1) * 32, t);
            asm volatile("cp.async.wait_group 1;" ::: "memory");
        } else {
            asm volatile("cp.async.wait_group 0;" ::: "memory");
        }
        __syncthreads();
        const uint32_t ab = su + buf * GSTAGE;
        #pragma unroll
        for (int k16 = 0; k16 < 2; k16++) {
            uint32_t afh[2][4], afl[2][4];
            uint32_t a_addr = ab + (wm * 32 + (lane & 15)) * 80 + k16 * 32 + (lane >> 4) * 16;
            ldm4(a_addr,                 afh[0][0], afh[0][1], afh[0][2], afh[0][3]);
            ldm4(a_addr + 16 * 80,       afh[1][0], afh[1][1], afh[1][2], afh[1][3]);
            ldm4(a_addr + 10240,         afl[0][0], afl[0][1], afl[0][2], afl[0][3]);
            ldm4(a_addr + 10240 + 1280,  afl[1][0], afl[1][1], afl[1][2], afl[1][3]);
            uint32_t bfh[4][2], bfl[4][2];
            #pragma unroll
            for (int p = 0; p < 2; p++) {
                uint32_t b_addr = ab + 20480 + (wn * 32 + p * 16 + (lane & 15)) * 80
                                + k16 * 32 + ((lane >> 4) & 1) * 16;
                uint32_t r0, r1, r2, r3;
                ldm4(b_addr, r0, r1, r2, r3);
                bfh[2 * p][0] = r0; bfh[2 * p + 1][0] = r1;
                bfh[2 * p][1] = r2; bfh[2 * p + 1][1] = r3;
                ldm4(b_addr + 5120, r0, r1, r2, r3);
                bfl[2 * p][0] = r0; bfl[2 * p + 1][0] = r1;
                bfl[2 * p][1] = r2; bfl[2 * p + 1][1] = r3;
            }
            #pragma unroll
            for (int mi = 0; mi < 2; mi++)
                #pragma unroll
                for (int ni = 0; ni < 4; ni++) {
                    mma16816(acc[mi][ni], afh[mi], bfh[ni]);
                    mma16816(acc[mi][ni], afh[mi], bfl[ni]);
                    mma16816(acc[mi][ni], afl[mi], bfh[ni]);
                }
        }
        __syncthreads();
    }
}

#define EPILOGUE_ITER(body)                                                    \
    {                                                                          \
        const int lane = threadIdx.x & 31, wid = threadIdx.x >> 5;             \
        const int wm = wid & 3, wn = wid >> 2;                                 \
        _Pragma("unroll")                                                      \
        for (int mi = 0; mi < 2; mi++)                                         \
            _Pragma("unroll")                                                  \
            for (int ni = 0; ni < 4; ni++)                                     \
                _Pragma("unroll")                                              \
                for (int e = 0; e < 4; e++) {                                  \
                    int row = wm * 32 + mi * 16 + (lane >> 2) + ((e >> 1) * 8);\
                    int col = wn * 32 + ni * 8 + (lane & 3) * 2 + (e & 1);     \
                    float v = acc[mi][ni][e];                                  \
                    body                                                       \
                }                                                              \
    }

// ================= projection kernels =================
__global__ __launch_bounds__(256) void k_qproj_t(const float* __restrict__ bq) {
    extern __shared__ __align__(128) uint8_t smem[];
    uint32_t su = smem_u32_of(smem);
    const int b = blockIdx.z, m0 = blockIdx.x * 128, n0 = blockIdx.y * 64;
    float acc[2][4][4] = {};
    gemm_main2(g_xh + ((size_t)b * NP + m0) * CC, g_xl + ((size_t)b * NP + m0) * CC,
               g_wqh + (size_t)n0 * CC, g_wql + (size_t)n0 * CC,
               CC, CC, 16, su, acc);
    EPILOGUE_ITER({
        v += bq[n0 + col];
        __nv_bfloat16 h = __float2bfloat16(v);
        size_t o = ((size_t)b * NP + m0 + row) * CC + n0 + col;
        g_qh[o] = h;
        g_ql[o] = __float2bfloat16(v - __bfloat162float(h));
    })
}

__global__ __launch_bounds__(256) void k_kvproj_t(const float* __restrict__ bkv) {
    extern __shared__ __align__(128) uint8_t smem[];
    uint32_t su = smem_u32_of(smem);
    const int b = blockIdx.z, m0 = blockIdx.x * 128, n0 = blockIdx.y * 64;
    float acc[2][4][4] = {};
    gemm_main2(g_lh + ((size_t)b * MP + m0) * CC, g_ll + ((size_t)b * MP + m0) * CC,
               g_wkh + (size_t)n0 * CC, g_wkl + (size_t)n0 * CC,
               CC, CC, 16, su, acc);
    EPILOGUE_ITER({
        int o = n0 + col;
        int m = m0 + row;
        v += bkv[o];
        __nv_bfloat16 h = __float2bfloat16(v);
        __nv_bfloat16 l = __float2bfloat16(v - __bfloat162float(h));
        if (o < 512) {
            size_t idx = (((size_t)b * NH + (o >> 6)) * MP + m) * HD + (o & 63);
            g_kh[idx] = h; g_kl[idx] = l;
        } else {
            int o2 = o - 512;
            size_t idx = (((size_t)b * NH + (o2 >> 6)) * HD + (o2 & 63)) * MP + m;
            g_vth[idx] = h; g_vtl[idx] = l;
        }
    })
}

// ================= fused flash attention (fixed-shift softmax) =================
constexpr int FPITCH  = 144;
constexpr int Q_BYTES = 128 * FPITCH;          // 18432
constexpr int T_BYTES = 64 * FPITCH;           // 9216
constexpr int CH_OFF  = 2 * Q_BYTES;           // 36864
constexpr int CH_SIZE = 4 * T_BYTES;           // 36864
constexpr int FLASH_SMEM = CH_OFF + 2 * CH_SIZE;   // 110592

__global__ __launch_bounds__(256) void k_flash(float* __restrict__ out) {
    extern __shared__ __align__(128) uint8_t fsm[];
    uint32_t su = smem_u32_of(fsm);
    const int bh = blockIdx.y, b = bh >> 3, h = bh & 7;
    const int n0 = blockIdx.x * 128;
    const int t = threadIdx.x, lane = t & 31, w = t >> 5;

    const __nv_bfloat16* qhp = g_qh + ((size_t)b * NP + n0) * CC + h * HD;
    const __nv_bfloat16* qlp = g_ql + ((size_t)b * NP + n0) * CC + h * HD;
    const __nv_bfloat16* khp = g_kh + (size_t)bh * MP * HD;
    const __nv_bfloat16* klp = g_kl + (size_t)bh * MP * HD;
    const __nv_bfloat16* vhp = g_vth + (size_t)bh * HD * MP;
    const __nv_bfloat16* vlp = g_vtl + (size_t)bh * HD * MP;

    #pragma unroll
    for (int j = 0; j < 4; j++) {
        int g = j * 256 + t, row = g >> 3, c16 = g & 7;
        cpa16(su + row * FPITCH + c16 * 16,           qhp + (size_t)row * CC + c16 * 8);
        cpa16(su + Q_BYTES + row * FPITCH + c16 * 16, qlp + (size_t)row * CC + c16 * 8);
    }
    asm volatile("cp.async.commit_group;");

    auto load_chunk = [&](int ci, int buf) {
        uint32_t base = su + CH_OFF + buf * CH_SIZE;
        #pragma unroll
        for (int j = 0; j < 2; j++) {
            int g = j * 256 + t, row = g >> 3, c16 = g & 7;
            cpa16(base +               row * FPITCH + c16 * 16,
                  khp + (size_t)(ci * 64 + row) * HD + c16 * 8);
            cpa16(base + T_BYTES +     row * FPITCH + c16 * 16,
                  klp + (size_t)(ci * 64 + row) * HD + c16 * 8);
            cpa16(base + 2 * T_BYTES + row * FPITCH + c16 * 16,
                  vhp + (size_t)row * MP + ci * 64 + c16 * 8);
            cpa16(base + 3 * T_BYTES + row * FPITCH + c16 * 16,
                  vlp + (size_t)row * MP + ci * 64 + c16 * 8);
        }
        asm volatile("cp.async.commit_group;");
    };
    load_chunk(0, 0);
    load_chunk(1, 1);
    asm volatile("cp.async.wait_group 1;" ::: "memory");
    __syncthreads();

    uint32_t qfh[4][4], qfl[4][4];
    #pragma unroll
    for (int g = 0; g < 4; g++) {
        uint32_t addr = su + (w * 16 + (lane & 15)) * FPITCH + g * 32 + (lane >> 4) * 16;
        ldm4(addr,           qfh[g][0], qfh[g][1], qfh[g][2], qfh[g][3]);
        ldm4(addr + Q_BYTES, qfl[g][0], qfl[g][1], qfl[g][2], qfl[g][3]);
    }

    float l0 = 0.f, l1 = 0.f;
    float oa[8][4] = {};

    for (int ci = 0; ci < 10; ci++) {
        const int buf = ci & 1;
        const uint32_t kb = su + CH_OFF + buf * CH_SIZE;

        // ---- S = Qh*Kh + Qh*Kl + Ql*Kh ----
        float sa[8][4] = {};
        #pragma unroll
        for (int g = 0; g < 4; g++) {
            uint32_t bkh[8][2], bkl[8][2];
            #pragma unroll
            for (int p = 0; p < 4; p++) {
                uint32_t addr = kb + (p * 16 + (lane & 15)) * FPITCH
                              + g * 32 + ((lane >> 4) & 1) * 16;
                uint32_t r0, r1, r2, r3;
                ldm4(addr, r0, r1, r2, r3);
                bkh[2 * p][0] = r0; bkh[2 * p + 1][0] = r1;
                bkh[2 * p][1] = r2; bkh[2 * p + 1][1] = r3;
                ldm4(addr + T_BYTES, r0, r1, r2, r3);
                bkl[2 * p][0] = r0; bkl[2 * p + 1][0] = r1;
                bkl[2 * p][1] = r2; bkl[2 * p + 1][1] = r3;
            }
            #pragma unroll
            for (int nb = 0; nb < 8; nb++) {
                mma16816(sa[nb], qfh[g], bkh[nb]);
                mma16816(sa[nb], qfh[g], bkl[nb]);
                mma16816(sa[nb], qfl[g], bkh[nb]);
            }
        }

        // ---- fixed-shift softmax: probs bounded, no running max needed ----
        float ps0 = 0.f, ps1 = 0.f;
        if (ci == 9) {
            #pragma unroll
            for (int nb = 0; nb < 8; nb++)
                #pragma unroll
                for (int e = 0; e < 4; e++) {
                    int j = 576 + nb * 8 + (lane & 3) * 2 + (e & 1);
                    float ev = (j < MT) ? __expf(sa[nb][e] * ATT_SCALE) : 0.f;
                    sa[nb][e] = ev;
                    if (e < 2) ps0 += ev; else ps1 += ev;
                }
        } else {
            #pragma unroll
            for (int nb = 0; nb < 8; nb++)
                #pragma unroll
                for (int e = 0; e < 4; e++) {
                    float ev = __expf(sa[nb][e] * ATT_SCALE);
                    sa[nb][e] = ev;
                    if (e < 2) ps0 += ev; else ps1 += ev;
                }
        }
        ps0 += __shfl_xor_sync(0xffffffffu, ps0, 1);
        ps0 += __shfl_xor_sync(0xffffffffu, ps0, 2);
        ps1 += __shfl_xor_sync(0xffffffffu, ps1, 1);
        ps1 += __shfl_xor_sync(0xffffffffu, ps1, 2);
        l0 += ps0;
        l1 += ps1;

        // ---- PV: O += Ph*Vh + Ph*Vl + Pl*Vh ----
        #pragma unroll
        for (int g = 0; g < 4; g++) {
            uint32_t aph[4], apl[4];
            #pragma unroll
            for (int q = 0; q < 2; q++) {
                int nb = 2 * g + q;
                float p0 = sa[nb][0], p1 = sa[nb][1], p2 = sa[nb][2], p3 = sa[nb][3];
                uint32_t hi01 = pack_bf2(p0, p1);
                uint32_t hi23 = pack_bf2(p2, p3);
                aph[2 * q]     = hi01;
                aph[2 * q + 1] = hi23;
                float r0f = p0 - __bfloat162float(__ushort_as_bfloat16((unsigned short)(hi01 & 0xffff)));
                float r1f = p1 - __bfloat162float(__ushort_as_bfloat16((unsigned short)(hi01 >> 16)));
                float r2f = p2 - __bfloat162float(__ushort_as_bfloat16((unsigned short)(hi23 & 0xffff)));
                float r3f = p3 - __bfloat162float(__ushort_as_bfloat16((unsigned short)(hi23 >> 16)));
                apl[2 * q]     = pack_bf2(r0f, r1f);
                apl[2 * q + 1] = pack_bf2(r2f, r3f);
            }
            uint32_t bvh[8][2], bvl[8][2];
            #pragma unroll
            for (int p = 0; p < 4; p++) {
                uint32_t addr = kb + 2 * T_BYTES + (p * 16 + (lane & 15)) * FPITCH
                              + g * 32 + ((lane >> 4) & 1) * 16;
                uint32_t r0, r1, r2, r3;
                ldm4(addr, r0, r1, r2, r3);
                bvh[2 * p][0] = r0; bvh[2 * p + 1][0] = r1;
                bvh[2 * p][1] = r2; bvh[2 * p + 1][1] = r3;
                ldm4(addr + T_BYTES, r0, r1, r2, r3);
                bvl[2 * p][0] = r0; bvl[2 * p + 1][0] = r1;
                bvl[2 * p][1] = r2; bvl[2 * p + 1][1] = r3;
            }
            #pragma unroll
            for (int nd = 0; nd < 8; nd++) {
                mma16816(oa[nd], aph, bvh[nd]);
                mma16816(oa[nd], aph, bvl[nd]);
                mma16816(oa[nd], apl, bvh[nd]);
            }
        }

        __syncthreads();
        if (ci + 2 < 10) {
            load_chunk(ci + 2, buf);
            asm volatile("cp.async.wait_group 1;" ::: "memory");
        } else if (ci + 1 < 10) {
            asm volatile("cp.async.wait_group 0;" ::: "memory");
        }
        __syncthreads();
    }

    const float inv0 = 1.f / l0, inv1 = 1.f / l1;
    const int r0 = w * 16 + (lane >> 2);
    const int nq0 = n0 + r0, nq1 = nq0 + 8;
    #pragma unroll
    for (int nd = 0; nd < 8; nd++) {
        int d = h * HD + nd * 8 + (lane & 3) * 2;
        if (nq0 < NT) {
            float2 v = make_float2(oa[nd][0] * inv0, oa[nd][1] * inv0);
            *(float2*)(out + ((size_t)b * NT + nq0) * CC + d) = v;
        }
        if (nq1 < NT) {
            float2 v = make_float2(oa[nd][2] * inv1, oa[nd][3] * inv1);
            *(float2*)(out + ((size_t)b * NT + nq1) * CC + d) = v;
        }
    }
}

// ================= support kernels =================
__global__ __launch_bounds__(256) void k_tsplit(const float* __restrict__ x) {
    __shared__ float tile[32][33];
    const int b = blockIdx.z, n0 = blockIdx.x * 32, c0 = blockIdx.y * 32;
    const int tx = threadIdx.x & 31, ty = threadIdx.x >> 5;
    const float* xp = x + ((size_t)b * CC + c0) * NT + n0;
    #pragma unroll
    for (int i = 0; i < 4; i++)
        tile[ty + 8 * i][tx] = xp[(size_t)(ty + 8 * i) * NT + tx];
    __syncthreads();
    #pragma unroll
    for (int i = 0; i < 4; i++) {
        int r = ty + 8 * i;
        float v = tile[tx][r];
        size_t o = ((size_t)b * NP + n0 + r) * CC + c0 + tx;
        __nv_bfloat16 h = __float2bfloat16(v);
        g_xh[o] = h;
        g_xl[o] = __float2bfloat16(v - __bfloat162float(h));
    }
}

__global__ void k_splitw(const float* __restrict__ Wq, const float* __restrict__ Wkv) {
    int i = blockIdx.x * 256 + threadIdx.x;
    if (i < CC * CC) {
        float v = Wq[i];
        __nv_bfloat16 h = __float2bfloat16(v);
        g_wqh[i] = h; g_wql[i] = __float2bfloat16(v - __bfloat162float(h));
    }
    if (i < 2 * CC * CC) {
        float v = Wkv[i];
        __nv_bfloat16 h = __float2bfloat16(v);
        g_wkh[i] = h; g_wkl[i] = __float2bfloat16(v - __bfloat162float(h));
    }
}

// fused branches 1, 2, 3: one block per (b, c); pooled plane staged in SMEM
__global__ __launch_bounds__(224) void k_branch(const float* __restrict__ x,
        const float* __restrict__ w1a, const float* __restrict__ b1a,
        const float* __restrict__ w1b, const float* __restrict__ b1b,
        const float* __restrict__ w2, const float* __restrict__ b2,
        const float* __restrict__ w3, const float* __restrict__ b3) {
    __shared__ float pool_s[196];
    const int bc = blockIdx.x;
    const int b = bc / CC, c = bc % CC;
    const int t = threadIdx.x;

    if (t < 196) {
        int w4 = t % 14, h4 = t / 14;
        const float* xp = x + (((size_t)bc * HH) + 4 * h4) * WW + 4 * w4;
        float wa[4], wb_[4], wc[16];
        #pragma unroll
        for (int r = 0; r < 4; r++) { wa[r] = w1a[c * 4 + r]; wb_[r] = w1b[c * 4 + r]; }
        #pragma unroll
        for (int r = 0; r < 16; r++) wc[r] = w2[c * 16 + r];
        float ba = b1a[c];
        float l1 = b1b[c], l2 = b2[c], pool = 0.f;
        #pragma unroll
        for (int i = 0; i < 4; i++) {
            float4 xv = *(const float4*)(xp + (size_t)i * WW);
            float tmid = ba + xv.x * wa[0] + xv.y * wa[1] + xv.z * wa[2] + xv.w * wa[3];
            l1 += fmaxf(tmid, 0.f) * wb_[i];
            l2 += xv.x * wc[4 * i] + xv.y * wc[4 * i + 1] + xv.z * wc[4 * i + 2] + xv.w * wc[4 * i + 3];
            pool += xv.x + xv.y + xv.z + xv.w;
        }
        g_lf[((size_t)b * MT + t) * CC + c] = fmaxf(l1, 0.f);
        g_lf[((size_t)b * MT + 196 + t) * CC + c] = fmaxf(l2, 0.f);
        pool_s[t] = pool * (1.f / 16.f);
    }
    __syncthreads();
    if (t < 196) {
        int w4 = t % 14, h4 = t / 14;
        float s = b3[c];
        #pragma unroll
        for (int i = 0; i < 3; i++) {
            int hh = h4 - 1 + i;
            if (hh < 0 || hh >= 14) continue;
            #pragma unroll
            for (int j = 0; j < 3; j++) {
                int ww = w4 - 1 + j;
                if (ww < 0 || ww >= 14) continue;
                s += pool_s[hh * 14 + ww] * w3[c * 9 + i * 3 + j];
            }
        }
        g_lf[((size_t)b * MT + 392 + t) * CC + c] = fmaxf(s, 0.f);
    }
}

__global__ __launch_bounds__(128) void k_ln(const float* __restrict__ gamma,
                                            const float* __restrict__ beta) {
    const int row = blockIdx.x;
    const int b = row / MT, m = row - b * MT;
    const float* p = g_lf + (size_t)row * CC;
    const int t = threadIdx.x;
    float4 v = *(const float4*)(p + t * 4);
    float s = v.x + v.y + v.z + v.w;
    float ss = v.x * v.x + v.y * v.y + v.z * v.z + v.w * v.w;
    #pragma unroll
    for (int o = 16; o >= 1; o >>= 1) {
        s  += __shfl_xor_sync(0xffffffffu, s, o);
        ss += __shfl_xor_sync(0xffffffffu, ss, o);
    }
    __shared__ float sh[8];
    int w = t >> 5;
    if ((t & 31) == 0) { sh[w * 2] = s; sh[w * 2 + 1] = ss; }
    __syncthreads();
    s  = sh[0] + sh[2] + sh[4] + sh[6];
    ss = sh[1] + sh[3] + sh[5] + sh[7];
    float mu = s * (1.f / CC);
    float var = ss * (1.f / CC) - mu * mu;
    float r = rsqrtf(var + 1e-5f);
    float4 g = *(const float4*)(gamma + t * 4);
    float4 be = *(const float4*)(beta + t * 4);
    float o0 = (v.x - mu) * r * g.x + be.x;
    float o1 = (v.y - mu) * r * g.y + be.y;
    float o2 = (v.z - mu) * r * g.z + be.z;
    float o3 = (v.w - mu) * r * g.w + be.w;
    size_t base = ((size_t)b * MP + m) * CC + t * 4;
    __nv_bfloat16 h0 = __float2bfloat16(o0), h1 = __float2bfloat16(o1);
    __nv_bfloat16 h2 = __float2bfloat16(o2), h3 = __float2bfloat16(o3);
    g_lh[base + 0] = h0; g_ll[base + 0] = __float2bfloat16(o0 - __bfloat162float(h0));
    g_lh[base + 1] = h1; g_ll[base + 1] = __float2bfloat16(o1 - __bfloat162float(h1));
    g_lh[base + 2] = h2; g_ll[base + 2] = __float2bfloat16(o2 - __bfloat162float(h2));
    g_lh[base + 3] = h3; g_ll[base + 3] = __float2bfloat16(o3 - __bfloat162float(h3));
}

// ---------------- launch ----------------
extern "C" void kernel_launch(void* const* d_in, const int* in_sizes, int n_in,
                              void* d_out, int out_size) {
    const float* x     = (const float*)d_in[0];
    const float* Wq    = (const float*)d_in[1];
    const float* bq    = (const float*)d_in[2];
    const float* Wkv   = (const float*)d_in[3];
    const float* bkv   = (const float*)d_in[4];
    const float* w1a   = (const float*)d_in[5];
    const float* b1a   = (const float*)d_in[6];
    const float* w1b   = (const float*)d_in[7];
    const float* b1b   = (const float*)d_in[8];
    const float* w2    = (const float*)d_in[9];
    const float* b2    = (const float*)d_in[10];
    const float* w3    = (const float*)d_in[11];
    const float* b3    = (const float*)d_in[12];
    const float* gamma = (const float*)d_in[13];
    const float* beta  = (const float*)d_in[14];
    float* out = (float*)d_out;

    cudaFuncSetAttribute(k_flash,    cudaFuncAttributeMaxDynamicSharedMemorySize, FLASH_SMEM);
    cudaFuncSetAttribute(k_qproj_t,  cudaFuncAttributeMaxDynamicSharedMemorySize, GEMM_SMEM);
    cudaFuncSetAttribute(k_kvproj_t, cudaFuncAttributeMaxDynamicSharedMemorySize, GEMM_SMEM);

    // input prep
    k_tsplit<<<dim3(NT / 32, CC / 32, BB), 256>>>(x);
    k_splitw<<<(2 * CC * CC + 255) / 256, 256>>>(Wq, Wkv);

    // fused branches
    k_branch<<<BB * CC, 224>>>(x, w1a, b1a, w1b, b1b, w2, b2, w3, b3);

    // LN -> split tokens
    k_ln<<<BB * MT, 128>>>(gamma, beta);

    // projections (HMMA)
    k_qproj_t <<<dim3(NP / 128, CC / 64, BB), 256, GEMM_SMEM>>>(bq);
    k_kvproj_t<<<dim3(MP / 128, 2 * CC / 64, BB), 256, GEMM_SMEM>>>(bkv);

    // fused flash attention
    k_flash<<<dim3(NP / 128, BB * NH), 256, FLASH_SMEM>>>(out);
}

// round 9
// speedup vs baseline: 2.7169x; 1.0724x over previous
#include <cuda_runtime.h>
#include <cuda_bf16.h>
#include <cstdint>

// ---------------- problem constants ----------------
constexpr int BB = 8;      // batch
constexpr int CC = 512;    // channels
constexpr int HH = 56, WW = 56;
constexpr int NT = 3136;   // H*W tokens
constexpr int MT = 588;    // 3*196 downsampled tokens
constexpr int NH = 8;      // heads
constexpr int HD = 64;     // head dim
constexpr int NP = 3200;   // NT padded to 128
constexpr int MP = 640;    // MT padded to 128
#define ATT_SCALE 0.125f

// ---------------- scratch (device globals; zero-initialized) ----------------
__device__ float g_lf[BB * MT * CC];

__device__ __nv_bfloat16 g_xh[(size_t)BB * NP * CC], g_xl[(size_t)BB * NP * CC];
__device__ __nv_bfloat16 g_wqh[CC * CC], g_wql[CC * CC];
__device__ __nv_bfloat16 g_wkh[2 * CC * CC], g_wkl[2 * CC * CC];
__device__ __nv_bfloat16 g_lh[(size_t)BB * MP * CC], g_ll[(size_t)BB * MP * CC];
__device__ __nv_bfloat16 g_qh[(size_t)BB * NP * CC], g_ql[(size_t)BB * NP * CC];
__device__ __nv_bfloat16 g_kh[(size_t)BB * NH * MP * HD], g_kl[(size_t)BB * NH * MP * HD];
__device__ __nv_bfloat16 g_vth[(size_t)BB * NH * HD * MP], g_vtl[(size_t)BB * NH * HD * MP];

// ---------------- PTX helpers (base sm_103 feature set only) ----------------
__device__ __forceinline__ uint32_t smem_u32_of(const void* p) {
    uint32_t a;
    asm("{ .reg .u64 t; cvta.to.shared.u64 t, %1; cvt.u32.u64 %0, t; }" : "=r"(a) : "l"(p));
    return a;
}
__device__ __forceinline__ void cpa16(uint32_t dst, const void* src) {
    asm volatile("cp.async.cg.shared.global [%0], [%1], 16;" :: "r"(dst), "l"(src));
}
__device__ __forceinline__ void ldm4(uint32_t addr, uint32_t& r0, uint32_t& r1,
                                     uint32_t& r2, uint32_t& r3) {
    asm volatile("ldmatrix.sync.aligned.m8n8.x4.shared.b16 {%0,%1,%2,%3}, [%4];"
                 : "=r"(r0), "=r"(r1), "=r"(r2), "=r"(r3) : "r"(addr));
}
__device__ __forceinline__ void mma16816(float* d, const uint32_t* a, const uint32_t* b) {
    asm volatile(
        "mma.sync.aligned.m16n8k16.row.col.f32.bf16.bf16.f32 "
        "{%0,%1,%2,%3}, {%4,%5,%6,%7}, {%8,%9}, {%0,%1,%2,%3};"
        : "+f"(d[0]), "+f"(d[1]), "+f"(d[2]), "+f"(d[3])
        : "r"(a[0]), "r"(a[1]), "r"(a[2]), "r"(a[3]), "r"(b[0]), "r"(b[1]));
}
__device__ __forceinline__ uint32_t pack_bf2(float lo, float hi) {
    __nv_bfloat16 a = __float2bfloat16(lo), b = __float2bfloat16(hi);
    return ((uint32_t)__bfloat16_as_ushort(b) << 16) | (uint32_t)__bfloat16_as_ushort(a);
}

// ---------------- HMMA GEMM engine v2: per-K-chunk 4-tile load, 3-term fused ----------
// Stage: Ah[128][80] @0, Al @10240, Bh[64][80] @20480, Bl @25600.  STAGE=30720.
constexpr int GSTAGE = 30720;
constexpr int GEMM_SMEM = 2 * GSTAGE;    // 61440 dynamic

__device__ __forceinline__ void g2_load(const __nv_bfloat16* Ah, const __nv_bfloat16* Al,
                                        const __nv_bfloat16* Bh, const __nv_bfloat16* Bl,
                                        int lda, int ldb, uint32_t base, int koff, int t) {
    #pragma unroll
    for (int j = 0; j < 2; j++) {
        int g = j * 256 + t;
        int row = g >> 2, c16 = g & 3;
        cpa16(base +         row * 80 + c16 * 16, Ah + (size_t)row * lda + koff + c16 * 8);
        cpa16(base + 10240 + row * 80 + c16 * 16, Al + (size_t)row * lda + koff + c16 * 8);
    }
    {
        int row = t >> 2, c16 = t & 3;
        cpa16(base + 20480 + row * 80 + c16 * 16, Bh + (size_t)row * ldb + koff + c16 * 8);
        cpa16(base + 25600 + row * 80 + c16 * 16, Bl + (size_t)row * ldb + koff + c16 * 8);
    }
    asm volatile("cp.async.commit_group;");
}

__device__ __forceinline__ void gemm_main2(const __nv_bfloat16* Ah, const __nv_bfloat16* Al,
                                           const __nv_bfloat16* Bh, const __nv_bfloat16* Bl,
                                           int lda, int ldb, int nchunks,
                                           uint32_t su, float acc[2][4][4]) {
    const int t = threadIdx.x;
    const int lane = t & 31, wid = t >> 5;
    const int wm = wid & 3, wn = wid >> 2;

    g2_load(Ah, Al, Bh, Bl, lda, ldb, su, 0, t);
    for (int i = 0; i < nchunks; i++) {
        const int buf = i & 1;
        if (i + 1 < nchunks) {
            g2_load(Ah, Al, Bh, Bl, lda, ldb, su + (buf ^ 1) * GSTAGE, (i + 1) * 32, t);
            asm volatile("cp.async.wait_group 1;" ::: "memory");
        } else {
            asm volatile("cp.async.wait_group 0;" ::: "memory");
        }
        __syncthreads();
        const uint32_t ab = su + buf * GSTAGE;
        #pragma unroll
        for (int k16 = 0; k16 < 2; k16++) {
            uint32_t afh[2][4], afl[2][4];
            uint32_t a_addr = ab + (wm * 32 + (lane & 15)) * 80 + k16 * 32 + (lane >> 4) * 16;
            ldm4(a_addr,                 afh[0][0], afh[0][1], afh[0][2], afh[0][3]);
            ldm4(a_addr + 16 * 80,       afh[1][0], afh[1][1], afh[1][2], afh[1][3]);
            ldm4(a_addr + 10240,         afl[0][0], afl[0][1], afl[0][2], afl[0][3]);
            ldm4(a_addr + 10240 + 1280,  afl[1][0], afl[1][1], afl[1][2], afl[1][3]);
            uint32_t bfh[4][2], bfl[4][2];
            #pragma unroll
            for (int p = 0; p < 2; p++) {
                uint32_t b_addr = ab + 20480 + (wn * 32 + p * 16 + (lane & 15)) * 80
                                + k16 * 32 + ((lane >> 4) & 1) * 16;
                uint32_t r0, r1, r2, r3;
                ldm4(b_addr, r0, r1, r2, r3);
                bfh[2 * p][0] = r0; bfh[2 * p + 1][0] = r1;
                bfh[2 * p][1] = r2; bfh[2 * p + 1][1] = r3;
                ldm4(b_addr + 5120, r0, r1, r2, r3);
                bfl[2 * p][0] = r0; bfl[2 * p + 1][0] = r1;
                bfl[2 * p][1] = r2; bfl[2 * p + 1][1] = r3;
            }
            #pragma unroll
            for (int mi = 0; mi < 2; mi++)
                #pragma unroll
                for (int ni = 0; ni < 4; ni++) {
                    mma16816(acc[mi][ni], afh[mi], bfh[ni]);
                    mma16816(acc[mi][ni], afh[mi], bfl[ni]);
                    mma16816(acc[mi][ni], afl[mi], bfh[ni]);
                }
        }
        __syncthreads();
    }
}

#define EPILOGUE_ITER(body)                                                    \
    {                                                                          \
        const int lane = threadIdx.x & 31, wid = threadIdx.x >> 5;             \
        const int wm = wid & 3, wn = wid >> 2;                                 \
        _Pragma("unroll")                                                      \
        for (int mi = 0; mi < 2; mi++)                                         \
            _Pragma("unroll")                                                  \
            for (int ni = 0; ni < 4; ni++)                                     \
                _Pragma("unroll")                                              \
                for (int e = 0; e < 4; e++) {                                  \
                    int row = wm * 32 + mi * 16 + (lane >> 2) + ((e >> 1) * 8);\
                    int col = wn * 32 + ni * 8 + (lane & 3) * 2 + (e & 1);     \
                    float v = acc[mi][ni][e];                                  \
                    body                                                       \
                }                                                              \
    }

// ================= projection kernels =================
__global__ __launch_bounds__(256) void k_qproj_t(const float* __restrict__ bq) {
    extern __shared__ __align__(128) uint8_t smem[];
    uint32_t su = smem_u32_of(smem);
    const int b = blockIdx.z, m0 = blockIdx.x * 128, n0 = blockIdx.y * 64;
    float acc[2][4][4] = {};
    gemm_main2(g_xh + ((size_t)b * NP + m0) * CC, g_xl + ((size_t)b * NP + m0) * CC,
               g_wqh + (size_t)n0 * CC, g_wql + (size_t)n0 * CC,
               CC, CC, 16, su, acc);
    EPILOGUE_ITER({
        v += bq[n0 + col];
        __nv_bfloat16 h = __float2bfloat16(v);
        size_t o = ((size_t)b * NP + m0 + row) * CC + n0 + col;
        g_qh[o] = h;
        g_ql[o] = __float2bfloat16(v - __bfloat162float(h));
    })
}

__global__ __launch_bounds__(256) void k_kvproj_t(const float* __restrict__ bkv) {
    extern __shared__ __align__(128) uint8_t smem[];
    uint32_t su = smem_u32_of(smem);
    const int b = blockIdx.z, m0 = blockIdx.x * 128, n0 = blockIdx.y * 64;
    float acc[2][4][4] = {};
    gemm_main2(g_lh + ((size_t)b * MP + m0) * CC, g_ll + ((size_t)b * MP + m0) * CC,
               g_wkh + (size_t)n0 * CC, g_wkl + (size_t)n0 * CC,
               CC, CC, 16, su, acc);
    EPILOGUE_ITER({
        int o = n0 + col;
        int m = m0 + row;
        v += bkv[o];
        __nv_bfloat16 h = __float2bfloat16(v);
        __nv_bfloat16 l = __float2bfloat16(v - __bfloat162float(h));
        if (o < 512) {
            size_t idx = (((size_t)b * NH + (o >> 6)) * MP + m) * HD + (o & 63);
            g_kh[idx] = h; g_kl[idx] = l;
        } else {
            int o2 = o - 512;
            size_t idx = (((size_t)b * NH + (o2 >> 6)) * HD + (o2 & 63)) * MP + m;
            g_vth[idx] = h; g_vtl[idx] = l;
        }
    })
}

// ================= fused flash attention (fixed-shift softmax, 2 CTA/SM) =========
constexpr int FPITCH  = 144;
constexpr int Q_BYTES = 128 * FPITCH;          // 18432
constexpr int T_BYTES = 64 * FPITCH;           // 9216
constexpr int CH_OFF  = 2 * Q_BYTES;           // 36864
constexpr int CH_SIZE = 4 * T_BYTES;           // 36864
constexpr int FLASH_SMEM = CH_OFF + 2 * CH_SIZE;   // 110592

__global__ __launch_bounds__(256, 2) void k_flash(float* __restrict__ out) {
    extern __shared__ __align__(128) uint8_t fsm[];
    uint32_t su = smem_u32_of(fsm);
    const int bh = blockIdx.y, b = bh >> 3, h = bh & 7;
    const int n0 = blockIdx.x * 128;
    const int t = threadIdx.x, lane = t & 31, w = t >> 5;

    const __nv_bfloat16* qhp = g_qh + ((size_t)b * NP + n0) * CC + h * HD;
    const __nv_bfloat16* qlp = g_ql + ((size_t)b * NP + n0) * CC + h * HD;
    const __nv_bfloat16* khp = g_kh + (size_t)bh * MP * HD;
    const __nv_bfloat16* klp = g_kl + (size_t)bh * MP * HD;
    const __nv_bfloat16* vhp = g_vth + (size_t)bh * HD * MP;
    const __nv_bfloat16* vlp = g_vtl + (size_t)bh * HD * MP;

    #pragma unroll
    for (int j = 0; j < 4; j++) {
        int g = j * 256 + t, row = g >> 3, c16 = g & 7;
        cpa16(su + row * FPITCH + c16 * 16,           qhp + (size_t)row * CC + c16 * 8);
        cpa16(su + Q_BYTES + row * FPITCH + c16 * 16, qlp + (size_t)row * CC + c16 * 8);
    }
    asm volatile("cp.async.commit_group;");

    auto load_chunk = [&](int ci, int buf) {
        uint32_t base = su + CH_OFF + buf * CH_SIZE;
        #pragma unroll
        for (int j = 0; j < 2; j++) {
            int g = j * 256 + t, row = g >> 3, c16 = g & 7;
            cpa16(base +               row * FPITCH + c16 * 16,
                  khp + (size_t)(ci * 64 + row) * HD + c16 * 8);
            cpa16(base + T_BYTES +     row * FPITCH + c16 * 16,
                  klp + (size_t)(ci * 64 + row) * HD + c16 * 8);
            cpa16(base + 2 * T_BYTES + row * FPITCH + c16 * 16,
                  vhp + (size_t)row * MP + ci * 64 + c16 * 8);
            cpa16(base + 3 * T_BYTES + row * FPITCH + c16 * 16,
                  vlp + (size_t)row * MP + ci * 64 + c16 * 8);
        }
        asm volatile("cp.async.commit_group;");
    };
    load_chunk(0, 0);
    load_chunk(1, 1);
    asm volatile("cp.async.wait_group 1;" ::: "memory");
    __syncthreads();

    float l0 = 0.f, l1 = 0.f;
    float oa[8][4] = {};

    const uint32_t q_frag_base = su + (w * 16 + (lane & 15)) * FPITCH + (lane >> 4) * 16;
    const uint32_t kb_row = (lane & 15) * FPITCH + ((lane >> 4) & 1) * 16;

    for (int ci = 0; ci < 10; ci++) {
        const int buf = ci & 1;
        const uint32_t kb = su + CH_OFF + buf * CH_SIZE;

        // ---- S = Qh*Kh + Qh*Kl + Ql*Kh (Q frags reloaded per g; B frags in halves) ----
        float sa[8][4] = {};
        #pragma unroll
        for (int g = 0; g < 4; g++) {
            uint32_t qfh[4], qfl[4];
            ldm4(q_frag_base + g * 32,           qfh[0], qfh[1], qfh[2], qfh[3]);
            ldm4(q_frag_base + g * 32 + Q_BYTES, qfl[0], qfl[1], qfl[2], qfl[3]);
            #pragma unroll
            for (int half = 0; half < 2; half++) {
                uint32_t bkh[4][2], bkl[4][2];
                #pragma unroll
                for (int p = 0; p < 2; p++) {
                    uint32_t addr = kb + (half * 32 + p * 16) * FPITCH + kb_row + g * 32;
                    uint32_t r0, r1, r2, r3;
                    ldm4(addr, r0, r1, r2, r3);
                    bkh[2 * p][0] = r0; bkh[2 * p + 1][0] = r1;
                    bkh[2 * p][1] = r2; bkh[2 * p + 1][1] = r3;
                    ldm4(addr + T_BYTES, r0, r1, r2, r3);
                    bkl[2 * p][0] = r0; bkl[2 * p + 1][0] = r1;
                    bkl[2 * p][1] = r2; bkl[2 * p + 1][1] = r3;
                }
                #pragma unroll
                for (int nb2 = 0; nb2 < 4; nb2++) {
                    int nb = half * 4 + nb2;
                    mma16816(sa[nb], qfh, bkh[nb2]);
                    mma16816(sa[nb], qfh, bkl[nb2]);
                    mma16816(sa[nb], qfl, bkh[nb2]);
                }
            }
        }

        // ---- fixed-shift softmax ----
        float ps0 = 0.f, ps1 = 0.f;
        if (ci == 9) {
            #pragma unroll
            for (int nb = 0; nb < 8; nb++)
                #pragma unroll
                for (int e = 0; e < 4; e++) {
                    int j = 576 + nb * 8 + (lane & 3) * 2 + (e & 1);
                    float ev = (j < MT) ? __expf(sa[nb][e] * ATT_SCALE) : 0.f;
                    sa[nb][e] = ev;
                    if (e < 2) ps0 += ev; else ps1 += ev;
                }
        } else {
            #pragma unroll
            for (int nb = 0; nb < 8; nb++)
                #pragma unroll
                for (int e = 0; e < 4; e++) {
                    float ev = __expf(sa[nb][e] * ATT_SCALE);
                    sa[nb][e] = ev;
                    if (e < 2) ps0 += ev; else ps1 += ev;
                }
        }
        ps0 += __shfl_xor_sync(0xffffffffu, ps0, 1);
        ps0 += __shfl_xor_sync(0xffffffffu, ps0, 2);
        ps1 += __shfl_xor_sync(0xffffffffu, ps1, 1);
        ps1 += __shfl_xor_sync(0xffffffffu, ps1, 2);
        l0 += ps0;
        l1 += ps1;

        // ---- PV: O += Ph*Vh + Ph*Vl + Pl*Vh (B frags in halves) ----
        #pragma unroll
        for (int g = 0; g < 4; g++) {
            uint32_t aph[4], apl[4];
            #pragma unroll
            for (int q = 0; q < 2; q++) {
                int nb = 2 * g + q;
                float p0 = sa[nb][0], p1 = sa[nb][1], p2 = sa[nb][2], p3 = sa[nb][3];
                uint32_t hi01 = pack_bf2(p0, p1);
                uint32_t hi23 = pack_bf2(p2, p3);
                aph[2 * q]     = hi01;
                aph[2 * q + 1] = hi23;
                float r0f = p0 - __bfloat162float(__ushort_as_bfloat16((unsigned short)(hi01 & 0xffff)));
                float r1f = p1 - __bfloat162float(__ushort_as_bfloat16((unsigned short)(hi01 >> 16)));
                float r2f = p2 - __bfloat162float(__ushort_as_bfloat16((unsigned short)(hi23 & 0xffff)));
                float r3f = p3 - __bfloat162float(__ushort_as_bfloat16((unsigned short)(hi23 >> 16)));
                apl[2 * q]     = pack_bf2(r0f, r1f);
                apl[2 * q + 1] = pack_bf2(r2f, r3f);
            }
            #pragma unroll
            for (int half = 0; half < 2; half++) {
                uint32_t bvh[4][2], bvl[4][2];
                #pragma unroll
                for (int p = 0; p < 2; p++) {
                    uint32_t addr = kb + 2 * T_BYTES + (half * 32 + p * 16) * FPITCH
                                  + kb_row + g * 32;
                    uint32_t r0, r1, r2, r3;
                    ldm4(addr, r0, r1, r2, r3);
                    bvh[2 * p][0] = r0; bvh[2 * p + 1][0] = r1;
                    bvh[2 * p][1] = r2; bvh[2 * p + 1][1] = r3;
                    ldm4(addr + T_BYTES, r0, r1, r2, r3);
                    bvl[2 * p][0] = r0; bvl[2 * p + 1][0] = r1;
                    bvl[2 * p][1] = r2; bvl[2 * p + 1][1] = r3;
                }
                #pragma unroll
                for (int nd2 = 0; nd2 < 4; nd2++) {
                    int nd = half * 4 + nd2;
                    mma16816(oa[nd], aph, bvh[nd2]);
                    mma16816(oa[nd], aph, bvl[nd2]);
                    mma16816(oa[nd], apl, bvh[nd2]);
                }
            }
        }

        __syncthreads();
        if (ci + 2 < 10) {
            load_chunk(ci + 2, buf);
            asm volatile("cp.async.wait_group 1;" ::: "memory");
        } else if (ci + 1 < 10) {
            asm volatile("cp.async.wait_group 0;" ::: "memory");
        }
        __syncthreads();
    }

    const float inv0 = 1.f / l0, inv1 = 1.f / l1;
    const int r0 = w * 16 + (lane >> 2);
    const int nq0 = n0 + r0, nq1 = nq0 + 8;
    #pragma unroll
    for (int nd = 0; nd < 8; nd++) {
        int d = h * HD + nd * 8 + (lane & 3) * 2;
        if (nq0 < NT) {
            float2 v = make_float2(oa[nd][0] * inv0, oa[nd][1] * inv0);
            *(float2*)(out + ((size_t)b * NT + nq0) * CC + d) = v;
        }
        if (nq1 < NT) {
            float2 v = make_float2(oa[nd][2] * inv1, oa[nd][3] * inv1);
            *(float2*)(out + ((size_t)b * NT + nq1) * CC + d) = v;
        }
    }
}

// ================= support kernels =================
__global__ __launch_bounds__(256) void k_tsplit(const float* __restrict__ x) {
    __shared__ float tile[32][33];
    const int b = blockIdx.z, n0 = blockIdx.x * 32, c0 = blockIdx.y * 32;
    const int tx = threadIdx.x & 31, ty = threadIdx.x >> 5;
    const float* xp = x + ((size_t)b * CC + c0) * NT + n0;
    #pragma unroll
    for (int i = 0; i < 4; i++)
        tile[ty + 8 * i][tx] = xp[(size_t)(ty + 8 * i) * NT + tx];
    __syncthreads();
    #pragma unroll
    for (int i = 0; i < 4; i++) {
        int r = ty + 8 * i;
        float v = tile[tx][r];
        size_t o = ((size_t)b * NP + n0 + r) * CC + c0 + tx;
        __nv_bfloat16 h = __float2bfloat16(v);
        g_xh[o] = h;
        g_xl[o] = __float2bfloat16(v - __bfloat162float(h));
    }
}

__global__ void k_splitw(const float* __restrict__ Wq, const float* __restrict__ Wkv) {
    int i = blockIdx.x * 256 + threadIdx.x;
    if (i < CC * CC) {
        float v = Wq[i];
        __nv_bfloat16 h = __float2bfloat16(v);
        g_wqh[i] = h; g_wql[i] = __float2bfloat16(v - __bfloat162float(h));
    }
    if (i < 2 * CC * CC) {
        float v = Wkv[i];
        __nv_bfloat16 h = __float2bfloat16(v);
        g_wkh[i] = h; g_wkl[i] = __float2bfloat16(v - __bfloat162float(h));
    }
}

// fused branches 1, 2, 3: one block per (b, c); pooled plane staged in SMEM
__global__ __launch_bounds__(224) void k_branch(const float* __restrict__ x,
        const float* __restrict__ w1a, const float* __restrict__ b1a,
        const float* __restrict__ w1b, const float* __restrict__ b1b,
        const float* __restrict__ w2, const float* __restrict__ b2,
        const float* __restrict__ w3, const float* __restrict__ b3) {
    __shared__ float pool_s[196];
    const int bc = blockIdx.x;
    const int b = bc / CC, c = bc % CC;
    const int t = threadIdx.x;

    if (t < 196) {
        int w4 = t % 14, h4 = t / 14;
        const float* xp = x + (((size_t)bc * HH) + 4 * h4) * WW + 4 * w4;
        float wa[4], wb_[4], wc[16];
        #pragma unroll
        for (int r = 0; r < 4; r++) { wa[r] = w1a[c * 4 + r]; wb_[r] = w1b[c * 4 + r]; }
        #pragma unroll
        for (int r = 0; r < 16; r++) wc[r] = w2[c * 16 + r];
        float ba = b1a[c];
        float l1 = b1b[c], l2 = b2[c], pool = 0.f;
        #pragma unroll
        for (int i = 0; i < 4; i++) {
            float4 xv = *(const float4*)(xp + (size_t)i * WW);
            float tmid = ba + xv.x * wa[0] + xv.y * wa[1] + xv.z * wa[2] + xv.w * wa[3];
            l1 += fmaxf(tmid, 0.f) * wb_[i];
            l2 += xv.x * wc[4 * i] + xv.y * wc[4 * i + 1] + xv.z * wc[4 * i + 2] + xv.w * wc[4 * i + 3];
            pool += xv.x + xv.y + xv.z + xv.w;
        }
        g_lf[((size_t)b * MT + t) * CC + c] = fmaxf(l1, 0.f);
        g_lf[((size_t)b * MT + 196 + t) * CC + c] = fmaxf(l2, 0.f);
        pool_s[t] = pool * (1.f / 16.f);
    }
    __syncthreads();
    if (t < 196) {
        int w4 = t % 14, h4 = t / 14;
        float s = b3[c];
        #pragma unroll
        for (int i = 0; i < 3; i++) {
            int hh = h4 - 1 + i;
            if (hh < 0 || hh >= 14) continue;
            #pragma unroll
            for (int j = 0; j < 3; j++) {
                int ww = w4 - 1 + j;
                if (ww < 0 || ww >= 14) continue;
                s += pool_s[hh * 14 + ww] * w3[c * 9 + i * 3 + j];
            }
        }
        g_lf[((size_t)b * MT + 392 + t) * CC + c] = fmaxf(s, 0.f);
    }
}

__global__ __launch_bounds__(128) void k_ln(const float* __restrict__ gamma,
                                            const float* __restrict__ beta) {
    const int row = blockIdx.x;
    const int b = row / MT, m = row - b * MT;
    const float* p = g_lf + (size_t)row * CC;
    const int t = threadIdx.x;
    float4 v = *(const float4*)(p + t * 4);
    float s = v.x + v.y + v.z + v.w;
    float ss = v.x * v.x + v.y * v.y + v.z * v.z + v.w * v.w;
    #pragma unroll
    for (int o = 16; o >= 1; o >>= 1) {
        s  += __shfl_xor_sync(0xffffffffu, s, o);
        ss += __shfl_xor_sync(0xffffffffu, ss, o);
    }
    __shared__ float sh[8];
    int w = t >> 5;
    if ((t & 31) == 0) { sh[w * 2] = s; sh[w * 2 + 1] = ss; }
    __syncthreads();
    s  = sh[0] + sh[2] + sh[4] + sh[6];
    ss = sh[1] + sh[3] + sh[5] + sh[7];
    float mu = s * (1.f / CC);
    float var = ss * (1.f / CC) - mu * mu;
    float r = rsqrtf(var + 1e-5f);
    float4 g = *(const float4*)(gamma + t * 4);
    float4 be = *(const float4*)(beta + t * 4);
    float o0 = (v.x - mu) * r * g.x + be.x;
    float o1 = (v.y - mu) * r * g.y + be.y;
    float o2 = (v.z - mu) * r * g.z + be.z;
    float o3 = (v.w - mu) * r * g.w + be.w;
    size_t base = ((size_t)b * MP + m) * CC + t * 4;
    __nv_bfloat16 h0 = __float2bfloat16(o0), h1 = __float2bfloat16(o1);
    __nv_bfloat16 h2 = __float2bfloat16(o2), h3 = __float2bfloat16(o3);
    g_lh[base + 0] = h0; g_ll[base + 0] = __float2bfloat16(o0 - __bfloat162float(h0));
    g_lh[base + 1] = h1; g_ll[base + 1] = __float2bfloat16(o1 - __bfloat162float(h1));
    g_lh[base + 2] = h2; g_ll[base + 2] = __float2bfloat16(o2 - __bfloat162float(h2));
    g_lh[base + 3] = h3; g_ll[base + 3] = __float2bfloat16(o3 - __bfloat162float(h3));
}

// ---------------- launch ----------------
extern "C" void kernel_launch(void* const* d_in, const int* in_sizes, int n_in,
                              void* d_out, int out_size) {
    const float* x     = (const float*)d_in[0];
    const float* Wq    = (const float*)d_in[1];
    const float* bq    = (const float*)d_in[2];
    const float* Wkv   = (const float*)d_in[3];
    const float* bkv   = (const float*)d_in[4];
    const float* w1a   = (const float*)d_in[5];
    const float* b1a   = (const float*)d_in[6];
    const float* w1b   = (const float*)d_in[7];
    const float* b1b   = (const float*)d_in[8];
    const float* w2    = (const float*)d_in[9];
    const float* b2    = (const float*)d_in[10];
    const float* w3    = (const float*)d_in[11];
    const float* b3    = (const float*)d_in[12];
    const float* gamma = (const float*)d_in[13];
    const float* beta  = (const float*)d_in[14];
    float* out = (float*)d_out;

    cudaFuncSetAttribute(k_flash,    cudaFuncAttributeMaxDynamicSharedMemorySize, FLASH_SMEM);
    cudaFuncSetAttribute(k_qproj_t,  cudaFuncAttributeMaxDynamicSharedMemorySize, GEMM_SMEM);
    cudaFuncSetAttribute(k_kvproj_t, cudaFuncAttributeMaxDynamicSharedMemorySize, GEMM_SMEM);

    // input prep
    k_tsplit<<<dim3(NT / 32, CC / 32, BB), 256>>>(x);
    k_splitw<<<(2 * CC * CC + 255) / 256, 256>>>(Wq, Wkv);

    // fused branches
    k_branch<<<BB * CC, 224>>>(x, w1a, b1a, w1b, b1b, w2, b2, w3, b3);

    // LN -> split tokens
    k_ln<<<BB * MT, 128>>>(gamma, beta);

    // projections (HMMA)
    k_qproj_t <<<dim3(NP / 128, CC / 64, BB), 256, GEMM_SMEM>>>(bq);
    k_kvproj_t<<<dim3(MP / 128, 2 * CC / 64, BB), 256, GEMM_SMEM>>>(bkv);

    // fused flash attention
    k_flash<<<dim3(NP / 128, BB * NH), 256, FLASH_SMEM>>>(out);
}

// round 10
// speedup vs baseline: 2.7478x; 1.0114x over previous
#include <cuda_runtime.h>
#include <cuda_bf16.h>
#include <cstdint>

// ---------------- problem constants ----------------
constexpr int BB = 8;      // batch
constexpr int CC = 512;    // channels
constexpr int HH = 56, WW = 56;
constexpr int NT = 3136;   // H*W tokens
constexpr int MT = 588;    // 3*196 downsampled tokens
constexpr int NH = 8;      // heads
constexpr int HD = 64;     // head dim
constexpr int NP = 3200;   // NT padded to 128
constexpr int MP = 640;    // MT padded to 128
#define ATT_SCALE 0.125f

// ---------------- scratch (device globals; zero-initialized) ----------------
__device__ float g_lf[BB * MT * CC];

__device__ __nv_bfloat16 g_xh[(size_t)BB * NP * CC], g_xl[(size_t)BB * NP * CC];
__device__ __nv_bfloat16 g_wqh[CC * CC], g_wql[CC * CC];
__device__ __nv_bfloat16 g_wkh[2 * CC * CC], g_wkl[2 * CC * CC];
__device__ __nv_bfloat16 g_lh[(size_t)BB * MP * CC], g_ll[(size_t)BB * MP * CC];
__device__ __nv_bfloat16 g_qh[(size_t)BB * NP * CC], g_ql[(size_t)BB * NP * CC];
__device__ __nv_bfloat16 g_kh[(size_t)BB * NH * MP * HD], g_kl[(size_t)BB * NH * MP * HD];
__device__ __nv_bfloat16 g_vth[(size_t)BB * NH * HD * MP], g_vtl[(size_t)BB * NH * HD * MP];

// ---------------- PTX helpers (base sm_103 feature set only) ----------------
__device__ __forceinline__ uint32_t smem_u32_of(const void* p) {
    uint32_t a;
    asm("{ .reg .u64 t; cvta.to.shared.u64 t, %1; cvt.u32.u64 %0, t; }" : "=r"(a) : "l"(p));
    return a;
}
__device__ __forceinline__ void cpa16(uint32_t dst, const void* src) {
    asm volatile("cp.async.cg.shared.global [%0], [%1], 16;" :: "r"(dst), "l"(src));
}
__device__ __forceinline__ void ldm4(uint32_t addr, uint32_t& r0, uint32_t& r1,
                                     uint32_t& r2, uint32_t& r3) {
    asm volatile("ldmatrix.sync.aligned.m8n8.x4.shared.b16 {%0,%1,%2,%3}, [%4];"
                 : "=r"(r0), "=r"(r1), "=r"(r2), "=r"(r3) : "r"(addr));
}
__device__ __forceinline__ void mma16816(float* d, const uint32_t* a, const uint32_t* b) {
    asm volatile(
        "mma.sync.aligned.m16n8k16.row.col.f32.bf16.bf16.f32 "
        "{%0,%1,%2,%3}, {%4,%5,%6,%7}, {%8,%9}, {%0,%1,%2,%3};"
        : "+f"(d[0]), "+f"(d[1]), "+f"(d[2]), "+f"(d[3])
        : "r"(a[0]), "r"(a[1]), "r"(a[2]), "r"(a[3]), "r"(b[0]), "r"(b[1]));
}
__device__ __forceinline__ uint32_t pack_bf2(float lo, float hi) {
    __nv_bfloat16 a = __float2bfloat16(lo), b = __float2bfloat16(hi);
    return ((uint32_t)__bfloat16_as_ushort(b) << 16) | (uint32_t)__bfloat16_as_ushort(a);
}

// ---------------- HMMA GEMM engine v3: 3-stage ring, 1 barrier/chunk ----------
// Stage: Ah[128][80] @0, Al @10240, Bh[64][80] @20480, Bl @25600.  GSTAGE=30720.
constexpr int GSTAGE = 30720;
constexpr int GEMM_SMEM = 3 * GSTAGE;    // 92160 dynamic

__device__ __forceinline__ void g2_load(const __nv_bfloat16* Ah, const __nv_bfloat16* Al,
                                        const __nv_bfloat16* Bh, const __nv_bfloat16* Bl,
                                        int lda, int ldb, uint32_t base, int koff, int t) {
    #pragma unroll
    for (int j = 0; j < 2; j++) {
        int g = j * 256 + t;
        int row = g >> 2, c16 = g & 3;
        cpa16(base +         row * 80 + c16 * 16, Ah + (size_t)row * lda + koff + c16 * 8);
        cpa16(base + 10240 + row * 80 + c16 * 16, Al + (size_t)row * lda + koff + c16 * 8);
    }
    {
        int row = t >> 2, c16 = t & 3;
        cpa16(base + 20480 + row * 80 + c16 * 16, Bh + (size_t)row * ldb + koff + c16 * 8);
        cpa16(base + 25600 + row * 80 + c16 * 16, Bl + (size_t)row * ldb + koff + c16 * 8);
    }
    asm volatile("cp.async.commit_group;");
}

__device__ __forceinline__ void gemm_main2(const __nv_bfloat16* Ah, const __nv_bfloat16* Al,
                                           const __nv_bfloat16* Bh, const __nv_bfloat16* Bl,
                                           int lda, int ldb, int nchunks,
                                           uint32_t su, float acc[2][4][4]) {
    const int t = threadIdx.x;
    const int lane = t & 31, wid = t >> 5;
    const int wm = wid & 3, wn = wid >> 2;

    g2_load(Ah, Al, Bh, Bl, lda, ldb, su, 0, t);
    if (nchunks > 1) g2_load(Ah, Al, Bh, Bl, lda, ldb, su + GSTAGE, 32, t);
    int rb = 0;                       // ring index of chunk i
    for (int i = 0; i < nchunks; i++) {
        if (i + 1 < nchunks) { asm volatile("cp.async.wait_group 1;" ::: "memory"); }
        else                 { asm volatile("cp.async.wait_group 0;" ::: "memory"); }
        __syncthreads();
        if (i + 2 < nchunks) {
            int wb = rb + 2; if (wb >= 3) wb -= 3;
            g2_load(Ah, Al, Bh, Bl, lda, ldb, su + wb * GSTAGE, (i + 2) * 32, t);
        }
        const uint32_t ab = su + rb * GSTAGE;
        #pragma unroll
        for (int k16 = 0; k16 < 2; k16++) {
            uint32_t afh[2][4], afl[2][4];
            uint32_t a_addr = ab + (wm * 32 + (lane & 15)) * 80 + k16 * 32 + (lane >> 4) * 16;
            ldm4(a_addr,                 afh[0][0], afh[0][1], afh[0][2], afh[0][3]);
            ldm4(a_addr + 16 * 80,       afh[1][0], afh[1][1], afh[1][2], afh[1][3]);
            ldm4(a_addr + 10240,         afl[0][0], afl[0][1], afl[0][2], afl[0][3]);
            ldm4(a_addr + 10240 + 1280,  afl[1][0], afl[1][1], afl[1][2], afl[1][3]);
            uint32_t bfh[4][2], bfl[4][2];
            #pragma unroll
            for (int p = 0; p < 2; p++) {
                uint32_t b_addr = ab + 20480 + (wn * 32 + p * 16 + (lane & 15)) * 80
                                + k16 * 32 + ((lane >> 4) & 1) * 16;
                uint32_t r0, r1, r2, r3;
                ldm4(b_addr, r0, r1, r2, r3);
                bfh[2 * p][0] = r0; bfh[2 * p + 1][0] = r1;
                bfh[2 * p][1] = r2; bfh[2 * p + 1][1] = r3;
                ldm4(b_addr + 5120, r0, r1, r2, r3);
                bfl[2 * p][0] = r0; bfl[2 * p + 1][0] = r1;
                bfl[2 * p][1] = r2; bfl[2 * p + 1][1] = r3;
            }
            #pragma unroll
            for (int mi = 0; mi < 2; mi++)
                #pragma unroll
                for (int ni = 0; ni < 4; ni++) {
                    mma16816(acc[mi][ni], afh[mi], bfh[ni]);
                    mma16816(acc[mi][ni], afh[mi], bfl[ni]);
                    mma16816(acc[mi][ni], afl[mi], bfh[ni]);
                }
        }
        if (++rb == 3) rb = 0;
    }
}

#define EPILOGUE_ITER(body)                                                    \
    {                                                                          \
        const int lane = threadIdx.x & 31, wid = threadIdx.x >> 5;             \
        const int wm = wid & 3, wn = wid >> 2;                                 \
        _Pragma("unroll")                                                      \
        for (int mi = 0; mi < 2; mi++)                                         \
            _Pragma("unroll")                                                  \
            for (int ni = 0; ni < 4; ni++)                                     \
                _Pragma("unroll")                                              \
                for (int e = 0; e < 4; e++) {                                  \
                    int row = wm * 32 + mi * 16 + (lane >> 2) + ((e >> 1) * 8);\
                    int col = wn * 32 + ni * 8 + (lane & 3) * 2 + (e & 1);     \
                    float v = acc[mi][ni][e];                                  \
                    body                                                       \
                }                                                              \
    }

// ================= projection kernels (2 CTA/SM) =================
__global__ __launch_bounds__(256, 2) void k_qproj_t(const float* __restrict__ bq) {
    extern __shared__ __align__(128) uint8_t smem[];
    uint32_t su = smem_u32_of(smem);
    const int b = blockIdx.z, m0 = blockIdx.x * 128, n0 = blockIdx.y * 64;
    float acc[2][4][4] = {};
    gemm_main2(g_xh + ((size_t)b * NP + m0) * CC, g_xl + ((size_t)b * NP + m0) * CC,
               g_wqh + (size_t)n0 * CC, g_wql + (size_t)n0 * CC,
               CC, CC, 16, su, acc);
    EPILOGUE_ITER({
        v += bq[n0 + col];
        __nv_bfloat16 h = __float2bfloat16(v);
        size_t o = ((size_t)b * NP + m0 + row) * CC + n0 + col;
        g_qh[o] = h;
        g_ql[o] = __float2bfloat16(v - __bfloat162float(h));
    })
}

__global__ __launch_bounds__(256, 2) void k_kvproj_t(const float* __restrict__ bkv) {
    extern __shared__ __align__(128) uint8_t smem[];
    uint32_t su = smem_u32_of(smem);
    const int b = blockIdx.z, m0 = blockIdx.x * 128, n0 = blockIdx.y * 64;
    float acc[2][4][4] = {};
    gemm_main2(g_lh + ((size_t)b * MP + m0) * CC, g_ll + ((size_t)b * MP + m0) * CC,
               g_wkh + (size_t)n0 * CC, g_wkl + (size_t)n0 * CC,
               CC, CC, 16, su, acc);
    EPILOGUE_ITER({
        int o = n0 + col;
        int m = m0 + row;
        v += bkv[o];
        __nv_bfloat16 h = __float2bfloat16(v);
        __nv_bfloat16 l = __float2bfloat16(v - __bfloat162float(h));
        if (o < 512) {
            size_t idx = (((size_t)b * NH + (o >> 6)) * MP + m) * HD + (o & 63);
            g_kh[idx] = h; g_kl[idx] = l;
        } else {
            int o2 = o - 512;
            size_t idx = (((size_t)b * NH + (o2 >> 6)) * HD + (o2 & 63)) * MP + m;
            g_vth[idx] = h; g_vtl[idx] = l;
        }
    })
}

// ================= fused flash attention (single-sync pipeline, 2 CTA/SM) =========
constexpr int FPITCH  = 144;
constexpr int Q_BYTES = 128 * FPITCH;          // 18432
constexpr int T_BYTES = 64 * FPITCH;           // 9216
constexpr int CH_OFF  = 2 * Q_BYTES;           // 36864
constexpr int CH_SIZE = 4 * T_BYTES;           // 36864
constexpr int FLASH_SMEM = CH_OFF + 2 * CH_SIZE;   // 110592

__global__ __launch_bounds__(256, 2) void k_flash(float* __restrict__ out) {
    extern __shared__ __align__(128) uint8_t fsm[];
    uint32_t su = smem_u32_of(fsm);
    const int bh = blockIdx.y, b = bh >> 3, h = bh & 7;
    const int n0 = blockIdx.x * 128;
    const int t = threadIdx.x, lane = t & 31, w = t >> 5;

    const __nv_bfloat16* qhp = g_qh + ((size_t)b * NP + n0) * CC + h * HD;
    const __nv_bfloat16* qlp = g_ql + ((size_t)b * NP + n0) * CC + h * HD;
    const __nv_bfloat16* khp = g_kh + (size_t)bh * MP * HD;
    const __nv_bfloat16* klp = g_kl + (size_t)bh * MP * HD;
    const __nv_bfloat16* vhp = g_vth + (size_t)bh * HD * MP;
    const __nv_bfloat16* vlp = g_vtl + (size_t)bh * HD * MP;

    #pragma unroll
    for (int j = 0; j < 4; j++) {
        int g = j * 256 + t, row = g >> 3, c16 = g & 7;
        cpa16(su + row * FPITCH + c16 * 16,           qhp + (size_t)row * CC + c16 * 8);
        cpa16(su + Q_BYTES + row * FPITCH + c16 * 16, qlp + (size_t)row * CC + c16 * 8);
    }
    asm volatile("cp.async.commit_group;");

    auto load_chunk = [&](int ci, int buf) {
        uint32_t base = su + CH_OFF + buf * CH_SIZE;
        #pragma unroll
        for (int j = 0; j < 2; j++) {
            int g = j * 256 + t, row = g >> 3, c16 = g & 7;
            cpa16(base +               row * FPITCH + c16 * 16,
                  khp + (size_t)(ci * 64 + row) * HD + c16 * 8);
            cpa16(base + T_BYTES +     row * FPITCH + c16 * 16,
                  klp + (size_t)(ci * 64 + row) * HD + c16 * 8);
            cpa16(base + 2 * T_BYTES + row * FPITCH + c16 * 16,
                  vhp + (size_t)row * MP + ci * 64 + c16 * 8);
            cpa16(base + 3 * T_BYTES + row * FPITCH + c16 * 16,
                  vlp + (size_t)row * MP + ci * 64 + c16 * 8);
        }
        asm volatile("cp.async.commit_group;");
    };
    load_chunk(0, 0);

    float l0 = 0.f, l1 = 0.f;
    float oa[8][4] = {};

    const uint32_t q_frag_base = su + (w * 16 + (lane & 15)) * FPITCH + (lane >> 4) * 16;
    const uint32_t kb_row = (lane & 15) * FPITCH + ((lane >> 4) & 1) * 16;

    for (int ci = 0; ci < 10; ci++) {
        const int buf = ci & 1;
        const uint32_t kb = su + CH_OFF + buf * CH_SIZE;

        // chunk ci (and Q on ci==0) ready after this wait; publish via barrier
        asm volatile("cp.async.wait_group 0;" ::: "memory");
        __syncthreads();
        if (ci + 1 < 10) load_chunk(ci + 1, buf ^ 1);

        // ---- S = Qh*Kh + Qh*Kl + Ql*Kh ----
        float sa[8][4] = {};
        #pragma unroll
        for (int g = 0; g < 4; g++) {
            uint32_t qfh[4], qfl[4];
            ldm4(q_frag_base + g * 32,           qfh[0], qfh[1], qfh[2], qfh[3]);
            ldm4(q_frag_base + g * 32 + Q_BYTES, qfl[0], qfl[1], qfl[2], qfl[3]);
            #pragma unroll
            for (int half = 0; half < 2; half++) {
                uint32_t bkh[4][2], bkl[4][2];
                #pragma unroll
                for (int p = 0; p < 2; p++) {
                    uint32_t addr = kb + (half * 32 + p * 16) * FPITCH + kb_row + g * 32;
                    uint32_t r0, r1, r2, r3;
                    ldm4(addr, r0, r1, r2, r3);
                    bkh[2 * p][0] = r0; bkh[2 * p + 1][0] = r1;
                    bkh[2 * p][1] = r2; bkh[2 * p + 1][1] = r3;
                    ldm4(addr + T_BYTES, r0, r1, r2, r3);
                    bkl[2 * p][0] = r0; bkl[2 * p + 1][0] = r1;
                    bkl[2 * p][1] = r2; bkl[2 * p + 1][1] = r3;
                }
                #pragma unroll
                for (int nb2 = 0; nb2 < 4; nb2++) {
                    int nb = half * 4 + nb2;
                    mma16816(sa[nb], qfh, bkh[nb2]);
                    mma16816(sa[nb], qfh, bkl[nb2]);
                    mma16816(sa[nb], qfl, bkh[nb2]);
                }
            }
        }

        // ---- fixed-shift softmax ----
        float ps0 = 0.f, ps1 = 0.f;
        if (ci == 9) {
            #pragma unroll
            for (int nb = 0; nb < 8; nb++)
                #pragma unroll
                for (int e = 0; e < 4; e++) {
                    int j = 576 + nb * 8 + (lane & 3) * 2 + (e & 1);
                    float ev = (j < MT) ? __expf(sa[nb][e] * ATT_SCALE) : 0.f;
                    sa[nb][e] = ev;
                    if (e < 2) ps0 += ev; else ps1 += ev;
                }
        } else {
            #pragma unroll
            for (int nb = 0; nb < 8; nb++)
                #pragma unroll
                for (int e = 0; e < 4; e++) {
                    float ev = __expf(sa[nb][e] * ATT_SCALE);
                    sa[nb][e] = ev;
                    if (e < 2) ps0 += ev; else ps1 += ev;
                }
        }
        ps0 += __shfl_xor_sync(0xffffffffu, ps0, 1);
        ps0 += __shfl_xor_sync(0xffffffffu, ps0, 2);
        ps1 += __shfl_xor_sync(0xffffffffu, ps1, 1);
        ps1 += __shfl_xor_sync(0xffffffffu, ps1, 2);
        l0 += ps0;
        l1 += ps1;

        // ---- PV: O += Ph*Vh + Ph*Vl + Pl*Vh ----
        #pragma unroll
        for (int g = 0; g < 4; g++) {
            uint32_t aph[4], apl[4];
            #pragma unroll
            for (int q = 0; q < 2; q++) {
                int nb = 2 * g + q;
                float p0 = sa[nb][0], p1 = sa[nb][1], p2 = sa[nb][2], p3 = sa[nb][3];
                uint32_t hi01 = pack_bf2(p0, p1);
                uint32_t hi23 = pack_bf2(p2, p3);
                aph[2 * q]     = hi01;
                aph[2 * q + 1] = hi23;
                float r0f = p0 - __bfloat162float(__ushort_as_bfloat16((unsigned short)(hi01 & 0xffff)));
                float r1f = p1 - __bfloat162float(__ushort_as_bfloat16((unsigned short)(hi01 >> 16)));
                float r2f = p2 - __bfloat162float(__ushort_as_bfloat16((unsigned short)(hi23 & 0xffff)));
                float r3f = p3 - __bfloat162float(__ushort_as_bfloat16((unsigned short)(hi23 >> 16)));
                apl[2 * q]     = pack_bf2(r0f, r1f);
                apl[2 * q + 1] = pack_bf2(r2f, r3f);
            }
            #pragma unroll
            for (int half = 0; half < 2; half++) {
                uint32_t bvh[4][2], bvl[4][2];
                #pragma unroll
                for (int p = 0; p < 2; p++) {
                    uint32_t addr = kb + 2 * T_BYTES + (half * 32 + p * 16) * FPITCH
                                  + kb_row + g * 32;
                    uint32_t r0, r1, r2, r3;
                    ldm4(addr, r0, r1, r2, r3);
                    bvh[2 * p][0] = r0; bvh[2 * p + 1][0] = r1;
                    bvh[2 * p][1] = r2; bvh[2 * p + 1][1] = r3;
                    ldm4(addr + T_BYTES, r0, r1, r2, r3);
                    bvl[2 * p][0] = r0; bvl[2 * p + 1][0] = r1;
                    bvl[2 * p][1] = r2; bvl[2 * p + 1][1] = r3;
                }
                #pragma unroll
                for (int nd2 = 0; nd2 < 4; nd2++) {
                    int nd = half * 4 + nd2;
                    mma16816(oa[nd], aph, bvh[nd2]);
                    mma16816(oa[nd], aph, bvl[nd2]);
                    mma16816(oa[nd], apl, bvh[nd2]);
                }
            }
        }
    }

    const float inv0 = 1.f / l0, inv1 = 1.f / l1;
    const int r0 = w * 16 + (lane >> 2);
    const int nq0 = n0 + r0, nq1 = nq0 + 8;
    #pragma unroll
    for (int nd = 0; nd < 8; nd++) {
        int d = h * HD + nd * 8 + (lane & 3) * 2;
        if (nq0 < NT) {
            float2 v = make_float2(oa[nd][0] * inv0, oa[nd][1] * inv0);
            *(float2*)(out + ((size_t)b * NT + nq0) * CC + d) = v;
        }
        if (nq1 < NT) {
            float2 v = make_float2(oa[nd][2] * inv1, oa[nd][3] * inv1);
            *(float2*)(out + ((size_t)b * NT + nq1) * CC + d) = v;
        }
    }
}

// ================= support kernels =================
__global__ __launch_bounds__(256) void k_tsplit(const float* __restrict__ x) {
    __shared__ float tile[32][33];
    const int b = blockIdx.z, n0 = blockIdx.x * 32, c0 = blockIdx.y * 32;
    const int tx = threadIdx.x & 31, ty = threadIdx.x >> 5;
    const float* xp = x + ((size_t)b * CC + c0) * NT + n0;
    #pragma unroll
    for (int i = 0; i < 4; i++)
        tile[ty + 8 * i][tx] = xp[(size_t)(ty + 8 * i) * NT + tx];
    __syncthreads();
    #pragma unroll
    for (int i = 0; i < 4; i++) {
        int r = ty + 8 * i;
        float v = tile[tx][r];
        size_t o = ((size_t)b * NP + n0 + r) * CC + c0 + tx;
        __nv_bfloat16 h = __float2bfloat16(v);
        g_xh[o] = h;
        g_xl[o] = __float2bfloat16(v - __bfloat162float(h));
    }
}

__global__ void k_splitw(const float* __restrict__ Wq, const float* __restrict__ Wkv) {
    int i = blockIdx.x * 256 + threadIdx.x;
    if (i < CC * CC) {
        float v = Wq[i];
        __nv_bfloat16 h = __float2bfloat16(v);
        g_wqh[i] = h; g_wql[i] = __float2bfloat16(v - __bfloat162float(h));
    }
    if (i < 2 * CC * CC) {
        float v = Wkv[i];
        __nv_bfloat16 h = __float2bfloat16(v);
        g_wkh[i] = h; g_wkl[i] = __float2bfloat16(v - __bfloat162float(h));
    }
}

// fused branches 1, 2, 3: one block per (b, c); pooled plane staged in SMEM
__global__ __launch_bounds__(224) void k_branch(const float* __restrict__ x,
        const float* __restrict__ w1a, const float* __restrict__ b1a,
        const float* __restrict__ w1b, const float* __restrict__ b1b,
        const float* __restrict__ w2, const float* __restrict__ b2,
        const float* __restrict__ w3, const float* __restrict__ b3) {
    __shared__ float pool_s[196];
    const int bc = blockIdx.x;
    const int b = bc / CC, c = bc % CC;
    const int t = threadIdx.x;

    if (t < 196) {
        int w4 = t % 14, h4 = t / 14;
        const float* xp = x + (((size_t)bc * HH) + 4 * h4) * WW + 4 * w4;
        float wa[4], wb_[4], wc[16];
        #pragma unroll
        for (int r = 0; r < 4; r++) { wa[r] = w1a[c * 4 + r]; wb_[r] = w1b[c * 4 + r]; }
        #pragma unroll
        for (int r = 0; r < 16; r++) wc[r] = w2[c * 16 + r];
        float ba = b1a[c];
        float l1 = b1b[c], l2 = b2[c], pool = 0.f;
        #pragma unroll
        for (int i = 0; i < 4; i++) {
            float4 xv = *(const float4*)(xp + (size_t)i * WW);
            float tmid = ba + xv.x * wa[0] + xv.y * wa[1] + xv.z * wa[2] + xv.w * wa[3];
            l1 += fmaxf(tmid, 0.f) * wb_[i];
            l2 += xv.x * wc[4 * i] + xv.y * wc[4 * i + 1] + xv.z * wc[4 * i + 2] + xv.w * wc[4 * i + 3];
            pool += xv.x + xv.y + xv.z + xv.w;
        }
        g_lf[((size_t)b * MT + t) * CC + c] = fmaxf(l1, 0.f);
        g_lf[((size_t)b * MT + 196 + t) * CC + c] = fmaxf(l2, 0.f);
        pool_s[t] = pool * (1.f / 16.f);
    }
    __syncthreads();
    if (t < 196) {
        int w4 = t % 14, h4 = t / 14;
        float s = b3[c];
        #pragma unroll
        for (int i = 0; i < 3; i++) {
            int hh = h4 - 1 + i;
            if (hh < 0 || hh >= 14) continue;
            #pragma unroll
            for (int j = 0; j < 3; j++) {
                int ww = w4 - 1 + j;
                if (ww < 0 || ww >= 14) continue;
                s += pool_s[hh * 14 + ww] * w3[c * 9 + i * 3 + j];
            }
        }
        g_lf[((size_t)b * MT + 392 + t) * CC + c] = fmaxf(s, 0.f);
    }
}

__global__ __launch_bounds__(128) void k_ln(const float* __restrict__ gamma,
                                            const float* __restrict__ beta) {
    const int row = blockIdx.x;
    const int b = row / MT, m = row - b * MT;
    const float* p = g_lf + (size_t)row * CC;
    const int t = threadIdx.x;
    float4 v = *(const float4*)(p + t * 4);
    float s = v.x + v.y + v.z + v.w;
    float ss = v.x * v.x + v.y * v.y + v.z * v.z + v.w * v.w;
    #pragma unroll
    for (int o = 16; o >= 1; o >>= 1) {
        s  += __shfl_xor_sync(0xffffffffu, s, o);
        ss += __shfl_xor_sync(0xffffffffu, ss, o);
    }
    __shared__ float sh[8];
    int w = t >> 5;
    if ((t & 31) == 0) { sh[w * 2] = s; sh[w * 2 + 1] = ss; }
    __syncthreads();
    s  = sh[0] + sh[2] + sh[4] + sh[6];
    ss = sh[1] + sh[3] + sh[5] + sh[7];
    float mu = s * (1.f / CC);
    float var = ss * (1.f / CC) - mu * mu;
    float r = rsqrtf(var + 1e-5f);
    float4 g = *(const float4*)(gamma + t * 4);
    float4 be = *(const float4*)(beta + t * 4);
    float o0 = (v.x - mu) * r * g.x + be.x;
    float o1 = (v.y - mu) * r * g.y + be.y;
    float o2 = (v.z - mu) * r * g.z + be.z;
    float o3 = (v.w - mu) * r * g.w + be.w;
    size_t base = ((size_t)b * MP + m) * CC + t * 4;
    __nv_bfloat16 h0 = __float2bfloat16(o0), h1 = __float2bfloat16(o1);
    __nv_bfloat16 h2 = __float2bfloat16(o2), h3 = __float2bfloat16(o3);
    g_lh[base + 0] = h0; g_ll[base + 0] = __float2bfloat16(o0 - __bfloat162float(h0));
    g_lh[base + 1] = h1; g_ll[base + 1] = __float2bfloat16(o1 - __bfloat162float(h1));
    g_lh[base + 2] = h2; g_ll[base + 2] = __float2bfloat16(o2 - __bfloat162float(h2));
    g_lh[base + 3] = h3; g_ll[base + 3] = __float2bfloat16(o3 - __bfloat162float(h3));
}

// ---------------- launch ----------------
extern "C" void kernel_launch(void* const* d_in, const int* in_sizes, int n_in,
                              void* d_out, int out_size) {
    const float* x     = (const float*)d_in[0];
    const float* Wq    = (const float*)d_in[1];
    const float* bq    = (const float*)d_in[2];
    const float* Wkv   = (const float*)d_in[3];
    const float* bkv   = (const float*)d_in[4];
    const float* w1a   = (const float*)d_in[5];
    const float* b1a   = (const float*)d_in[6];
    const float* w1b   = (const float*)d_in[7];
    const float* b1b   = (const float*)d_in[8];
    const float* w2    = (const float*)d_in[9];
    const float* b2    = (const float*)d_in[10];
    const float* w3    = (const float*)d_in[11];
    const float* b3    = (const float*)d_in[12];
    const float* gamma = (const float*)d_in[13];
    const float* beta  = (const float*)d_in[14];
    float* out = (float*)d_out;

    cudaFuncSetAttribute(k_flash,    cudaFuncAttributeMaxDynamicSharedMemorySize, FLASH_SMEM);
    cudaFuncSetAttribute(k_qproj_t,  cudaFuncAttributeMaxDynamicSharedMemorySize, GEMM_SMEM);
    cudaFuncSetAttribute(k_kvproj_t, cudaFuncAttributeMaxDynamicSharedMemorySize, GEMM_SMEM);

    // input prep
    k_tsplit<<<dim3(NT / 32, CC / 32, BB), 256>>>(x);
    k_splitw<<<(2 * CC * CC + 255) / 256, 256>>>(Wq, Wkv);

    // fused branches
    k_branch<<<BB * CC, 224>>>(x, w1a, b1a, w1b, b1b, w2, b2, w3, b3);

    // LN -> split tokens
    k_ln<<<BB * MT, 128>>>(gamma, beta);

    // projections (HMMA)
    k_qproj_t <<<dim3(NP / 128, CC / 64, BB), 256, GEMM_SMEM>>>(bq);
    k_kvproj_t<<<dim3(MP / 128, 2 * CC / 64, BB), 256, GEMM_SMEM>>>(bkv);

    // fused flash attention
    k_flash<<<dim3(NP / 128, BB * NH), 256, FLASH_SMEM>>>(out);
}

// round 11
// speedup vs baseline: 2.8680x; 1.0437x over previous
#include <cuda_runtime.h>
#include <cuda_bf16.h>
#include <cstdint>

// ---------------- problem constants ----------------
constexpr int BB = 8;      // batch
constexpr int CC = 512;    // channels
constexpr int HH = 56, WW = 56;
constexpr int NT = 3136;   // H*W tokens
constexpr int MT = 588;    // 3*196 downsampled tokens
constexpr int NH = 8;      // heads
constexpr int HD = 64;     // head dim
constexpr int NP = 3200;   // NT padded to 128
constexpr int MP = 640;    // MT padded to 128
#define ATT_SCALE 0.125f

// ---------------- scratch (device globals; zero-initialized) ----------------
__device__ float g_lf[BB * MT * CC];

__device__ __nv_bfloat16 g_xh[(size_t)BB * NP * CC], g_xl[(size_t)BB * NP * CC];
__device__ __nv_bfloat16 g_wqh[CC * CC], g_wql[CC * CC];
__device__ __nv_bfloat16 g_wkh[2 * CC * CC], g_wkl[2 * CC * CC];
__device__ __nv_bfloat16 g_lh[(size_t)BB * MP * CC], g_ll[(size_t)BB * MP * CC];
__device__ __nv_bfloat16 g_qh[(size_t)BB * NP * CC], g_ql[(size_t)BB * NP * CC];
__device__ __nv_bfloat16 g_kh[(size_t)BB * NH * MP * HD], g_kl[(size_t)BB * NH * MP * HD];
__device__ __nv_bfloat16 g_vth[(size_t)BB * NH * HD * MP], g_vtl[(size_t)BB * NH * HD * MP];

// ---------------- PTX helpers (base sm_103 feature set only) ----------------
__device__ __forceinline__ uint32_t smem_u32_of(const void* p) {
    uint32_t a;
    asm("{ .reg .u64 t; cvta.to.shared.u64 t, %1; cvt.u32.u64 %0, t; }" : "=r"(a) : "l"(p));
    return a;
}
__device__ __forceinline__ void cpa16(uint32_t dst, const void* src) {
    asm volatile("cp.async.cg.shared.global [%0], [%1], 16;" :: "r"(dst), "l"(src));
}
__device__ __forceinline__ void ldm4(uint32_t addr, uint32_t& r0, uint32_t& r1,
                                     uint32_t& r2, uint32_t& r3) {
    asm volatile("ldmatrix.sync.aligned.m8n8.x4.shared.b16 {%0,%1,%2,%3}, [%4];"
                 : "=r"(r0), "=r"(r1), "=r"(r2), "=r"(r3) : "r"(addr));
}
__device__ __forceinline__ void mma16816(float* d, const uint32_t* a, const uint32_t* b) {
    asm volatile(
        "mma.sync.aligned.m16n8k16.row.col.f32.bf16.bf16.f32 "
        "{%0,%1,%2,%3}, {%4,%5,%6,%7}, {%8,%9}, {%0,%1,%2,%3};"
        : "+f"(d[0]), "+f"(d[1]), "+f"(d[2]), "+f"(d[3])
        : "r"(a[0]), "r"(a[1]), "r"(a[2]), "r"(a[3]), "r"(b[0]), "r"(b[1]));
}
__device__ __forceinline__ uint32_t pack_bf2(float lo, float hi) {
    __nv_bfloat16 a = __float2bfloat16(lo), b = __float2bfloat16(hi);
    return ((uint32_t)__bfloat16_as_ushort(b) << 16) | (uint32_t)__bfloat16_as_ushort(a);
}

// ---------------- HMMA GEMM engine v3: 3-stage ring, 1 barrier/chunk ----------
constexpr int GSTAGE = 30720;
constexpr int GEMM_SMEM = 3 * GSTAGE;    // 92160 dynamic

__device__ __forceinline__ void g2_load(const __nv_bfloat16* Ah, const __nv_bfloat16* Al,
                                        const __nv_bfloat16* Bh, const __nv_bfloat16* Bl,
                                        int lda, int ldb, uint32_t base, int koff, int t) {
    #pragma unroll
    for (int j = 0; j < 2; j++) {
        int g = j * 256 + t;
        int row = g >> 2, c16 = g & 3;
        cpa16(base +         row * 80 + c16 * 16, Ah + (size_t)row * lda + koff + c16 * 8);
        cpa16(base + 10240 + row * 80 + c16 * 16, Al + (size_t)row * lda + koff + c16 * 8);
    }
    {
        int row = t >> 2, c16 = t & 3;
        cpa16(base + 20480 + row * 80 + c16 * 16, Bh + (size_t)row * ldb + koff + c16 * 8);
        cpa16(base + 25600 + row * 80 + c16 * 16, Bl + (size_t)row * ldb + koff + c16 * 8);
    }
    asm volatile("cp.async.commit_group;");
}

__device__ __forceinline__ void gemm_main2(const __nv_bfloat16* Ah, const __nv_bfloat16* Al,
                                           const __nv_bfloat16* Bh, const __nv_bfloat16* Bl,
                                           int lda, int ldb, int nchunks,
                                           uint32_t su, float acc[2][4][4]) {
    const int t = threadIdx.x;
    const int lane = t & 31, wid = t >> 5;
    const int wm = wid & 3, wn = wid >> 2;

    g2_load(Ah, Al, Bh, Bl, lda, ldb, su, 0, t);
    if (nchunks > 1) g2_load(Ah, Al, Bh, Bl, lda, ldb, su + GSTAGE, 32, t);
    int rb = 0;                       // ring index of chunk i
    for (int i = 0; i < nchunks; i++) {
        if (i + 1 < nchunks) { asm volatile("cp.async.wait_group 1;" ::: "memory"); }
        else                 { asm volatile("cp.async.wait_group 0;" ::: "memory"); }
        __syncthreads();
        if (i + 2 < nchunks) {
            int wb = rb + 2; if (wb >= 3) wb -= 3;
            g2_load(Ah, Al, Bh, Bl, lda, ldb, su + wb * GSTAGE, (i + 2) * 32, t);
        }
        const uint32_t ab = su + rb * GSTAGE;
        #pragma unroll
        for (int k16 = 0; k16 < 2; k16++) {
            uint32_t afh[2][4], afl[2][4];
            uint32_t a_addr = ab + (wm * 32 + (lane & 15)) * 80 + k16 * 32 + (lane >> 4) * 16;
            ldm4(a_addr,                 afh[0][0], afh[0][1], afh[0][2], afh[0][3]);
            ldm4(a_addr + 16 * 80,       afh[1][0], afh[1][1], afh[1][2], afh[1][3]);
            ldm4(a_addr + 10240,         afl[0][0], afl[0][1], afl[0][2], afl[0][3]);
            ldm4(a_addr + 10240 + 1280,  afl[1][0], afl[1][1], afl[1][2], afl[1][3]);
            uint32_t bfh[4][2], bfl[4][2];
            #pragma unroll
            for (int p = 0; p < 2; p++) {
                uint32_t b_addr = ab + 20480 + (wn * 32 + p * 16 + (lane & 15)) * 80
                                + k16 * 32 + ((lane >> 4) & 1) * 16;
                uint32_t r0, r1, r2, r3;
                ldm4(b_addr, r0, r1, r2, r3);
                bfh[2 * p][0] = r0; bfh[2 * p + 1][0] = r1;
                bfh[2 * p][1] = r2; bfh[2 * p + 1][1] = r3;
                ldm4(b_addr + 5120, r0, r1, r2, r3);
                bfl[2 * p][0] = r0; bfl[2 * p + 1][0] = r1;
                bfl[2 * p][1] = r2; bfl[2 * p + 1][1] = r3;
            }
            #pragma unroll
            for (int mi = 0; mi < 2; mi++)
                #pragma unroll
                for (int ni = 0; ni < 4; ni++) {
                    mma16816(acc[mi][ni], afh[mi], bfh[ni]);
                    mma16816(acc[mi][ni], afh[mi], bfl[ni]);
                    mma16816(acc[mi][ni], afl[mi], bfh[ni]);
                }
        }
        if (++rb == 3) rb = 0;
    }
}

#define EPILOGUE_ITER(body)                                                    \
    {                                                                          \
        const int lane = threadIdx.x & 31, wid = threadIdx.x >> 5;             \
        const int wm = wid & 3, wn = wid >> 2;                                 \
        _Pragma("unroll")                                                      \
        for (int mi = 0; mi < 2; mi++)                                         \
            _Pragma("unroll")                                                  \
            for (int ni = 0; ni < 4; ni++)                                     \
                _Pragma("unroll")                                              \
                for (int e = 0; e < 4; e++) {                                  \
                    int row = wm * 32 + mi * 16 + (lane >> 2) + ((e >> 1) * 8);\
                    int col = wn * 32 + ni * 8 + (lane & 3) * 2 + (e & 1);     \
                    float v = acc[mi][ni][e];                                  \
                    body                                                       \
                }                                                              \
    }

// ================= projection kernels (2 CTA/SM) =================
__global__ __launch_bounds__(256, 2) void k_qproj_t(const float* __restrict__ bq) {
    extern __shared__ __align__(128) uint8_t smem[];
    uint32_t su = smem_u32_of(smem);
    const int b = blockIdx.z, m0 = blockIdx.x * 128, n0 = blockIdx.y * 64;
    float acc[2][4][4] = {};
    gemm_main2(g_xh + ((size_t)b * NP + m0) * CC, g_xl + ((size_t)b * NP + m0) * CC,
               g_wqh + (size_t)n0 * CC, g_wql + (size_t)n0 * CC,
               CC, CC, 16, su, acc);
    EPILOGUE_ITER({
        v += bq[n0 + col];
        __nv_bfloat16 h = __float2bfloat16(v);
        size_t o = ((size_t)b * NP + m0 + row) * CC + n0 + col;
        g_qh[o] = h;
        g_ql[o] = __float2bfloat16(v - __bfloat162float(h));
    })
}

__global__ __launch_bounds__(256, 2) void k_kvproj_t(const float* __restrict__ bkv) {
    extern __shared__ __align__(128) uint8_t smem[];
    uint32_t su = smem_u32_of(smem);
    const int b = blockIdx.z, m0 = blockIdx.x * 128, n0 = blockIdx.y * 64;
    float acc[2][4][4] = {};
    gemm_main2(g_lh + ((size_t)b * MP + m0) * CC, g_ll + ((size_t)b * MP + m0) * CC,
               g_wkh + (size_t)n0 * CC, g_wkl + (size_t)n0 * CC,
               CC, CC, 16, su, acc);
    EPILOGUE_ITER({
        int o = n0 + col;
        int m = m0 + row;
        v += bkv[o];
        __nv_bfloat16 h = __float2bfloat16(v);
        __nv_bfloat16 l = __float2bfloat16(v - __bfloat162float(h));
        if (o < 512) {
            size_t idx = (((size_t)b * NH + (o >> 6)) * MP + m) * HD + (o & 63);
            g_kh[idx] = h; g_kl[idx] = l;
        } else {
            int o2 = o - 512;
            size_t idx = (((size_t)b * NH + (o2 >> 6)) * HD + (o2 & 63)) * MP + m;
            g_vth[idx] = h; g_vtl[idx] = l;
        }
    })
}

// ================= fused flash attention (single-sync pipeline, 2 CTA/SM) =========
constexpr int FPITCH  = 144;
constexpr int Q_BYTES = 128 * FPITCH;          // 18432
constexpr int T_BYTES = 64 * FPITCH;           // 9216
constexpr int CH_OFF  = 2 * Q_BYTES;           // 36864
constexpr int CH_SIZE = 4 * T_BYTES;           // 36864
constexpr int FLASH_SMEM = CH_OFF + 2 * CH_SIZE;   // 110592

__global__ __launch_bounds__(256, 2) void k_flash(float* __restrict__ out) {
    extern __shared__ __align__(128) uint8_t fsm[];
    uint32_t su = smem_u32_of(fsm);
    const int bh = blockIdx.y, b = bh >> 3, h = bh & 7;
    const int n0 = blockIdx.x * 128;
    const int t = threadIdx.x, lane = t & 31, w = t >> 5;

    const __nv_bfloat16* qhp = g_qh + ((size_t)b * NP + n0) * CC + h * HD;
    const __nv_bfloat16* qlp = g_ql + ((size_t)b * NP + n0) * CC + h * HD;
    const __nv_bfloat16* khp = g_kh + (size_t)bh * MP * HD;
    const __nv_bfloat16* klp = g_kl + (size_t)bh * MP * HD;
    const __nv_bfloat16* vhp = g_vth + (size_t)bh * HD * MP;
    const __nv_bfloat16* vlp = g_vtl + (size_t)bh * HD * MP;

    #pragma unroll
    for (int j = 0; j < 4; j++) {
        int g = j * 256 + t, row = g >> 3, c16 = g & 7;
        cpa16(su + row * FPITCH + c16 * 16,           qhp + (size_t)row * CC + c16 * 8);
        cpa16(su + Q_BYTES + row * FPITCH + c16 * 16, qlp + (size_t)row * CC + c16 * 8);
    }
    asm volatile("cp.async.commit_group;");

    auto load_chunk = [&](int ci, int buf) {
        uint32_t base = su + CH_OFF + buf * CH_SIZE;
        #pragma unroll
        for (int j = 0; j < 2; j++) {
            int g = j * 256 + t, row = g >> 3, c16 = g & 7;
            cpa16(base +               row * FPITCH + c16 * 16,
                  khp + (size_t)(ci * 64 + row) * HD + c16 * 8);
            cpa16(base + T_BYTES +     row * FPITCH + c16 * 16,
                  klp + (size_t)(ci * 64 + row) * HD + c16 * 8);
            cpa16(base + 2 * T_BYTES + row * FPITCH + c16 * 16,
                  vhp + (size_t)row * MP + ci * 64 + c16 * 8);
            cpa16(base + 3 * T_BYTES + row * FPITCH + c16 * 16,
                  vlp + (size_t)row * MP + ci * 64 + c16 * 8);
        }
        asm volatile("cp.async.commit_group;");
    };
    load_chunk(0, 0);

    float l0 = 0.f, l1 = 0.f;
    float oa[8][4] = {};

    const uint32_t q_frag_base = su + (w * 16 + (lane & 15)) * FPITCH + (lane >> 4) * 16;
    const uint32_t kb_row = (lane & 15) * FPITCH + ((lane >> 4) & 1) * 16;

    for (int ci = 0; ci < 10; ci++) {
        const int buf = ci & 1;
        const uint32_t kb = su + CH_OFF + buf * CH_SIZE;

        asm volatile("cp.async.wait_group 0;" ::: "memory");
        __syncthreads();
        if (ci + 1 < 10) load_chunk(ci + 1, buf ^ 1);

        // ---- S = Qh*Kh + Qh*Kl + Ql*Kh ----
        float sa[8][4] = {};
        #pragma unroll
        for (int g = 0; g < 4; g++) {
            uint32_t qfh[4], qfl[4];
            ldm4(q_frag_base + g * 32,           qfh[0], qfh[1], qfh[2], qfh[3]);
            ldm4(q_frag_base + g * 32 + Q_BYTES, qfl[0], qfl[1], qfl[2], qfl[3]);
            #pragma unroll
            for (int half = 0; half < 2; half++) {
                uint32_t bkh[4][2], bkl[4][2];
                #pragma unroll
                for (int p = 0; p < 2; p++) {
                    uint32_t addr = kb + (half * 32 + p * 16) * FPITCH + kb_row + g * 32;
                    uint32_t r0, r1, r2, r3;
                    ldm4(addr, r0, r1, r2, r3);
                    bkh[2 * p][0] = r0; bkh[2 * p + 1][0] = r1;
                    bkh[2 * p][1] = r2; bkh[2 * p + 1][1] = r3;
                    ldm4(addr + T_BYTES, r0, r1, r2, r3);
                    bkl[2 * p][0] = r0; bkl[2 * p + 1][0] = r1;
                    bkl[2 * p][1] = r2; bkl[2 * p + 1][1] = r3;
                }
                #pragma unroll
                for (int nb2 = 0; nb2 < 4; nb2++) {
                    int nb = half * 4 + nb2;
                    mma16816(sa[nb], qfh, bkh[nb2]);
                    mma16816(sa[nb], qfh, bkl[nb2]);
                    mma16816(sa[nb], qfl, bkh[nb2]);
                }
            }
        }

        // ---- fixed-shift softmax ----
        float ps0 = 0.f, ps1 = 0.f;
        if (ci == 9) {
            #pragma unroll
            for (int nb = 0; nb < 8; nb++)
                #pragma unroll
                for (int e = 0; e < 4; e++) {
                    int j = 576 + nb * 8 + (lane & 3) * 2 + (e & 1);
                    float ev = (j < MT) ? __expf(sa[nb][e] * ATT_SCALE) : 0.f;
                    sa[nb][e] = ev;
                    if (e < 2) ps0 += ev; else ps1 += ev;
                }
        } else {
            #pragma unroll
            for (int nb = 0; nb < 8; nb++)
                #pragma unroll
                for (int e = 0; e < 4; e++) {
                    float ev = __expf(sa[nb][e] * ATT_SCALE);
                    sa[nb][e] = ev;
                    if (e < 2) ps0 += ev; else ps1 += ev;
                }
        }
        ps0 += __shfl_xor_sync(0xffffffffu, ps0, 1);
        ps0 += __shfl_xor_sync(0xffffffffu, ps0, 2);
        ps1 += __shfl_xor_sync(0xffffffffu, ps1, 1);
        ps1 += __shfl_xor_sync(0xffffffffu, ps1, 2);
        l0 += ps0;
        l1 += ps1;

        // ---- PV: O += Ph*Vh + Ph*Vl + Pl*Vh ----
        #pragma unroll
        for (int g = 0; g < 4; g++) {
            uint32_t aph[4], apl[4];
            #pragma unroll
            for (int q = 0; q < 2; q++) {
                int nb = 2 * g + q;
                float p0 = sa[nb][0], p1 = sa[nb][1], p2 = sa[nb][2], p3 = sa[nb][3];
                uint32_t hi01 = pack_bf2(p0, p1);
                uint32_t hi23 = pack_bf2(p2, p3);
                aph[2 * q]     = hi01;
                aph[2 * q + 1] = hi23;
                float r0f = p0 - __bfloat162float(__ushort_as_bfloat16((unsigned short)(hi01 & 0xffff)));
                float r1f = p1 - __bfloat162float(__ushort_as_bfloat16((unsigned short)(hi01 >> 16)));
                float r2f = p2 - __bfloat162float(__ushort_as_bfloat16((unsigned short)(hi23 & 0xffff)));
                float r3f = p3 - __bfloat162float(__ushort_as_bfloat16((unsigned short)(hi23 >> 16)));
                apl[2 * q]     = pack_bf2(r0f, r1f);
                apl[2 * q + 1] = pack_bf2(r2f, r3f);
            }
            #pragma unroll
            for (int half = 0; half < 2; half++) {
                uint32_t bvh[4][2], bvl[4][2];
                #pragma unroll
                for (int p = 0; p < 2; p++) {
                    uint32_t addr = kb + 2 * T_BYTES + (half * 32 + p * 16) * FPITCH
                                  + kb_row + g * 32;
                    uint32_t r0, r1, r2, r3;
                    ldm4(addr, r0, r1, r2, r3);
                    bvh[2 * p][0] = r0; bvh[2 * p + 1][0] = r1;
                    bvh[2 * p][1] = r2; bvh[2 * p + 1][1] = r3;
                    ldm4(addr + T_BYTES, r0, r1, r2, r3);
                    bvl[2 * p][0] = r0; bvl[2 * p + 1][0] = r1;
                    bvl[2 * p][1] = r2; bvl[2 * p + 1][1] = r3;
                }
                #pragma unroll
                for (int nd2 = 0; nd2 < 4; nd2++) {
                    int nd = half * 4 + nd2;
                    mma16816(oa[nd], aph, bvh[nd2]);
                    mma16816(oa[nd], aph, bvl[nd2]);
                    mma16816(oa[nd], apl, bvh[nd2]);
                }
            }
        }
    }

    const float inv0 = 1.f / l0, inv1 = 1.f / l1;
    const int r0 = w * 16 + (lane >> 2);
    const int nq0 = n0 + r0, nq1 = nq0 + 8;
    #pragma unroll
    for (int nd = 0; nd < 8; nd++) {
        int d = h * HD + nd * 8 + (lane & 3) * 2;
        if (nq0 < NT) {
            float2 v = make_float2(oa[nd][0] * inv0, oa[nd][1] * inv0);
            *(float2*)(out + ((size_t)b * NT + nq0) * CC + d) = v;
        }
        if (nq1 < NT) {
            float2 v = make_float2(oa[nd][2] * inv1, oa[nd][3] * inv1);
            *(float2*)(out + ((size_t)b * NT + nq1) * CC + d) = v;
        }
    }
}

// ================= support kernels =================
__global__ __launch_bounds__(256) void k_tsplit(const float* __restrict__ x) {
    __shared__ float tile[32][33];
    const int b = blockIdx.z, n0 = blockIdx.x * 32, c0 = blockIdx.y * 32;
    const int tx = threadIdx.x & 31, ty = threadIdx.x >> 5;
    const float* xp = x + ((size_t)b * CC + c0) * NT + n0;
    #pragma unroll
    for (int i = 0; i < 4; i++)
        tile[ty + 8 * i][tx] = xp[(size_t)(ty + 8 * i) * NT + tx];
    __syncthreads();
    #pragma unroll
    for (int i = 0; i < 4; i++) {
        int r = ty + 8 * i;
        float v = tile[tx][r];
        size_t o = ((size_t)b * NP + n0 + r) * CC + c0 + tx;
        __nv_bfloat16 h = __float2bfloat16(v);
        g_xh[o] = h;
        g_xl[o] = __float2bfloat16(v - __bfloat162float(h));
    }
}

__global__ void k_splitw(const float* __restrict__ Wq, const float* __restrict__ Wkv) {
    int i = blockIdx.x * 256 + threadIdx.x;
    if (i < CC * CC) {
        float v = Wq[i];
        __nv_bfloat16 h = __float2bfloat16(v);
        g_wqh[i] = h; g_wql[i] = __float2bfloat16(v - __bfloat162float(h));
    }
    if (i < 2 * CC * CC) {
        float v = Wkv[i];
        __nv_bfloat16 h = __float2bfloat16(v);
        g_wkh[i] = h; g_wkl[i] = __float2bfloat16(v - __bfloat162float(h));
    }
}

// fused branches 1, 2, 3: one block per (b, c); pooled plane staged in SMEM
__global__ __launch_bounds__(224) void k_branch(const float* __restrict__ x,
        const float* __restrict__ w1a, const float* __restrict__ b1a,
        const float* __restrict__ w1b, const float* __restrict__ b1b,
        const float* __restrict__ w2, const float* __restrict__ b2,
        const float* __restrict__ w3, const float* __restrict__ b3) {
    __shared__ float pool_s[196];
    const int bc = blockIdx.x;
    const int b = bc / CC, c = bc % CC;
    const int t = threadIdx.x;

    if (t < 196) {
        int w4 = t % 14, h4 = t / 14;
        const float* xp = x + (((size_t)bc * HH) + 4 * h4) * WW + 4 * w4;
        float wa[4], wb_[4], wc[16];
        #pragma unroll
        for (int r = 0; r < 4; r++) { wa[r] = w1a[c * 4 + r]; wb_[r] = w1b[c * 4 + r]; }
        #pragma unroll
        for (int r = 0; r < 16; r++) wc[r] = w2[c * 16 + r];
        float ba = b1a[c];
        float l1 = b1b[c], l2 = b2[c], pool = 0.f;
        #pragma unroll
        for (int i = 0; i < 4; i++) {
            float4 xv = *(const float4*)(xp + (size_t)i * WW);
            float tmid = ba + xv.x * wa[0] + xv.y * wa[1] + xv.z * wa[2] + xv.w * wa[3];
            l1 += fmaxf(tmid, 0.f) * wb_[i];
            l2 += xv.x * wc[4 * i] + xv.y * wc[4 * i + 1] + xv.z * wc[4 * i + 2] + xv.w * wc[4 * i + 3];
            pool += xv.x + xv.y + xv.z + xv.w;
        }
        g_lf[((size_t)b * MT + t) * CC + c] = fmaxf(l1, 0.f);
        g_lf[((size_t)b * MT + 196 + t) * CC + c] = fmaxf(l2, 0.f);
        pool_s[t] = pool * (1.f / 16.f);
    }
    __syncthreads();
    if (t < 196) {
        int w4 = t % 14, h4 = t / 14;
        float s = b3[c];
        #pragma unroll
        for (int i = 0; i < 3; i++) {
            int hh = h4 - 1 + i;
            if (hh < 0 || hh >= 14) continue;
            #pragma unroll
            for (int j = 0; j < 3; j++) {
                int ww = w4 - 1 + j;
                if (ww < 0 || ww >= 14) continue;
                s += pool_s[hh * 14 + ww] * w3[c * 9 + i * 3 + j];
            }
        }
        g_lf[((size_t)b * MT + 392 + t) * CC + c] = fmaxf(s, 0.f);
    }
}

__global__ __launch_bounds__(128) void k_ln(const float* __restrict__ gamma,
                                            const float* __restrict__ beta) {
    const int row = blockIdx.x;
    const int b = row / MT, m = row - b * MT;
    const float* p = g_lf + (size_t)row * CC;
    const int t = threadIdx.x;
    float4 v = *(const float4*)(p + t * 4);
    float s = v.x + v.y + v.z + v.w;
    float ss = v.x * v.x + v.y * v.y + v.z * v.z + v.w * v.w;
    #pragma unroll
    for (int o = 16; o >= 1; o >>= 1) {
        s  += __shfl_xor_sync(0xffffffffu, s, o);
        ss += __shfl_xor_sync(0xffffffffu, ss, o);
    }
    __shared__ float sh[8];
    int w = t >> 5;
    if ((t & 31) == 0) { sh[w * 2] = s; sh[w * 2 + 1] = ss; }
    __syncthreads();
    s  = sh[0] + sh[2] + sh[4] + sh[6];
    ss = sh[1] + sh[3] + sh[5] + sh[7];
    float mu = s * (1.f / CC);
    float var = ss * (1.f / CC) - mu * mu;
    float r = rsqrtf(var + 1e-5f);
    float4 g = *(const float4*)(gamma + t * 4);
    float4 be = *(const float4*)(beta + t * 4);
    float o0 = (v.x - mu) * r * g.x + be.x;
    float o1 = (v.y - mu) * r * g.y + be.y;
    float o2 = (v.z - mu) * r * g.z + be.z;
    float o3 = (v.w - mu) * r * g.w + be.w;
    size_t base = ((size_t)b * MP + m) * CC + t * 4;
    __nv_bfloat16 h0 = __float2bfloat16(o0), h1 = __float2bfloat16(o1);
    __nv_bfloat16 h2 = __float2bfloat16(o2), h3 = __float2bfloat16(o3);
    g_lh[base + 0] = h0; g_ll[base + 0] = __float2bfloat16(o0 - __bfloat162float(h0));
    g_lh[base + 1] = h1; g_ll[base + 1] = __float2bfloat16(o1 - __bfloat162float(h1));
    g_lh[base + 2] = h2; g_ll[base + 2] = __float2bfloat16(o2 - __bfloat162float(h2));
    g_lh[base + 3] = h3; g_ll[base + 3] = __float2bfloat16(o3 - __bfloat162float(h3));
}

// ---------------- launch (fork/join streams for independent chains) ----------------
extern "C" void kernel_launch(void* const* d_in, const int* in_sizes, int n_in,
                              void* d_out, int out_size) {
    const float* x     = (const float*)d_in[0];
    const float* Wq    = (const float*)d_in[1];
    const float* bq    = (const float*)d_in[2];
    const float* Wkv   = (const float*)d_in[3];
    const float* bkv   = (const float*)d_in[4];
    const float* w1a   = (const float*)d_in[5];
    const float* b1a   = (const float*)d_in[6];
    const float* w1b   = (const float*)d_in[7];
    const float* b1b   = (const float*)d_in[8];
    const float* w2    = (const float*)d_in[9];
    const float* b2    = (const float*)d_in[10];
    const float* w3    = (const float*)d_in[11];
    const float* b3    = (const float*)d_in[12];
    const float* gamma = (const float*)d_in[13];
    const float* beta  = (const float*)d_in[14];
    float* out = (float*)d_out;

    // one-time resource init (same captured work every call)
    static cudaStream_t s2 = nullptr;
    static cudaEvent_t e_fork = nullptr, e_join = nullptr;
    if (s2 == nullptr) {
        cudaStreamCreateWithFlags(&s2, cudaStreamNonBlocking);
        cudaEventCreateWithFlags(&e_fork, cudaEventDisableTiming);
        cudaEventCreateWithFlags(&e_join, cudaEventDisableTiming);
        cudaFuncSetAttribute(k_flash,    cudaFuncAttributeMaxDynamicSharedMemorySize, FLASH_SMEM);
        cudaFuncSetAttribute(k_qproj_t,  cudaFuncAttributeMaxDynamicSharedMemorySize, GEMM_SMEM);
        cudaFuncSetAttribute(k_kvproj_t, cudaFuncAttributeMaxDynamicSharedMemorySize, GEMM_SMEM);
    }

    // main stream: weight split first (needed by both chains), then fork
    k_splitw<<<(2 * CC * CC + 255) / 256, 256>>>(Wq, Wkv);
    cudaEventRecord(e_fork, 0);
    cudaStreamWaitEvent(s2, e_fork, 0);

    // side chain (stream s2): branches -> LN -> KV projection
    k_branch<<<BB * CC, 224, 0, s2>>>(x, w1a, b1a, w1b, b1b, w2, b2, w3, b3);
    k_ln<<<BB * MT, 128, 0, s2>>>(gamma, beta);
    k_kvproj_t<<<dim3(MP / 128, 2 * CC / 64, BB), 256, GEMM_SMEM, s2>>>(bkv);
    cudaEventRecord(e_join, s2);

    // main chain: x transpose/split -> Q projection
    k_tsplit<<<dim3(NT / 32, CC / 32, BB), 256>>>(x);
    k_qproj_t<<<dim3(NP / 128, CC / 64, BB), 256, GEMM_SMEM>>>(bq);

    // join, then fused flash attention
    cudaStreamWaitEvent(0, e_join, 0);
    k_flash<<<dim3(NP / 128, BB * NH), 256, FLASH_SMEM>>>(out);
}

// round 12
// speedup vs baseline: 2.8748x; 1.0024x over previous
#include <cuda_runtime.h>
#include <cuda_bf16.h>
#include <cstdint>

// ---------------- problem constants ----------------
constexpr int BB = 8;      // batch
constexpr int CC = 512;    // channels
constexpr int HH = 56, WW = 56;
constexpr int NT = 3136;   // H*W tokens
constexpr int MT = 588;    // 3*196 downsampled tokens
constexpr int NH = 8;      // heads
constexpr int HD = 64;     // head dim
constexpr int NP = 3200;   // NT padded to 128
constexpr int MP = 640;    // MT padded to 128
#define ATT_SCALE 0.125f

// ---------------- scratch (device globals; zero-initialized) ----------------
__device__ float g_lf[BB * MT * CC];

__device__ __nv_bfloat16 g_xh[(size_t)BB * NP * CC], g_xl[(size_t)BB * NP * CC];
__device__ __nv_bfloat16 g_wqh[CC * CC], g_wql[CC * CC];
__device__ __nv_bfloat16 g_wkh[2 * CC * CC], g_wkl[2 * CC * CC];
__device__ __nv_bfloat16 g_lh[(size_t)BB * MP * CC], g_ll[(size_t)BB * MP * CC];
__device__ __nv_bfloat16 g_qh[(size_t)BB * NP * CC], g_ql[(size_t)BB * NP * CC];
__device__ __nv_bfloat16 g_kh[(size_t)BB * NH * MP * HD], g_kl[(size_t)BB * NH * MP * HD];
__device__ __nv_bfloat16 g_vth[(size_t)BB * NH * HD * MP], g_vtl[(size_t)BB * NH * HD * MP];

// ---------------- PTX helpers (base sm_103 feature set only) ----------------
__device__ __forceinline__ uint32_t smem_u32_of(const void* p) {
    uint32_t a;
    asm("{ .reg .u64 t; cvta.to.shared.u64 t, %1; cvt.u32.u64 %0, t; }" : "=r"(a) : "l"(p));
    return a;
}
__device__ __forceinline__ void cpa16(uint32_t dst, const void* src) {
    asm volatile("cp.async.cg.shared.global [%0], [%1], 16;" :: "r"(dst), "l"(src));
}
__device__ __forceinline__ void ldm4(uint32_t addr, uint32_t& r0, uint32_t& r1,
                                     uint32_t& r2, uint32_t& r3) {
    asm volatile("ldmatrix.sync.aligned.m8n8.x4.shared.b16 {%0,%1,%2,%3}, [%4];"
                 : "=r"(r0), "=r"(r1), "=r"(r2), "=r"(r3) : "r"(addr));
}
__device__ __forceinline__ void mma16816(float* d, const uint32_t* a, const uint32_t* b) {
    asm volatile(
        "mma.sync.aligned.m16n8k16.row.col.f32.bf16.bf16.f32 "
        "{%0,%1,%2,%3}, {%4,%5,%6,%7}, {%8,%9}, {%0,%1,%2,%3};"
        : "+f"(d[0]), "+f"(d[1]), "+f"(d[2]), "+f"(d[3])
        : "r"(a[0]), "r"(a[1]), "r"(a[2]), "r"(a[3]), "r"(b[0]), "r"(b[1]));
}
__device__ __forceinline__ uint32_t pack_bf2(float lo, float hi) {
    __nv_bfloat16 a = __float2bfloat16(lo), b = __float2bfloat16(hi);
    return ((uint32_t)__bfloat16_as_ushort(b) << 16) | (uint32_t)__bfloat16_as_ushort(a);
}

// ---------------- HMMA GEMM engine v3: 3-stage ring, 1 barrier/chunk ----------
constexpr int GSTAGE = 30720;
constexpr int GEMM_SMEM = 3 * GSTAGE;    // 92160 dynamic

__device__ __forceinline__ void g2_load(const __nv_bfloat16* Ah, const __nv_bfloat16* Al,
                                        const __nv_bfloat16* Bh, const __nv_bfloat16* Bl,
                                        int lda, int ldb, uint32_t base, int koff, int t) {
    #pragma unroll
    for (int j = 0; j < 2; j++) {
        int g = j * 256 + t;
        int row = g >> 2, c16 = g & 3;
        cpa16(base +         row * 80 + c16 * 16, Ah + (size_t)row * lda + koff + c16 * 8);
        cpa16(base + 10240 + row * 80 + c16 * 16, Al + (size_t)row * lda + koff + c16 * 8);
    }
    {
        int row = t >> 2, c16 = t & 3;
        cpa16(base + 20480 + row * 80 + c16 * 16, Bh + (size_t)row * ldb + koff + c16 * 8);
        cpa16(base + 25600 + row * 80 + c16 * 16, Bl + (size_t)row * ldb + koff + c16 * 8);
    }
    asm volatile("cp.async.commit_group;");
}

__device__ __forceinline__ void gemm_main2(const __nv_bfloat16* Ah, const __nv_bfloat16* Al,
                                           const __nv_bfloat16* Bh, const __nv_bfloat16* Bl,
                                           int lda, int ldb, int nchunks,
                                           uint32_t su, float acc[2][4][4]) {
    const int t = threadIdx.x;
    const int lane = t & 31, wid = t >> 5;
    const int wm = wid & 3, wn = wid >> 2;

    g2_load(Ah, Al, Bh, Bl, lda, ldb, su, 0, t);
    if (nchunks > 1) g2_load(Ah, Al, Bh, Bl, lda, ldb, su + GSTAGE, 32, t);
    int rb = 0;                       // ring index of chunk i
    for (int i = 0; i < nchunks; i++) {
        if (i + 1 < nchunks) { asm volatile("cp.async.wait_group 1;" ::: "memory"); }
        else                 { asm volatile("cp.async.wait_group 0;" ::: "memory"); }
        __syncthreads();
        if (i + 2 < nchunks) {
            int wb = rb + 2; if (wb >= 3) wb -= 3;
            g2_load(Ah, Al, Bh, Bl, lda, ldb, su + wb * GSTAGE, (i + 2) * 32, t);
        }
        const uint32_t ab = su + rb * GSTAGE;
        #pragma unroll
        for (int k16 = 0; k16 < 2; k16++) {
            uint32_t afh[2][4], afl[2][4];
            uint32_t a_addr = ab + (wm * 32 + (lane & 15)) * 80 + k16 * 32 + (lane >> 4) * 16;
            ldm4(a_addr,                 afh[0][0], afh[0][1], afh[0][2], afh[0][3]);
            ldm4(a_addr + 16 * 80,       afh[1][0], afh[1][1], afh[1][2], afh[1][3]);
            ldm4(a_addr + 10240,         afl[0][0], afl[0][1], afl[0][2], afl[0][3]);
            ldm4(a_addr + 10240 + 1280,  afl[1][0], afl[1][1], afl[1][2], afl[1][3]);
            uint32_t bfh[4][2], bfl[4][2];
            #pragma unroll
            for (int p = 0; p < 2; p++) {
                uint32_t b_addr = ab + 20480 + (wn * 32 + p * 16 + (lane & 15)) * 80
                                + k16 * 32 + ((lane >> 4) & 1) * 16;
                uint32_t r0, r1, r2, r3;
                ldm4(b_addr, r0, r1, r2, r3);
                bfh[2 * p][0] = r0; bfh[2 * p + 1][0] = r1;
                bfh[2 * p][1] = r2; bfh[2 * p + 1][1] = r3;
                ldm4(b_addr + 5120, r0, r1, r2, r3);
                bfl[2 * p][0] = r0; bfl[2 * p + 1][0] = r1;
                bfl[2 * p][1] = r2; bfl[2 * p + 1][1] = r3;
            }
            #pragma unroll
            for (int mi = 0; mi < 2; mi++)
                #pragma unroll
                for (int ni = 0; ni < 4; ni++) {
                    mma16816(acc[mi][ni], afh[mi], bfh[ni]);
                    mma16816(acc[mi][ni], afh[mi], bfl[ni]);
                    mma16816(acc[mi][ni], afl[mi], bfh[ni]);
                }
        }
        if (++rb == 3) rb = 0;
    }
}

#define EPILOGUE_ITER(body)                                                    \
    {                                                                          \
        const int lane = threadIdx.x & 31, wid = threadIdx.x >> 5;             \
        const int wm = wid & 3, wn = wid >> 2;                                 \
        _Pragma("unroll")                                                      \
        for (int mi = 0; mi < 2; mi++)                                         \
            _Pragma("unroll")                                                  \
            for (int ni = 0; ni < 4; ni++)                                     \
                _Pragma("unroll")                                              \
                for (int e = 0; e < 4; e++) {                                  \
                    int row = wm * 32 + mi * 16 + (lane >> 2) + ((e >> 1) * 8);\
                    int col = wn * 32 + ni * 8 + (lane & 3) * 2 + (e & 1);     \
                    float v = acc[mi][ni][e];                                  \
                    body                                                       \
                }                                                              \
    }

// ================= projection kernels (2 CTA/SM, batch-offset sliced) =================
__global__ __launch_bounds__(256, 2) void k_qproj_t(const float* __restrict__ bq, int b0) {
    extern __shared__ __align__(128) uint8_t smem[];
    uint32_t su = smem_u32_of(smem);
    const int b = b0 + blockIdx.z, m0 = blockIdx.x * 128, n0 = blockIdx.y * 64;
    float acc[2][4][4] = {};
    gemm_main2(g_xh + ((size_t)b * NP + m0) * CC, g_xl + ((size_t)b * NP + m0) * CC,
               g_wqh + (size_t)n0 * CC, g_wql + (size_t)n0 * CC,
               CC, CC, 16, su, acc);
    EPILOGUE_ITER({
        v += bq[n0 + col];
        __nv_bfloat16 h = __float2bfloat16(v);
        size_t o = ((size_t)b * NP + m0 + row) * CC + n0 + col;
        g_qh[o] = h;
        g_ql[o] = __float2bfloat16(v - __bfloat162float(h));
    })
}

__global__ __launch_bounds__(256, 2) void k_kvproj_t(const float* __restrict__ bkv) {
    extern __shared__ __align__(128) uint8_t smem[];
    uint32_t su = smem_u32_of(smem);
    const int b = blockIdx.z, m0 = blockIdx.x * 128, n0 = blockIdx.y * 64;
    float acc[2][4][4] = {};
    gemm_main2(g_lh + ((size_t)b * MP + m0) * CC, g_ll + ((size_t)b * MP + m0) * CC,
               g_wkh + (size_t)n0 * CC, g_wkl + (size_t)n0 * CC,
               CC, CC, 16, su, acc);
    EPILOGUE_ITER({
        int o = n0 + col;
        int m = m0 + row;
        v += bkv[o];
        __nv_bfloat16 h = __float2bfloat16(v);
        __nv_bfloat16 l = __float2bfloat16(v - __bfloat162float(h));
        if (o < 512) {
            size_t idx = (((size_t)b * NH + (o >> 6)) * MP + m) * HD + (o & 63);
            g_kh[idx] = h; g_kl[idx] = l;
        } else {
            int o2 = o - 512;
            size_t idx = (((size_t)b * NH + (o2 >> 6)) * HD + (o2 & 63)) * MP + m;
            g_vth[idx] = h; g_vtl[idx] = l;
        }
    })
}

// ================= fused flash attention (single-sync pipeline, 2 CTA/SM) =========
constexpr int FPITCH  = 144;
constexpr int Q_BYTES = 128 * FPITCH;          // 18432
constexpr int T_BYTES = 64 * FPITCH;           // 9216
constexpr int CH_OFF  = 2 * Q_BYTES;           // 36864
constexpr int CH_SIZE = 4 * T_BYTES;           // 36864
constexpr int FLASH_SMEM = CH_OFF + 2 * CH_SIZE;   // 110592

__global__ __launch_bounds__(256, 2) void k_flash(float* __restrict__ out, int bh0) {
    extern __shared__ __align__(128) uint8_t fsm[];
    uint32_t su = smem_u32_of(fsm);
    const int bh = bh0 + blockIdx.y, b = bh >> 3, h = bh & 7;
    const int n0 = blockIdx.x * 128;
    const int t = threadIdx.x, lane = t & 31, w = t >> 5;

    const __nv_bfloat16* qhp = g_qh + ((size_t)b * NP + n0) * CC + h * HD;
    const __nv_bfloat16* qlp = g_ql + ((size_t)b * NP + n0) * CC + h * HD;
    const __nv_bfloat16* khp = g_kh + (size_t)bh * MP * HD;
    const __nv_bfloat16* klp = g_kl + (size_t)bh * MP * HD;
    const __nv_bfloat16* vhp = g_vth + (size_t)bh * HD * MP;
    const __nv_bfloat16* vlp = g_vtl + (size_t)bh * HD * MP;

    #pragma unroll
    for (int j = 0; j < 4; j++) {
        int g = j * 256 + t, row = g >> 3, c16 = g & 7;
        cpa16(su + row * FPITCH + c16 * 16,           qhp + (size_t)row * CC + c16 * 8);
        cpa16(su + Q_BYTES + row * FPITCH + c16 * 16, qlp + (size_t)row * CC + c16 * 8);
    }
    asm volatile("cp.async.commit_group;");

    auto load_chunk = [&](int ci, int buf) {
        uint32_t base = su + CH_OFF + buf * CH_SIZE;
        #pragma unroll
        for (int j = 0; j < 2; j++) {
            int g = j * 256 + t, row = g >> 3, c16 = g & 7;
            cpa16(base +               row * FPITCH + c16 * 16,
                  khp + (size_t)(ci * 64 + row) * HD + c16 * 8);
            cpa16(base + T_BYTES +     row * FPITCH + c16 * 16,
                  klp + (size_t)(ci * 64 + row) * HD + c16 * 8);
            cpa16(base + 2 * T_BYTES + row * FPITCH + c16 * 16,
                  vhp + (size_t)row * MP + ci * 64 + c16 * 8);
            cpa16(base + 3 * T_BYTES + row * FPITCH + c16 * 16,
                  vlp + (size_t)row * MP + ci * 64 + c16 * 8);
        }
        asm volatile("cp.async.commit_group;");
    };
    load_chunk(0, 0);

    float l0 = 0.f, l1 = 0.f;
    float oa[8][4] = {};

    const uint32_t q_frag_base = su + (w * 16 + (lane & 15)) * FPITCH + (lane >> 4) * 16;
    const uint32_t kb_row = (lane & 15) * FPITCH + ((lane >> 4) & 1) * 16;

    for (int ci = 0; ci < 10; ci++) {
        const int buf = ci & 1;
        const uint32_t kb = su + CH_OFF + buf * CH_SIZE;

        asm volatile("cp.async.wait_group 0;" ::: "memory");
        __syncthreads();
        if (ci + 1 < 10) load_chunk(ci + 1, buf ^ 1);

        // ---- S = Qh*Kh + Qh*Kl + Ql*Kh ----
        float sa[8][4] = {};
        #pragma unroll
        for (int g = 0; g < 4; g++) {
            uint32_t qfh[4], qfl[4];
            ldm4(q_frag_base + g * 32,           qfh[0], qfh[1], qfh[2], qfh[3]);
            ldm4(q_frag_base + g * 32 + Q_BYTES, qfl[0], qfl[1], qfl[2], qfl[3]);
            #pragma unroll
            for (int half = 0; half < 2; half++) {
                uint32_t bkh[4][2], bkl[4][2];
                #pragma unroll
                for (int p = 0; p < 2; p++) {
                    uint32_t addr = kb + (half * 32 + p * 16) * FPITCH + kb_row + g * 32;
                    uint32_t r0, r1, r2, r3;
                    ldm4(addr, r0, r1, r2, r3);
                    bkh[2 * p][0] = r0; bkh[2 * p + 1][0] = r1;
                    bkh[2 * p][1] = r2; bkh[2 * p + 1][1] = r3;
                    ldm4(addr + T_BYTES, r0, r1, r2, r3);
                    bkl[2 * p][0] = r0; bkl[2 * p + 1][0] = r1;
                    bkl[2 * p][1] = r2; bkl[2 * p + 1][1] = r3;
                }
                #pragma unroll
                for (int nb2 = 0; nb2 < 4; nb2++) {
                    int nb = half * 4 + nb2;
                    mma16816(sa[nb], qfh, bkh[nb2]);
                    mma16816(sa[nb], qfh, bkl[nb2]);
                    mma16816(sa[nb], qfl, bkh[nb2]);
                }
            }
        }

        // ---- fixed-shift softmax ----
        float ps0 = 0.f, ps1 = 0.f;
        if (ci == 9) {
            #pragma unroll
            for (int nb = 0; nb < 8; nb++)
                #pragma unroll
                for (int e = 0; e < 4; e++) {
                    int j = 576 + nb * 8 + (lane & 3) * 2 + (e & 1);
                    float ev = (j < MT) ? __expf(sa[nb][e] * ATT_SCALE) : 0.f;
                    sa[nb][e] = ev;
                    if (e < 2) ps0 += ev; else ps1 += ev;
                }
        } else {
            #pragma unroll
            for (int nb = 0; nb < 8; nb++)
                #pragma unroll
                for (int e = 0; e < 4; e++) {
                    float ev = __expf(sa[nb][e] * ATT_SCALE);
                    sa[nb][e] = ev;
                    if (e < 2) ps0 += ev; else ps1 += ev;
                }
        }
        ps0 += __shfl_xor_sync(0xffffffffu, ps0, 1);
        ps0 += __shfl_xor_sync(0xffffffffu, ps0, 2);
        ps1 += __shfl_xor_sync(0xffffffffu, ps1, 1);
        ps1 += __shfl_xor_sync(0xffffffffu, ps1, 2);
        l0 += ps0;
        l1 += ps1;

        // ---- PV: O += Ph*Vh + Ph*Vl + Pl*Vh ----
        #pragma unroll
        for (int g = 0; g < 4; g++) {
            uint32_t aph[4], apl[4];
            #pragma unroll
            for (int q = 0; q < 2; q++) {
                int nb = 2 * g + q;
                float p0 = sa[nb][0], p1 = sa[nb][1], p2 = sa[nb][2], p3 = sa[nb][3];
                uint32_t hi01 = pack_bf2(p0, p1);
                uint32_t hi23 = pack_bf2(p2, p3);
                aph[2 * q]     = hi01;
                aph[2 * q + 1] = hi23;
                float r0f = p0 - __bfloat162float(__ushort_as_bfloat16((unsigned short)(hi01 & 0xffff)));
                float r1f = p1 - __bfloat162float(__ushort_as_bfloat16((unsigned short)(hi01 >> 16)));
                float r2f = p2 - __bfloat162float(__ushort_as_bfloat16((unsigned short)(hi23 & 0xffff)));
                float r3f = p3 - __bfloat162float(__ushort_as_bfloat16((unsigned short)(hi23 >> 16)));
                apl[2 * q]     = pack_bf2(r0f, r1f);
                apl[2 * q + 1] = pack_bf2(r2f, r3f);
            }
            #pragma unroll
            for (int half = 0; half < 2; half++) {
                uint32_t bvh[4][2], bvl[4][2];
                #pragma unroll
                for (int p = 0; p < 2; p++) {
                    uint32_t addr = kb + 2 * T_BYTES + (half * 32 + p * 16) * FPITCH
                                  + kb_row + g * 32;
                    uint32_t r0, r1, r2, r3;
                    ldm4(addr, r0, r1, r2, r3);
                    bvh[2 * p][0] = r0; bvh[2 * p + 1][0] = r1;
                    bvh[2 * p][1] = r2; bvh[2 * p + 1][1] = r3;
                    ldm4(addr + T_BYTES, r0, r1, r2, r3);
                    bvl[2 * p][0] = r0; bvl[2 * p + 1][0] = r1;
                    bvl[2 * p][1] = r2; bvl[2 * p + 1][1] = r3;
                }
                #pragma unroll
                for (int nd2 = 0; nd2 < 4; nd2++) {
                    int nd = half * 4 + nd2;
                    mma16816(oa[nd], aph, bvh[nd2]);
                    mma16816(oa[nd], aph, bvl[nd2]);
                    mma16816(oa[nd], apl, bvh[nd2]);
                }
            }
        }
    }

    const float inv0 = 1.f / l0, inv1 = 1.f / l1;
    const int r0 = w * 16 + (lane >> 2);
    const int nq0 = n0 + r0, nq1 = nq0 + 8;
    #pragma unroll
    for (int nd = 0; nd < 8; nd++) {
        int d = h * HD + nd * 8 + (lane & 3) * 2;
        if (nq0 < NT) {
            float2 v = make_float2(oa[nd][0] * inv0, oa[nd][1] * inv0);
            *(float2*)(out + ((size_t)b * NT + nq0) * CC + d) = v;
        }
        if (nq1 < NT) {
            float2 v = make_float2(oa[nd][2] * inv1, oa[nd][3] * inv1);
            *(float2*)(out + ((size_t)b * NT + nq1) * CC + d) = v;
        }
    }
}

// ================= support kernels =================
__global__ __launch_bounds__(256) void k_tsplit(const float* __restrict__ x) {
    __shared__ float tile[32][33];
    const int b = blockIdx.z, n0 = blockIdx.x * 32, c0 = blockIdx.y * 32;
    const int tx = threadIdx.x & 31, ty = threadIdx.x >> 5;
    const float* xp = x + ((size_t)b * CC + c0) * NT + n0;
    #pragma unroll
    for (int i = 0; i < 4; i++)
        tile[ty + 8 * i][tx] = xp[(size_t)(ty + 8 * i) * NT + tx];
    __syncthreads();
    #pragma unroll
    for (int i = 0; i < 4; i++) {
        int r = ty + 8 * i;
        float v = tile[tx][r];
        size_t o = ((size_t)b * NP + n0 + r) * CC + c0 + tx;
        __nv_bfloat16 h = __float2bfloat16(v);
        g_xh[o] = h;
        g_xl[o] = __float2bfloat16(v - __bfloat162float(h));
    }
}

__global__ void k_splitw(const float* __restrict__ Wq, const float* __restrict__ Wkv) {
    int i = blockIdx.x * 256 + threadIdx.x;
    if (i < CC * CC) {
        float v = Wq[i];
        __nv_bfloat16 h = __float2bfloat16(v);
        g_wqh[i] = h; g_wql[i] = __float2bfloat16(v - __bfloat162float(h));
    }
    if (i < 2 * CC * CC) {
        float v = Wkv[i];
        __nv_bfloat16 h = __float2bfloat16(v);
        g_wkh[i] = h; g_wkl[i] = __float2bfloat16(v - __bfloat162float(h));
    }
}

// fused branches 1, 2, 3: one block per (b, c); pooled plane staged in SMEM
__global__ __launch_bounds__(224) void k_branch(const float* __restrict__ x,
        const float* __restrict__ w1a, const float* __restrict__ b1a,
        const float* __restrict__ w1b, const float* __restrict__ b1b,
        const float* __restrict__ w2, const float* __restrict__ b2,
        const float* __restrict__ w3, const float* __restrict__ b3) {
    __shared__ float pool_s[196];
    const int bc = blockIdx.x;
    const int b = bc / CC, c = bc % CC;
    const int t = threadIdx.x;

    if (t < 196) {
        int w4 = t % 14, h4 = t / 14;
        const float* xp = x + (((size_t)bc * HH) + 4 * h4) * WW + 4 * w4;
        float wa[4], wb_[4], wc[16];
        #pragma unroll
        for (int r = 0; r < 4; r++) { wa[r] = w1a[c * 4 + r]; wb_[r] = w1b[c * 4 + r]; }
        #pragma unroll
        for (int r = 0; r < 16; r++) wc[r] = w2[c * 16 + r];
        float ba = b1a[c];
        float l1 = b1b[c], l2 = b2[c], pool = 0.f;
        #pragma unroll
        for (int i = 0; i < 4; i++) {
            float4 xv = *(const float4*)(xp + (size_t)i * WW);
            float tmid = ba + xv.x * wa[0] + xv.y * wa[1] + xv.z * wa[2] + xv.w * wa[3];
            l1 += fmaxf(tmid, 0.f) * wb_[i];
            l2 += xv.x * wc[4 * i] + xv.y * wc[4 * i + 1] + xv.z * wc[4 * i + 2] + xv.w * wc[4 * i + 3];
            pool += xv.x + xv.y + xv.z + xv.w;
        }
        g_lf[((size_t)b * MT + t) * CC + c] = fmaxf(l1, 0.f);
        g_lf[((size_t)b * MT + 196 + t) * CC + c] = fmaxf(l2, 0.f);
        pool_s[t] = pool * (1.f / 16.f);
    }
    __syncthreads();
    if (t < 196) {
        int w4 = t % 14, h4 = t / 14;
        float s = b3[c];
        #pragma unroll
        for (int i = 0; i < 3; i++) {
            int hh = h4 - 1 + i;
            if (hh < 0 || hh >= 14) continue;
            #pragma unroll
            for (int j = 0; j < 3; j++) {
                int ww = w4 - 1 + j;
                if (ww < 0 || ww >= 14) continue;
                s += pool_s[hh * 14 + ww] * w3[c * 9 + i * 3 + j];
            }
        }
        g_lf[((size_t)b * MT + 392 + t) * CC + c] = fmaxf(s, 0.f);
    }
}

__global__ __launch_bounds__(128) void k_ln(const float* __restrict__ gamma,
                                            const float* __restrict__ beta) {
    const int row = blockIdx.x;
    const int b = row / MT, m = row - b * MT;
    const float* p = g_lf + (size_t)row * CC;
    const int t = threadIdx.x;
    float4 v = *(const float4*)(p + t * 4);
    float s = v.x + v.y + v.z + v.w;
    float ss = v.x * v.x + v.y * v.y + v.z * v.z + v.w * v.w;
    #pragma unroll
    for (int o = 16; o >= 1; o >>= 1) {
        s  += __shfl_xor_sync(0xffffffffu, s, o);
        ss += __shfl_xor_sync(0xffffffffu, ss, o);
    }
    __shared__ float sh[8];
    int w = t >> 5;
    if ((t & 31) == 0) { sh[w * 2] = s; sh[w * 2 + 1] = ss; }
    __syncthreads();
    s  = sh[0] + sh[2] + sh[4] + sh[6];
    ss = sh[1] + sh[3] + sh[5] + sh[7];
    float mu = s * (1.f / CC);
    float var = ss * (1.f / CC) - mu * mu;
    float r = rsqrtf(var + 1e-5f);
    float4 g = *(const float4*)(gamma + t * 4);
    float4 be = *(const float4*)(beta + t * 4);
    float o0 = (v.x - mu) * r * g.x + be.x;
    float o1 = (v.y - mu) * r * g.y + be.y;
    float o2 = (v.z - mu) * r * g.z + be.z;
    float o3 = (v.w - mu) * r * g.w + be.w;
    size_t base = ((size_t)b * MP + m) * CC + t * 4;
    __nv_bfloat16 h0 = __float2bfloat16(o0), h1 = __float2bfloat16(o1);
    __nv_bfloat16 h2 = __float2bfloat16(o2), h3 = __float2bfloat16(o3);
    g_lh[base + 0] = h0; g_ll[base + 0] = __float2bfloat16(o0 - __bfloat162float(h0));
    g_lh[base + 1] = h1; g_ll[base + 1] = __float2bfloat16(o1 - __bfloat162float(h1));
    g_lh[base + 2] = h2; g_ll[base + 2] = __float2bfloat16(o2 - __bfloat162float(h2));
    g_lh[base + 3] = h3; g_ll[base + 3] = __float2bfloat16(o3 - __bfloat162float(h3));
}

// ---------------- launch: batch-sliced qproj -> flash pipeline ----------------
extern "C" void kernel_launch(void* const* d_in, const int* in_sizes, int n_in,
                              void* d_out, int out_size) {
    const float* x     = (const float*)d_in[0];
    const float* Wq    = (const float*)d_in[1];
    const float* bq    = (const float*)d_in[2];
    const float* Wkv   = (const float*)d_in[3];
    const float* bkv   = (const float*)d_in[4];
    const float* w1a   = (const float*)d_in[5];
    const float* b1a   = (const float*)d_in[6];
    const float* w1b   = (const float*)d_in[7];
    const float* b1b   = (const float*)d_in[8];
    const float* w2    = (const float*)d_in[9];
    const float* b2    = (const float*)d_in[10];
    const float* w3    = (const float*)d_in[11];
    const float* b3    = (const float*)d_in[12];
    const float* gamma = (const float*)d_in[13];
    const float* beta  = (const float*)d_in[14];
    float* out = (float*)d_out;

    // one-time resource init (identical captured graph every call)
    static cudaStream_t s2 = nullptr, s3 = nullptr;
    static cudaEvent_t e_fork = nullptr, e_kv = nullptr, e_done = nullptr;
    static cudaEvent_t e_q[4] = {nullptr, nullptr, nullptr, nullptr};
    if (s2 == nullptr) {
        cudaStreamCreateWithFlags(&s2, cudaStreamNonBlocking);
        cudaStreamCreateWithFlags(&s3, cudaStreamNonBlocking);
        cudaEventCreateWithFlags(&e_fork, cudaEventDisableTiming);
        cudaEventCreateWithFlags(&e_kv,   cudaEventDisableTiming);
        cudaEventCreateWithFlags(&e_done, cudaEventDisableTiming);
        for (int i = 0; i < 4; i++) cudaEventCreateWithFlags(&e_q[i], cudaEventDisableTiming);
        cudaFuncSetAttribute(k_flash,    cudaFuncAttributeMaxDynamicSharedMemorySize, FLASH_SMEM);
        cudaFuncSetAttribute(k_qproj_t,  cudaFuncAttributeMaxDynamicSharedMemorySize, GEMM_SMEM);
        cudaFuncSetAttribute(k_kvproj_t, cudaFuncAttributeMaxDynamicSharedMemorySize, GEMM_SMEM);
    }

    // main stream: weight split (needed by both chains), then fork
    k_splitw<<<(2 * CC * CC + 255) / 256, 256>>>(Wq, Wkv);
    cudaEventRecord(e_fork, 0);
    cudaStreamWaitEvent(s2, e_fork, 0);

    // side chain (s2): branches -> LN -> KV projection -> e_kv
    k_branch<<<BB * CC, 224, 0, s2>>>(x, w1a, b1a, w1b, b1b, w2, b2, w3, b3);
    k_ln<<<BB * MT, 128, 0, s2>>>(gamma, beta);
    k_kvproj_t<<<dim3(MP / 128, 2 * CC / 64, BB), 256, GEMM_SMEM, s2>>>(bkv);
    cudaEventRecord(e_kv, s2);

    // main chain: x transpose/split, then 4 qproj slices (2 batches each)
    k_tsplit<<<dim3(NT / 32, CC / 32, BB), 256>>>(x);
    for (int sIdx = 0; sIdx < 4; sIdx++) {
        k_qproj_t<<<dim3(NP / 128, CC / 64, 2), 256, GEMM_SMEM>>>(bq, 2 * sIdx);
        cudaEventRecord(e_q[sIdx], 0);
    }

    // flash slices on s3: each waits its q slice; kv gate once
    cudaStreamWaitEvent(s3, e_kv, 0);
    for (int sIdx = 0; sIdx < 4; sIdx++) {
        cudaStreamWaitEvent(s3, e_q[sIdx], 0);
        k_flash<<<dim3(NP / 128, 2 * NH), 256, FLASH_SMEM, s3>>>(out, 2 * sIdx * NH);
    }
    cudaEventRecord(e_done, s3);

    // join everything back into the capture stream
    cudaStreamWaitEvent(0, e_done, 0);
}

// round 13
// speedup vs baseline: 2.9121x; 1.0129x over previous
#include <cuda_runtime.h>
#include <cuda_bf16.h>
#include <cstdint>

// ---------------- problem constants ----------------
constexpr int BB = 8;      // batch
constexpr int CC = 512;    // channels
constexpr int HH = 56, WW = 56;
constexpr int NT = 3136;   // H*W tokens
constexpr int MT = 588;    // 3*196 downsampled tokens
constexpr int NH = 8;      // heads
constexpr int HD = 64;     // head dim
constexpr int NP = 3200;   // NT padded to 128
constexpr int MP = 640;    // MT padded to 128
#define ATT_SCALE 0.125f

// ---------------- scratch (device globals; zero-initialized) ----------------
__device__ float g_lf[BB * MT * CC];

__device__ __nv_bfloat16 g_xh[(size_t)BB * NP * CC], g_xl[(size_t)BB * NP * CC];
__device__ __nv_bfloat16 g_wqh[CC * CC], g_wql[CC * CC];
__device__ __nv_bfloat16 g_wkh[2 * CC * CC], g_wkl[2 * CC * CC];
__device__ __nv_bfloat16 g_lh[(size_t)BB * MP * CC], g_ll[(size_t)BB * MP * CC];
__device__ __nv_bfloat16 g_qh[(size_t)BB * NP * CC], g_ql[(size_t)BB * NP * CC];
__device__ __nv_bfloat16 g_kh[(size_t)BB * NH * MP * HD], g_kl[(size_t)BB * NH * MP * HD];
__device__ __nv_bfloat16 g_vth[(size_t)BB * NH * HD * MP], g_vtl[(size_t)BB * NH * HD * MP];

// ---------------- PTX helpers (base sm_103 feature set only) ----------------
__device__ __forceinline__ uint32_t smem_u32_of(const void* p) {
    uint32_t a;
    asm("{ .reg .u64 t; cvta.to.shared.u64 t, %1; cvt.u32.u64 %0, t; }" : "=r"(a) : "l"(p));
    return a;
}
__device__ __forceinline__ void cpa16(uint32_t dst, const void* src) {
    asm volatile("cp.async.cg.shared.global [%0], [%1], 16;" :: "r"(dst), "l"(src));
}
__device__ __forceinline__ void ldm4(uint32_t addr, uint32_t& r0, uint32_t& r1,
                                     uint32_t& r2, uint32_t& r3) {
    asm volatile("ldmatrix.sync.aligned.m8n8.x4.shared.b16 {%0,%1,%2,%3}, [%4];"
                 : "=r"(r0), "=r"(r1), "=r"(r2), "=r"(r3) : "r"(addr));
}
__device__ __forceinline__ void mma16816(float* d, const uint32_t* a, const uint32_t* b) {
    asm volatile(
        "mma.sync.aligned.m16n8k16.row.col.f32.bf16.bf16.f32 "
        "{%0,%1,%2,%3}, {%4,%5,%6,%7}, {%8,%9}, {%0,%1,%2,%3};"
        : "+f"(d[0]), "+f"(d[1]), "+f"(d[2]), "+f"(d[3])
        : "r"(a[0]), "r"(a[1]), "r"(a[2]), "r"(a[3]), "r"(b[0]), "r"(b[1]));
}
__device__ __forceinline__ uint32_t pack_bf2(float lo, float hi) {
    __nv_bfloat16 a = __float2bfloat16(lo), b = __float2bfloat16(hi);
    return ((uint32_t)__bfloat16_as_ushort(b) << 16) | (uint32_t)__bfloat16_as_ushort(a);
}

// ---------------- HMMA GEMM engine v3: 3-stage ring, 1 barrier/chunk ----------
constexpr int GSTAGE = 30720;
constexpr int GEMM_SMEM = 3 * GSTAGE;    // 92160 dynamic

__device__ __forceinline__ void g2_load(const __nv_bfloat16* Ah, const __nv_bfloat16* Al,
                                        const __nv_bfloat16* Bh, const __nv_bfloat16* Bl,
                                        int lda, int ldb, uint32_t base, int koff, int t) {
    #pragma unroll
    for (int j = 0; j < 2; j++) {
        int g = j * 256 + t;
        int row = g >> 2, c16 = g & 3;
        cpa16(base +         row * 80 + c16 * 16, Ah + (size_t)row * lda + koff + c16 * 8);
        cpa16(base + 10240 + row * 80 + c16 * 16, Al + (size_t)row * lda + koff + c16 * 8);
    }
    {
        int row = t >> 2, c16 = t & 3;
        cpa16(base + 20480 + row * 80 + c16 * 16, Bh + (size_t)row * ldb + koff + c16 * 8);
        cpa16(base + 25600 + row * 80 + c16 * 16, Bl + (size_t)row * ldb + koff + c16 * 8);
    }
    asm volatile("cp.async.commit_group;");
}

__device__ __forceinline__ void gemm_main2(const __nv_bfloat16* Ah, const __nv_bfloat16* Al,
                                           const __nv_bfloat16* Bh, const __nv_bfloat16* Bl,
                                           int lda, int ldb, int nchunks,
                                           uint32_t su, float acc[2][4][4]) {
    const int t = threadIdx.x;
    const int lane = t & 31, wid = t >> 5;
    const int wm = wid & 3, wn = wid >> 2;

    g2_load(Ah, Al, Bh, Bl, lda, ldb, su, 0, t);
    if (nchunks > 1) g2_load(Ah, Al, Bh, Bl, lda, ldb, su + GSTAGE, 32, t);
    int rb = 0;                       // ring index of chunk i
    for (int i = 0; i < nchunks; i++) {
        if (i + 1 < nchunks) { asm volatile("cp.async.wait_group 1;" ::: "memory"); }
        else                 { asm volatile("cp.async.wait_group 0;" ::: "memory"); }
        __syncthreads();
        if (i + 2 < nchunks) {
            int wb = rb + 2; if (wb >= 3) wb -= 3;
            g2_load(Ah, Al, Bh, Bl, lda, ldb, su + wb * GSTAGE, (i + 2) * 32, t);
        }
        const uint32_t ab = su + rb * GSTAGE;
        #pragma unroll
        for (int k16 = 0; k16 < 2; k16++) {
            uint32_t afh[2][4], afl[2][4];
            uint32_t a_addr = ab + (wm * 32 + (lane & 15)) * 80 + k16 * 32 + (lane >> 4) * 16;
            ldm4(a_addr,                 afh[0][0], afh[0][1], afh[0][2], afh[0][3]);
            ldm4(a_addr + 16 * 80,       afh[1][0], afh[1][1], afh[1][2], afh[1][3]);
            ldm4(a_addr + 10240,         afl[0][0], afl[0][1], afl[0][2], afl[0][3]);
            ldm4(a_addr + 10240 + 1280,  afl[1][0], afl[1][1], afl[1][2], afl[1][3]);
            uint32_t bfh[4][2], bfl[4][2];
            #pragma unroll
            for (int p = 0; p < 2; p++) {
                uint32_t b_addr = ab + 20480 + (wn * 32 + p * 16 + (lane & 15)) * 80
                                + k16 * 32 + ((lane >> 4) & 1) * 16;
                uint32_t r0, r1, r2, r3;
                ldm4(b_addr, r0, r1, r2, r3);
                bfh[2 * p][0] = r0; bfh[2 * p + 1][0] = r1;
                bfh[2 * p][1] = r2; bfh[2 * p + 1][1] = r3;
                ldm4(b_addr + 5120, r0, r1, r2, r3);
                bfl[2 * p][0] = r0; bfl[2 * p + 1][0] = r1;
                bfl[2 * p][1] = r2; bfl[2 * p + 1][1] = r3;
            }
            #pragma unroll
            for (int mi = 0; mi < 2; mi++)
                #pragma unroll
                for (int ni = 0; ni < 4; ni++) {
                    mma16816(acc[mi][ni], afh[mi], bfh[ni]);
                    mma16816(acc[mi][ni], afh[mi], bfl[ni]);
                    mma16816(acc[mi][ni], afl[mi], bfh[ni]);
                }
        }
        if (++rb == 3) rb = 0;
    }
}

#define EPILOGUE_ITER(body)                                                    \
    {                                                                          \
        const int lane = threadIdx.x & 31, wid = threadIdx.x >> 5;             \
        const int wm = wid & 3, wn = wid >> 2;                                 \
        _Pragma("unroll")                                                      \
        for (int mi = 0; mi < 2; mi++)                                         \
            _Pragma("unroll")                                                  \
            for (int ni = 0; ni < 4; ni++)                                     \
                _Pragma("unroll")                                              \
                for (int e = 0; e < 4; e++) {                                  \
                    int row = wm * 32 + mi * 16 + (lane >> 2) + ((e >> 1) * 8);\
                    int col = wn * 32 + ni * 8 + (lane & 3) * 2 + (e & 1);     \
                    float v = acc[mi][ni][e];                                  \
                    body                                                       \
                }                                                              \
    }

// ================= projection kernels (2 CTA/SM, batch-offset sliced) =================
__global__ __launch_bounds__(256, 2) void k_qproj_t(const float* __restrict__ bq, int b0) {
    extern __shared__ __align__(128) uint8_t smem[];
    uint32_t su = smem_u32_of(smem);
    const int b = b0 + blockIdx.z, m0 = blockIdx.x * 128, n0 = blockIdx.y * 64;
    float acc[2][4][4] = {};
    gemm_main2(g_xh + ((size_t)b * NP + m0) * CC, g_xl + ((size_t)b * NP + m0) * CC,
               g_wqh + (size_t)n0 * CC, g_wql + (size_t)n0 * CC,
               CC, CC, 16, su, acc);
    EPILOGUE_ITER({
        v += bq[n0 + col];
        __nv_bfloat16 h = __float2bfloat16(v);
        size_t o = ((size_t)b * NP + m0 + row) * CC + n0 + col;
        g_qh[o] = h;
        g_ql[o] = __float2bfloat16(v - __bfloat162float(h));
    })
}

__global__ __launch_bounds__(256, 2) void k_kvproj_t(const float* __restrict__ bkv) {
    extern __shared__ __align__(128) uint8_t smem[];
    uint32_t su = smem_u32_of(smem);
    const int b = blockIdx.z, m0 = blockIdx.x * 128, n0 = blockIdx.y * 64;
    float acc[2][4][4] = {};
    gemm_main2(g_lh + ((size_t)b * MP + m0) * CC, g_ll + ((size_t)b * MP + m0) * CC,
               g_wkh + (size_t)n0 * CC, g_wkl + (size_t)n0 * CC,
               CC, CC, 16, su, acc);
    EPILOGUE_ITER({
        int o = n0 + col;
        int m = m0 + row;
        v += bkv[o];
        __nv_bfloat16 h = __float2bfloat16(v);
        __nv_bfloat16 l = __float2bfloat16(v - __bfloat162float(h));
        if (o < 512) {
            size_t idx = (((size_t)b * NH + (o >> 6)) * MP + m) * HD + (o & 63);
            g_kh[idx] = h; g_kl[idx] = l;
        } else {
            int o2 = o - 512;
            size_t idx = (((size_t)b * NH + (o2 >> 6)) * HD + (o2 & 63)) * MP + m;
            g_vth[idx] = h; g_vtl[idx] = l;
        }
    })
}

// ================= fused flash attention (single-sync pipeline, 2 CTA/SM) =========
constexpr int FPITCH  = 144;
constexpr int Q_BYTES = 128 * FPITCH;          // 18432
constexpr int T_BYTES = 64 * FPITCH;           // 9216
constexpr int CH_OFF  = 2 * Q_BYTES;           // 36864
constexpr int CH_SIZE = 4 * T_BYTES;           // 36864
constexpr int FLASH_SMEM = CH_OFF + 2 * CH_SIZE;   // 110592

__global__ __launch_bounds__(256, 2) void k_flash(float* __restrict__ out, int bh0) {
    extern __shared__ __align__(128) uint8_t fsm[];
    uint32_t su = smem_u32_of(fsm);
    const int bh = bh0 + blockIdx.y, b = bh >> 3, h = bh & 7;
    const int n0 = blockIdx.x * 128;
    const int t = threadIdx.x, lane = t & 31, w = t >> 5;

    const __nv_bfloat16* qhp = g_qh + ((size_t)b * NP + n0) * CC + h * HD;
    const __nv_bfloat16* qlp = g_ql + ((size_t)b * NP + n0) * CC + h * HD;
    const __nv_bfloat16* khp = g_kh + (size_t)bh * MP * HD;
    const __nv_bfloat16* klp = g_kl + (size_t)bh * MP * HD;
    const __nv_bfloat16* vhp = g_vth + (size_t)bh * HD * MP;
    const __nv_bfloat16* vlp = g_vtl + (size_t)bh * HD * MP;

    #pragma unroll
    for (int j = 0; j < 4; j++) {
        int g = j * 256 + t, row = g >> 3, c16 = g & 7;
        cpa16(su + row * FPITCH + c16 * 16,           qhp + (size_t)row * CC + c16 * 8);
        cpa16(su + Q_BYTES + row * FPITCH + c16 * 16, qlp + (size_t)row * CC + c16 * 8);
    }
    asm volatile("cp.async.commit_group;");

    auto load_chunk = [&](int ci, int buf) {
        uint32_t base = su + CH_OFF + buf * CH_SIZE;
        #pragma unroll
        for (int j = 0; j < 2; j++) {
            int g = j * 256 + t, row = g >> 3, c16 = g & 7;
            cpa16(base +               row * FPITCH + c16 * 16,
                  khp + (size_t)(ci * 64 + row) * HD + c16 * 8);
            cpa16(base + T_BYTES +     row * FPITCH + c16 * 16,
                  klp + (size_t)(ci * 64 + row) * HD + c16 * 8);
            cpa16(base + 2 * T_BYTES + row * FPITCH + c16 * 16,
                  vhp + (size_t)row * MP + ci * 64 + c16 * 8);
            cpa16(base + 3 * T_BYTES + row * FPITCH + c16 * 16,
                  vlp + (size_t)row * MP + ci * 64 + c16 * 8);
        }
        asm volatile("cp.async.commit_group;");
    };
    load_chunk(0, 0);

    float l0 = 0.f, l1 = 0.f;
    float oa[8][4] = {};

    const uint32_t q_frag_base = su + (w * 16 + (lane & 15)) * FPITCH + (lane >> 4) * 16;
    const uint32_t kb_row = (lane & 15) * FPITCH + ((lane >> 4) & 1) * 16;

    for (int ci = 0; ci < 10; ci++) {
        const int buf = ci & 1;
        const uint32_t kb = su + CH_OFF + buf * CH_SIZE;

        asm volatile("cp.async.wait_group 0;" ::: "memory");
        __syncthreads();
        if (ci + 1 < 10) load_chunk(ci + 1, buf ^ 1);

        // ---- S = Qh*Kh + Qh*Kl + Ql*Kh ----
        float sa[8][4] = {};
        #pragma unroll
        for (int g = 0; g < 4; g++) {
            uint32_t qfh[4], qfl[4];
            ldm4(q_frag_base + g * 32,           qfh[0], qfh[1], qfh[2], qfh[3]);
            ldm4(q_frag_base + g * 32 + Q_BYTES, qfl[0], qfl[1], qfl[2], qfl[3]);
            #pragma unroll
            for (int half = 0; half < 2; half++) {
                uint32_t bkh[4][2], bkl[4][2];
                #pragma unroll
                for (int p = 0; p < 2; p++) {
                    uint32_t addr = kb + (half * 32 + p * 16) * FPITCH + kb_row + g * 32;
                    uint32_t r0, r1, r2, r3;
                    ldm4(addr, r0, r1, r2, r3);
                    bkh[2 * p][0] = r0; bkh[2 * p + 1][0] = r1;
                    bkh[2 * p][1] = r2; bkh[2 * p + 1][1] = r3;
                    ldm4(addr + T_BYTES, r0, r1, r2, r3);
                    bkl[2 * p][0] = r0; bkl[2 * p + 1][0] = r1;
                    bkl[2 * p][1] = r2; bkl[2 * p + 1][1] = r3;
                }
                #pragma unroll
                for (int nb2 = 0; nb2 < 4; nb2++) {
                    int nb = half * 4 + nb2;
                    mma16816(sa[nb], qfh, bkh[nb2]);
                    mma16816(sa[nb], qfh, bkl[nb2]);
                    mma16816(sa[nb], qfl, bkh[nb2]);
                }
            }
        }

        // ---- fixed-shift softmax ----
        float ps0 = 0.f, ps1 = 0.f;
        if (ci == 9) {
            #pragma unroll
            for (int nb = 0; nb < 8; nb++)
                #pragma unroll
                for (int e = 0; e < 4; e++) {
                    int j = 576 + nb * 8 + (lane & 3) * 2 + (e & 1);
                    float ev = (j < MT) ? __expf(sa[nb][e] * ATT_SCALE) : 0.f;
                    sa[nb][e] = ev;
                    if (e < 2) ps0 += ev; else ps1 += ev;
                }
        } else {
            #pragma unroll
            for (int nb = 0; nb < 8; nb++)
                #pragma unroll
                for (int e = 0; e < 4; e++) {
                    float ev = __expf(sa[nb][e] * ATT_SCALE);
                    sa[nb][e] = ev;
                    if (e < 2) ps0 += ev; else ps1 += ev;
                }
        }
        ps0 += __shfl_xor_sync(0xffffffffu, ps0, 1);
        ps0 += __shfl_xor_sync(0xffffffffu, ps0, 2);
        ps1 += __shfl_xor_sync(0xffffffffu, ps1, 1);
        ps1 += __shfl_xor_sync(0xffffffffu, ps1, 2);
        l0 += ps0;
        l1 += ps1;

        // ---- PV: O += Ph*Vh + Ph*Vl + Pl*Vh ----
        #pragma unroll
        for (int g = 0; g < 4; g++) {
            uint32_t aph[4], apl[4];
            #pragma unroll
            for (int q = 0; q < 2; q++) {
                int nb = 2 * g + q;
                float p0 = sa[nb][0], p1 = sa[nb][1], p2 = sa[nb][2], p3 = sa[nb][3];
                uint32_t hi01 = pack_bf2(p0, p1);
                uint32_t hi23 = pack_bf2(p2, p3);
                aph[2 * q]     = hi01;
                aph[2 * q + 1] = hi23;
                float r0f = p0 - __bfloat162float(__ushort_as_bfloat16((unsigned short)(hi01 & 0xffff)));
                float r1f = p1 - __bfloat162float(__ushort_as_bfloat16((unsigned short)(hi01 >> 16)));
                float r2f = p2 - __bfloat162float(__ushort_as_bfloat16((unsigned short)(hi23 & 0xffff)));
                float r3f = p3 - __bfloat162float(__ushort_as_bfloat16((unsigned short)(hi23 >> 16)));
                apl[2 * q]     = pack_bf2(r0f, r1f);
                apl[2 * q + 1] = pack_bf2(r2f, r3f);
            }
            #pragma unroll
            for (int half = 0; half < 2; half++) {
                uint32_t bvh[4][2], bvl[4][2];
                #pragma unroll
                for (int p = 0; p < 2; p++) {
                    uint32_t addr = kb + 2 * T_BYTES + (half * 32 + p * 16) * FPITCH
                                  + kb_row + g * 32;
                    uint32_t r0, r1, r2, r3;
                    ldm4(addr, r0, r1, r2, r3);
                    bvh[2 * p][0] = r0; bvh[2 * p + 1][0] = r1;
                    bvh[2 * p][1] = r2; bvh[2 * p + 1][1] = r3;
                    ldm4(addr + T_BYTES, r0, r1, r2, r3);
                    bvl[2 * p][0] = r0; bvl[2 * p + 1][0] = r1;
                    bvl[2 * p][1] = r2; bvl[2 * p + 1][1] = r3;
                }
                #pragma unroll
                for (int nd2 = 0; nd2 < 4; nd2++) {
                    int nd = half * 4 + nd2;
                    mma16816(oa[nd], aph, bvh[nd2]);
                    mma16816(oa[nd], aph, bvl[nd2]);
                    mma16816(oa[nd], apl, bvh[nd2]);
                }
            }
        }
    }

    const float inv0 = 1.f / l0, inv1 = 1.f / l1;
    const int r0 = w * 16 + (lane >> 2);
    const int nq0 = n0 + r0, nq1 = nq0 + 8;
    #pragma unroll
    for (int nd = 0; nd < 8; nd++) {
        int d = h * HD + nd * 8 + (lane & 3) * 2;
        if (nq0 < NT) {
            float2 v = make_float2(oa[nd][0] * inv0, oa[nd][1] * inv0);
            *(float2*)(out + ((size_t)b * NT + nq0) * CC + d) = v;
        }
        if (nq1 < NT) {
            float2 v = make_float2(oa[nd][2] * inv1, oa[nd][3] * inv1);
            *(float2*)(out + ((size_t)b * NT + nq1) * CC + d) = v;
        }
    }
}

// ================= support kernels =================
__global__ __launch_bounds__(256) void k_tsplit(const float* __restrict__ x) {
    __shared__ float tile[32][33];
    const int b = blockIdx.z, n0 = blockIdx.x * 32, c0 = blockIdx.y * 32;
    const int tx = threadIdx.x & 31, ty = threadIdx.x >> 5;
    const float* xp = x + ((size_t)b * CC + c0) * NT + n0;
    #pragma unroll
    for (int i = 0; i < 4; i++)
        tile[ty + 8 * i][tx] = xp[(size_t)(ty + 8 * i) * NT + tx];
    __syncthreads();
    #pragma unroll
    for (int i = 0; i < 4; i++) {
        int r = ty + 8 * i;
        float v = tile[tx][r];
        size_t o = ((size_t)b * NP + n0 + r) * CC + c0 + tx;
        __nv_bfloat16 h = __float2bfloat16(v);
        g_xh[o] = h;
        g_xl[o] = __float2bfloat16(v - __bfloat162float(h));
    }
}

__global__ void k_splitw(const float* __restrict__ Wq, const float* __restrict__ Wkv) {
    int i = blockIdx.x * 256 + threadIdx.x;
    if (i < CC * CC) {
        float v = Wq[i];
        __nv_bfloat16 h = __float2bfloat16(v);
        g_wqh[i] = h; g_wql[i] = __float2bfloat16(v - __bfloat162float(h));
    }
    if (i < 2 * CC * CC) {
        float v = Wkv[i];
        __nv_bfloat16 h = __float2bfloat16(v);
        g_wkh[i] = h; g_wkl[i] = __float2bfloat16(v - __bfloat162float(h));
    }
}

// fused branches 1, 2, 3: one block per (b, c); pooled plane staged in SMEM
__global__ __launch_bounds__(224) void k_branch(const float* __restrict__ x,
        const float* __restrict__ w1a, const float* __restrict__ b1a,
        const float* __restrict__ w1b, const float* __restrict__ b1b,
        const float* __restrict__ w2, const float* __restrict__ b2,
        const float* __restrict__ w3, const float* __restrict__ b3) {
    __shared__ float pool_s[196];
    const int bc = blockIdx.x;
    const int b = bc / CC, c = bc % CC;
    const int t = threadIdx.x;

    if (t < 196) {
        int w4 = t % 14, h4 = t / 14;
        const float* xp = x + (((size_t)bc * HH) + 4 * h4) * WW + 4 * w4;
        float wa[4], wb_[4], wc[16];
        #pragma unroll
        for (int r = 0; r < 4; r++) { wa[r] = w1a[c * 4 + r]; wb_[r] = w1b[c * 4 + r]; }
        #pragma unroll
        for (int r = 0; r < 16; r++) wc[r] = w2[c * 16 + r];
        float ba = b1a[c];
        float l1 = b1b[c], l2 = b2[c], pool = 0.f;
        #pragma unroll
        for (int i = 0; i < 4; i++) {
            float4 xv = *(const float4*)(xp + (size_t)i * WW);
            float tmid = ba + xv.x * wa[0] + xv.y * wa[1] + xv.z * wa[2] + xv.w * wa[3];
            l1 += fmaxf(tmid, 0.f) * wb_[i];
            l2 += xv.x * wc[4 * i] + xv.y * wc[4 * i + 1] + xv.z * wc[4 * i + 2] + xv.w * wc[4 * i + 3];
            pool += xv.x + xv.y + xv.z + xv.w;
        }
        g_lf[((size_t)b * MT + t) * CC + c] = fmaxf(l1, 0.f);
        g_lf[((size_t)b * MT + 196 + t) * CC + c] = fmaxf(l2, 0.f);
        pool_s[t] = pool * (1.f / 16.f);
    }
    __syncthreads();
    if (t < 196) {
        int w4 = t % 14, h4 = t / 14;
        float s = b3[c];
        #pragma unroll
        for (int i = 0; i < 3; i++) {
            int hh = h4 - 1 + i;
            if (hh < 0 || hh >= 14) continue;
            #pragma unroll
            for (int j = 0; j < 3; j++) {
                int ww = w4 - 1 + j;
                if (ww < 0 || ww >= 14) continue;
                s += pool_s[hh * 14 + ww] * w3[c * 9 + i * 3 + j];
            }
        }
        g_lf[((size_t)b * MT + 392 + t) * CC + c] = fmaxf(s, 0.f);
    }
}

__global__ __launch_bounds__(128) void k_ln(const float* __restrict__ gamma,
                                            const float* __restrict__ beta) {
    const int row = blockIdx.x;
    const int b = row / MT, m = row - b * MT;
    const float* p = g_lf + (size_t)row * CC;
    const int t = threadIdx.x;
    float4 v = *(const float4*)(p + t * 4);
    float s = v.x + v.y + v.z + v.w;
    float ss = v.x * v.x + v.y * v.y + v.z * v.z + v.w * v.w;
    #pragma unroll
    for (int o = 16; o >= 1; o >>= 1) {
        s  += __shfl_xor_sync(0xffffffffu, s, o);
        ss += __shfl_xor_sync(0xffffffffu, ss, o);
    }
    __shared__ float sh[8];
    int w = t >> 5;
    if ((t & 31) == 0) { sh[w * 2] = s; sh[w * 2 + 1] = ss; }
    __syncthreads();
    s  = sh[0] + sh[2] + sh[4] + sh[6];
    ss = sh[1] + sh[3] + sh[5] + sh[7];
    float mu = s * (1.f / CC);
    float var = ss * (1.f / CC) - mu * mu;
    float r = rsqrtf(var + 1e-5f);
    float4 g = *(const float4*)(gamma + t * 4);
    float4 be = *(const float4*)(beta + t * 4);
    float o0 = (v.x - mu) * r * g.x + be.x;
    float o1 = (v.y - mu) * r * g.y + be.y;
    float o2 = (v.z - mu) * r * g.z + be.z;
    float o3 = (v.w - mu) * r * g.w + be.w;
    size_t base = ((size_t)b * MP + m) * CC + t * 4;
    __nv_bfloat16 h0 = __float2bfloat16(o0), h1 = __float2bfloat16(o1);
    __nv_bfloat16 h2 = __float2bfloat16(o2), h3 = __float2bfloat16(o3);
    g_lh[base + 0] = h0; g_ll[base + 0] = __float2bfloat16(o0 - __bfloat162float(h0));
    g_lh[base + 1] = h1; g_ll[base + 1] = __float2bfloat16(o1 - __bfloat162float(h1));
    g_lh[base + 2] = h2; g_ll[base + 2] = __float2bfloat16(o2 - __bfloat162float(h2));
    g_lh[base + 3] = h3; g_ll[base + 3] = __float2bfloat16(o3 - __bfloat162float(h3));
}

// ---------------- launch: pipelined schedule with tail-filling streams ----------------
extern "C" void kernel_launch(void* const* d_in, const int* in_sizes, int n_in,
                              void* d_out, int out_size) {
    const float* x     = (const float*)d_in[0];
    const float* Wq    = (const float*)d_in[1];
    const float* bq    = (const float*)d_in[2];
    const float* Wkv   = (const float*)d_in[3];
    const float* bkv   = (const float*)d_in[4];
    const float* w1a   = (const float*)d_in[5];
    const float* b1a   = (const float*)d_in[6];
    const float* w1b   = (const float*)d_in[7];
    const float* b1b   = (const float*)d_in[8];
    const float* w2    = (const float*)d_in[9];
    const float* b2    = (const float*)d_in[10];
    const float* w3    = (const float*)d_in[11];
    const float* b3    = (const float*)d_in[12];
    const float* gamma = (const float*)d_in[13];
    const float* beta  = (const float*)d_in[14];
    float* out = (float*)d_out;

    // one-time resource init (identical captured graph every call)
    static cudaStream_t s2 = nullptr, f0 = nullptr, f1 = nullptr;
    static cudaEvent_t e_fork = nullptr, e_kv = nullptr, e_d0 = nullptr, e_d1 = nullptr;
    static cudaEvent_t e_q[2] = {nullptr, nullptr};
    if (s2 == nullptr) {
        cudaStreamCreateWithFlags(&s2, cudaStreamNonBlocking);
        cudaStreamCreateWithFlags(&f0, cudaStreamNonBlocking);
        cudaStreamCreateWithFlags(&f1, cudaStreamNonBlocking);
        cudaEventCreateWithFlags(&e_fork, cudaEventDisableTiming);
        cudaEventCreateWithFlags(&e_kv,   cudaEventDisableTiming);
        cudaEventCreateWithFlags(&e_d0,   cudaEventDisableTiming);
        cudaEventCreateWithFlags(&e_d1,   cudaEventDisableTiming);
        for (int i = 0; i < 2; i++) cudaEventCreateWithFlags(&e_q[i], cudaEventDisableTiming);
        cudaFuncSetAttribute(k_flash,    cudaFuncAttributeMaxDynamicSharedMemorySize, FLASH_SMEM);
        cudaFuncSetAttribute(k_qproj_t,  cudaFuncAttributeMaxDynamicSharedMemorySize, GEMM_SMEM);
        cudaFuncSetAttribute(k_kvproj_t, cudaFuncAttributeMaxDynamicSharedMemorySize, GEMM_SMEM);
    }

    // main stream: weight split (needed by both chains), then fork
    k_splitw<<<(2 * CC * CC + 255) / 256, 256>>>(Wq, Wkv);
    cudaEventRecord(e_fork, 0);
    cudaStreamWaitEvent(s2, e_fork, 0);

    // side chain (s2): branches -> LN -> KV projection -> e_kv
    k_branch<<<BB * CC, 224, 0, s2>>>(x, w1a, b1a, w1b, b1b, w2, b2, w3, b3);
    k_ln<<<BB * MT, 128, 0, s2>>>(gamma, beta);
    k_kvproj_t<<<dim3(MP / 128, 2 * CC / 64, BB), 256, GEMM_SMEM, s2>>>(bkv);
    cudaEventRecord(e_kv, s2);

    // main chain: x transpose/split, then 2 qproj halves (4 batches each)
    k_tsplit<<<dim3(NT / 32, CC / 32, BB), 256>>>(x);
    for (int half = 0; half < 2; half++) {
        k_qproj_t<<<dim3(NP / 128, CC / 64, 4), 256, GEMM_SMEM>>>(bq, 4 * half);
        cudaEventRecord(e_q[half], 0);
    }

    // flash: 4 slices (2 batches each) alternating across two streams so
    // slice tails overlap with the next slice's head
    cudaStreamWaitEvent(f0, e_kv, 0);
    cudaStreamWaitEvent(f1, e_kv, 0);
    for (int sIdx = 0; sIdx < 4; sIdx++) {
        cudaStream_t fs = (sIdx & 1) ? f1 : f0;
        cudaStreamWaitEvent(fs, e_q[sIdx >> 1], 0);
        k_flash<<<dim3(NP / 128, 2 * NH), 256, FLASH_SMEM, fs>>>(out, 2 * sIdx * NH);
    }
    cudaEventRecord(e_d0, f0);
    cudaEventRecord(e_d1, f1);

    // join everything back into the capture stream
    cudaStreamWaitEvent(0, e_d0, 0);
    cudaStreamWaitEvent(0, e_d1, 0);
}